// round 6
// baseline (speedup 1.0000x reference)
#include <cuda_runtime.h>
#include <cuda_bf16.h>
#include <cstdint>
#include <math.h>

#define BB 16
#define CC 512
#define KK 32
#define HWN 4096
#define EPSF 1e-5f
#define NSPLIT 8

// ---------------- scratch (static device globals: no allocation) ----------------
__device__ float g_feats[(size_t)BB * HWN * CC];   // (b, n, c)  134 MB
__device__ float g_assign[(size_t)BB * HWN * KK];  // (b, n, k)  8 MB
__device__ float g_x2[BB * HWN];                   // per-pixel ||feats||^2
__device__ float g_enc[BB * KK * CC];              // partial encoded
__device__ float g_asum[BB * KK];                  // sum_n assign
__device__ float g_gamma[BB * CC];
__device__ __nv_bfloat16 g_xhi[(size_t)BB * HWN * CC];  // x^T (b,n,c) bf16 hi
__device__ __nv_bfloat16 g_xlo[(size_t)BB * HWN * CC];  // x^T (b,n,c) bf16 lo
__device__ __nv_bfloat16 g_whi[CC * CC];
__device__ __nv_bfloat16 g_wlo[CC * CC];

// ---------------- helpers (baseline PTX only: sm_80-era, valid at compute_103) ----------------
__device__ __forceinline__ uint32_t smem_u32(const void* p) {
    uint32_t a;
    asm("{ .reg .u64 t; cvta.to.shared.u64 t, %1; cvt.u32.u64 %0, t; }" : "=r"(a) : "l"(p));
    return a;
}
__device__ __forceinline__ uint32_t swz64(uint32_t o) { return o ^ ((o >> 3) & 0x30); }

__device__ __forceinline__ void cpasync16(uint32_t dst, const void* src) {
    asm volatile("cp.async.cg.shared.global [%0], [%1], 16;"
                 :: "r"(dst), "l"(__cvta_generic_to_global(src)) : "memory");
}
#define CP_COMMIT() asm volatile("cp.async.commit_group;" ::: "memory")
#define CP_WAIT2()  asm volatile("cp.async.wait_group 2;" ::: "memory")

__device__ __forceinline__ void ldsm4(uint32_t addr, uint32_t* r) {
    asm volatile("ldmatrix.sync.aligned.m8n8.x4.shared.b16 {%0,%1,%2,%3}, [%4];"
                 : "=r"(r[0]), "=r"(r[1]), "=r"(r[2]), "=r"(r[3]) : "r"(addr));
}
__device__ __forceinline__ void mma_bf16(float* c, const uint32_t* a, uint32_t b0, uint32_t b1) {
    asm volatile(
        "mma.sync.aligned.m16n8k16.row.col.f32.bf16.bf16.f32 "
        "{%0,%1,%2,%3}, {%4,%5,%6,%7}, {%8,%9}, {%0,%1,%2,%3};"
        : "+f"(c[0]), "+f"(c[1]), "+f"(c[2]), "+f"(c[3])
        : "r"(a[0]), "r"(a[1]), "r"(a[2]), "r"(a[3]), "r"(b0), "r"(b1));
}

// ---------------- K_pre_w: conv_w -> bf16 hi/lo ----------------
__global__ void kpw(const float* __restrict__ w) {
    int i = blockIdx.x * blockDim.x + threadIdx.x;
    if (i < CC * CC) {
        float v = w[i];
        __nv_bfloat16 h = __float2bfloat16(v);
        g_whi[i] = h;
        g_wlo[i] = __float2bfloat16(v - __bfloat162float(h));
    }
}

// ---------------- K_pre_x: transpose x (b,c,n)->(b,n,c) + split bf16 hi/lo ----------------
__global__ void __launch_bounds__(256) kpx(const float* __restrict__ x) {
    __shared__ float t[32][33];
    int tx = threadIdx.x, ty = threadIdx.y;
    int b = blockIdx.z;
    int cb = blockIdx.y * 32;
    int nb = blockIdx.x * 32;
    const float* xb = x + (size_t)b * CC * HWN;
#pragma unroll
    for (int i = ty; i < 32; i += 8)
        t[i][tx] = xb[(size_t)(cb + i) * HWN + nb + tx];
    __syncthreads();
#pragma unroll
    for (int i = ty; i < 32; i += 8) {
        float v = t[tx][i];
        __nv_bfloat16 h = __float2bfloat16(v);
        size_t o = ((size_t)b * HWN + nb + i) * CC + cb + tx;
        g_xhi[o] = h;
        g_xlo[o] = __float2bfloat16(v - __bfloat162float(h));
    }
}

// ---------------- K0: zero scratch ----------------
__global__ void k0_init() {
    int i = blockIdx.x * blockDim.x + threadIdx.x;
    if (i < BB * KK * CC) g_enc[i] = 0.f;
    if (i < BB * HWN)     g_x2[i] = 0.f;
    if (i < BB * KK)      g_asum[i] = 0.f;
}

// ---------------- K1: HMMA split-bf16 GEMM + BN2 + relu -> feats, x2 ----------------
// CTA: 128 px (M) x 128 ch (N), 16 warps in 4(m) x 4(n), warp tile 32x32.
// K-chunks of 32, 3-stage cp.async pipeline, SW64 swizzle (64B rows).
// Stage (32 KB): Xhi[128x64B] Xlo Whi Wlo at +0,+8K,+16K,+24K.
#define K1_STAGE  32768
#define K1_BNS    1024
#define SMEM_K1M  (K1_BNS + 3 * K1_STAGE)

__global__ void __launch_bounds__(512, 1) k1_mma(
    const float* __restrict__ g2, const float* __restrict__ b2,
    const float* __restrict__ m2, const float* __restrict__ v2)
{
    extern __shared__ char sm[];
    uint32_t sb = smem_u32(sm);
    int tid = threadIdx.x;
    int lane = tid & 31;
    int wid = tid >> 5;          // 0..15
    int warp_m = wid >> 2;       // 0..3
    int warp_n = wid & 3;        // 0..3
    int n0 = blockIdx.x * 128;   // output-channel base
    int m0 = blockIdx.y * 128;   // pixel base (b*HWN + n)

    float* bns = (float*)sm;
    float* bnh = (float*)(sm + 512);
    if (tid < 128) {
        int o = n0 + tid;
        float s = rsqrtf(v2[o] + EPSF) * g2[o];
        bns[tid] = s;
        bnh[tid] = b2[o] - m2[o] * s;
    }

    const __nv_bfloat16* xh = g_xhi + (size_t)m0 * CC;
    const __nv_bfloat16* xl = g_xlo + (size_t)m0 * CC;
    const __nv_bfloat16* wh = g_whi + (size_t)n0 * CC;
    const __nv_bfloat16* wl = g_wlo + (size_t)n0 * CC;

    int ld_row = tid >> 2, ld_seg = tid & 3;
    uint32_t ld_d = swz64((uint32_t)(ld_row * 64 + ld_seg * 16));

    auto issue_stage = [&](int s) {
        uint32_t base = sb + K1_BNS + (s % 3) * K1_STAGE;
        size_t go = (size_t)ld_row * CC + s * 32 + ld_seg * 8;
        cpasync16(base + ld_d,         xh + go);
        cpasync16(base + 8192 + ld_d,  xl + go);
        cpasync16(base + 16384 + ld_d, wh + go);
        cpasync16(base + 24576 + ld_d, wl + go);
    };

    issue_stage(0); CP_COMMIT();
    issue_stage(1); CP_COMMIT();
    issue_stage(2); CP_COMMIT();

    float c[2][4][4];
#pragma unroll
    for (int i = 0; i < 2; i++)
#pragma unroll
        for (int j = 0; j < 4; j++)
#pragma unroll
            for (int l = 0; l < 4; l++) c[i][j][l] = 0.f;

    for (int s = 0; s < 16; s++) {
        CP_WAIT2();
        __syncthreads();
        uint32_t tb = sb + K1_BNS + (s % 3) * K1_STAGE;
#pragma unroll
        for (int kk = 0; kk < 2; kk++) {
            uint32_t ah[2][4], al[2][4], bh[2][4], bl[2][4];
#pragma unroll
            for (int mt = 0; mt < 2; mt++) {
                uint32_t off = swz64((uint32_t)((warp_m * 32 + mt * 16 + (lane & 15)) * 64
                                               + kk * 32 + (lane >> 4) * 16));
                ldsm4(tb + off, ah[mt]);
                ldsm4(tb + 8192 + off, al[mt]);
            }
#pragma unroll
            for (int ng = 0; ng < 2; ng++) {
                uint32_t off = swz64((uint32_t)((warp_n * 32 + ng * 16 + (lane & 15)) * 64
                                               + kk * 32 + (lane >> 4) * 16));
                ldsm4(tb + 16384 + off, bh[ng]);
                ldsm4(tb + 24576 + off, bl[ng]);
            }
            // B ldsm.x4 returns [n0-7,k0-7],[n8-15,k0-7],[n0-7,k8-15],[n8-15,k8-15];
            // n8-slice h uses {regs h, h+2}
#pragma unroll
            for (int mt = 0; mt < 2; mt++)
#pragma unroll
                for (int ng = 0; ng < 2; ng++)
#pragma unroll
                    for (int h = 0; h < 2; h++) {
                        float* cc = c[mt][ng * 2 + h];
                        mma_bf16(cc, ah[mt], bh[ng][h], bh[ng][h + 2]);
                        mma_bf16(cc, ah[mt], bl[ng][h], bl[ng][h + 2]);
                        mma_bf16(cc, al[mt], bh[ng][h], bh[ng][h + 2]);
                    }
        }
        __syncthreads();
        if (s + 3 < 16) issue_stage(s + 3);
        CP_COMMIT();
    }

    // epilogue: BN2 + relu -> g_feats, x2 partials via quad shuffle + atomics
#pragma unroll
    for (int mt = 0; mt < 2; mt++) {
        int r0 = m0 + warp_m * 32 + mt * 16 + (lane >> 2);
        float q0 = 0.f, q1 = 0.f;
#pragma unroll
        for (int j = 0; j < 4; j++) {
            int cl = warp_n * 32 + j * 8 + (lane & 3) * 2;
            float s0 = bns[cl], h0 = bnh[cl];
            float s1 = bns[cl + 1], h1 = bnh[cl + 1];
            float v00 = fmaxf(fmaf(c[mt][j][0], s0, h0), 0.f);
            float v01 = fmaxf(fmaf(c[mt][j][1], s1, h1), 0.f);
            float v10 = fmaxf(fmaf(c[mt][j][2], s0, h0), 0.f);
            float v11 = fmaxf(fmaf(c[mt][j][3], s1, h1), 0.f);
            *(float2*)&g_feats[(size_t)r0 * CC + n0 + cl] = make_float2(v00, v01);
            *(float2*)&g_feats[(size_t)(r0 + 8) * CC + n0 + cl] = make_float2(v10, v11);
            q0 = fmaf(v00, v00, fmaf(v01, v01, q0));
            q1 = fmaf(v10, v10, fmaf(v11, v11, q1));
        }
        q0 += __shfl_xor_sync(0xffffffffu, q0, 1);
        q0 += __shfl_xor_sync(0xffffffffu, q0, 2);
        q1 += __shfl_xor_sync(0xffffffffu, q1, 1);
        q1 += __shfl_xor_sync(0xffffffffu, q1, 2);
        if ((lane & 3) == 0) {
            atomicAdd(&g_x2[r0], q0);
            atomicAdd(&g_x2[r0 + 8], q1);
        }
    }
}

// ---------------- K2: xc GEMM (128px x 32codes) + fused scaled-L2 softmax -> assign ----------------
__global__ void __launch_bounds__(256) k2_assign(
    const float* __restrict__ cw, const float* __restrict__ scale)
{
    __shared__ float Fs[128][33];
    __shared__ float Cs[32][33];
    __shared__ float c2s[32];
    __shared__ float x2s[128];
    __shared__ float scs[32];
    int tid = threadIdx.x;
    int m0 = blockIdx.x * 128;

    {
        int k = tid >> 3, seg = tid & 7;
        const float* p = cw + k * CC + seg * 64;
        float s = 0.f;
#pragma unroll 16
        for (int i = 0; i < 64; i++) { float v = p[i]; s = fmaf(v, v, s); }
#pragma unroll
        for (int off = 4; off >= 1; off >>= 1)
            s += __shfl_xor_sync(0xffffffffu, s, off);
        if (seg == 0) c2s[k] = s;
        if (tid < 32) scs[tid] = scale[tid];
        if (tid < 128) x2s[tid] = g_x2[m0 + tid];
    }

    int kg = tid & 7;
    int pg = tid >> 3;
    float acc[4][4];
#pragma unroll
    for (int i = 0; i < 4; i++)
#pragma unroll
        for (int j = 0; j < 4; j++) acc[i][j] = 0.f;

    for (int c0 = 0; c0 < CC; c0 += 32) {
#pragma unroll
        for (int i = 0; i < 4; i++) {
            int idx4 = tid + i * 256;
            int p = idx4 >> 3, c4 = idx4 & 7;
            float4 v = *(const float4*)&g_feats[((size_t)(m0 + p)) * CC + c0 + c4 * 4];
            Fs[p][c4 * 4 + 0] = v.x; Fs[p][c4 * 4 + 1] = v.y;
            Fs[p][c4 * 4 + 2] = v.z; Fs[p][c4 * 4 + 3] = v.w;
        }
        {
            int k = tid >> 3, c4 = tid & 7;
            float4 v = *(const float4*)&cw[(size_t)k * CC + c0 + c4 * 4];
            Cs[k][c4 * 4 + 0] = v.x; Cs[k][c4 * 4 + 1] = v.y;
            Cs[k][c4 * 4 + 2] = v.z; Cs[k][c4 * 4 + 3] = v.w;
        }
        __syncthreads();
#pragma unroll 8
        for (int ccv = 0; ccv < 32; ccv++) {
            float rf[4], rc[4];
#pragma unroll
            for (int i = 0; i < 4; i++) rf[i] = Fs[pg * 4 + i][ccv];
#pragma unroll
            for (int j = 0; j < 4; j++) rc[j] = Cs[kg * 4 + j][ccv];
#pragma unroll
            for (int i = 0; i < 4; i++)
#pragma unroll
                for (int j = 0; j < 4; j++)
                    acc[i][j] = fmaf(rf[i], rc[j], acc[i][j]);
        }
        __syncthreads();
    }

#pragma unroll
    for (int i = 0; i < 4; i++) {
        int p = pg * 4 + i;
        float x2v = x2s[p];
        float d[4];
        float mx = -1e30f;
#pragma unroll
        for (int j = 0; j < 4; j++) {
            int k = kg * 4 + j;
            d[j] = scs[k] * (x2v - 2.f * acc[i][j] + c2s[k]);
            mx = fmaxf(mx, d[j]);
        }
#pragma unroll
        for (int off = 4; off >= 1; off >>= 1)
            mx = fmaxf(mx, __shfl_xor_sync(0xffffffffu, mx, off));
        float se = 0.f;
#pragma unroll
        for (int j = 0; j < 4; j++) { d[j] = __expf(d[j] - mx); se += d[j]; }
#pragma unroll
        for (int off = 4; off >= 1; off >>= 1)
            se += __shfl_xor_sync(0xffffffffu, se, off);
        float inv = 1.f / se;
        *(float4*)&g_assign[((size_t)(m0 + p)) * KK + kg * 4] =
            make_float4(d[0] * inv, d[1] * inv, d[2] * inv, d[3] * inv);
    }
}

// ---------------- K3: encoded_part = assign^T @ feats (n-split, atomic acc) + asum ----------------
__global__ void __launch_bounds__(256) k3_agg()
{
    __shared__ float Ws[32][33];
    __shared__ float Fs[32][132];
    int tid = threadIdx.x;
    int b  = blockIdx.z;
    int c0 = blockIdx.x * 128;
    int n0 = blockIdx.y * (HWN / NSPLIT);
    int m0 = b * HWN + n0;
    int kg = tid >> 5;
    int cg = tid & 31;

    float acc[4][4];
#pragma unroll
    for (int j = 0; j < 4; j++)
#pragma unroll
        for (int l = 0; l < 4; l++) acc[j][l] = 0.f;
    float asumr[4] = {0.f, 0.f, 0.f, 0.f};

    for (int nt = 0; nt < HWN / NSPLIT; nt += 32) {
        {
            int nn = tid >> 3, kq = tid & 7;
            float4 v = *(const float4*)&g_assign[((size_t)(m0 + nt + nn)) * KK + kq * 4];
            Ws[nn][kq * 4 + 0] = v.x; Ws[nn][kq * 4 + 1] = v.y;
            Ws[nn][kq * 4 + 2] = v.z; Ws[nn][kq * 4 + 3] = v.w;
        }
#pragma unroll
        for (int i = 0; i < 4; i++) {
            int idx4 = tid + i * 256;
            int nn = idx4 >> 5, c4 = idx4 & 31;
            float4 v = *(const float4*)&g_feats[((size_t)(m0 + nt + nn)) * CC + c0 + c4 * 4];
            *(float4*)&Fs[nn][c4 * 4] = v;
        }
        __syncthreads();
#pragma unroll 4
        for (int nn = 0; nn < 32; nn++) {
            float w0 = Ws[nn][kg * 4 + 0];
            float w1 = Ws[nn][kg * 4 + 1];
            float w2 = Ws[nn][kg * 4 + 2];
            float w3 = Ws[nn][kg * 4 + 3];
            float4 f = *(const float4*)&Fs[nn][cg * 4];
            acc[0][0] = fmaf(w0, f.x, acc[0][0]); acc[0][1] = fmaf(w0, f.y, acc[0][1]);
            acc[0][2] = fmaf(w0, f.z, acc[0][2]); acc[0][3] = fmaf(w0, f.w, acc[0][3]);
            acc[1][0] = fmaf(w1, f.x, acc[1][0]); acc[1][1] = fmaf(w1, f.y, acc[1][1]);
            acc[1][2] = fmaf(w1, f.z, acc[1][2]); acc[1][3] = fmaf(w1, f.w, acc[1][3]);
            acc[2][0] = fmaf(w2, f.x, acc[2][0]); acc[2][1] = fmaf(w2, f.y, acc[2][1]);
            acc[2][2] = fmaf(w2, f.z, acc[2][2]); acc[2][3] = fmaf(w2, f.w, acc[2][3]);
            acc[3][0] = fmaf(w3, f.x, acc[3][0]); acc[3][1] = fmaf(w3, f.y, acc[3][1]);
            acc[3][2] = fmaf(w3, f.z, acc[3][2]); acc[3][3] = fmaf(w3, f.w, acc[3][3]);
            if (cg == 0) {
                asumr[0] += w0; asumr[1] += w1; asumr[2] += w2; asumr[3] += w3;
            }
        }
        __syncthreads();
    }

    int cbase = c0 + cg * 4;
#pragma unroll
    for (int j = 0; j < 4; j++) {
        int k = kg * 4 + j;
        float* dst = &g_enc[((size_t)b * KK + k) * CC + cbase];
        atomicAdd(dst + 0, acc[j][0]);
        atomicAdd(dst + 1, acc[j][1]);
        atomicAdd(dst + 2, acc[j][2]);
        atomicAdd(dst + 3, acc[j][3]);
    }
    if (cg == 0 && blockIdx.x == 0) {
#pragma unroll
        for (int j = 0; j < 4; j++)
            atomicAdd(&g_asum[b * KK + kg * 4 + j], asumr[j]);
    }
}

// ---------------- K4 ----------------
__global__ void k4_ef(
    const float* __restrict__ cw, const float* __restrict__ g1,
    const float* __restrict__ b1, const float* __restrict__ m1,
    const float* __restrict__ v1, float* __restrict__ ef_out)
{
    int b = blockIdx.y;
    int c = blockIdx.x * 128 + threadIdx.x;
    float s = 0.f;
#pragma unroll
    for (int k = 0; k < KK; k++) {
        float e = g_enc[((size_t)b * KK + k) * CC + c] - g_asum[b * KK + k] * cw[(size_t)k * CC + c];
        float sc = rsqrtf(v1[k] + EPSF) * g1[k];
        e = fmaf(e - m1[k], sc, b1[k]);
        e = fmaxf(e, 0.f);
        s += e;
    }
    ef_out[b * CC + c] = s * (1.f / KK);
}

// ---------------- K5 ----------------
__global__ void __launch_bounds__(512) k5_gamma(
    const float* __restrict__ fcw, const float* __restrict__ fcb,
    const float* __restrict__ ef)
{
    __shared__ float efs[CC];
    int b = blockIdx.x;
    int o = threadIdx.x;
    efs[o] = ef[b * CC + o];
    __syncthreads();
    const float* wr = fcw + (size_t)o * CC;
    float s = fcb[o];
#pragma unroll 8
    for (int c = 0; c < CC; c += 4) {
        float4 w4 = *(const float4*)&wr[c];
        s = fmaf(w4.x, efs[c + 0], s);
        s = fmaf(w4.y, efs[c + 1], s);
        s = fmaf(w4.z, efs[c + 2], s);
        s = fmaf(w4.w, efs[c + 3], s);
    }
    g_gamma[b * CC + o] = 1.f / (1.f + __expf(-s));
}

// ---------------- K6 ----------------
__global__ void __launch_bounds__(256) k6_out(
    const float* __restrict__ x, float* __restrict__ out)
{
    size_t i4 = (size_t)blockIdx.x * blockDim.x + threadIdx.x;
    size_t total4 = (size_t)BB * CC * HWN / 4;
    if (i4 >= total4) return;
    size_t i = i4 * 4;
    int bc = (int)(i >> 12);
    float g = 1.f + g_gamma[bc];
    float4 v = *(const float4*)&x[i];
    v.x = fmaxf(v.x * g, 0.f);
    v.y = fmaxf(v.y * g, 0.f);
    v.z = fmaxf(v.z * g, 0.f);
    v.w = fmaxf(v.w * g, 0.f);
    *(float4*)&out[i] = v;
}

// ---------------- launch ----------------
extern "C" void kernel_launch(void* const* d_in, const int* in_sizes, int n_in,
                              void* d_out, int out_size)
{
    const float* x      = (const float*)d_in[0];
    const float* conv_w = (const float*)d_in[1];
    const float* bn2_g  = (const float*)d_in[2];
    const float* bn2_b  = (const float*)d_in[3];
    const float* bn2_m  = (const float*)d_in[4];
    const float* bn2_v  = (const float*)d_in[5];
    const float* cw     = (const float*)d_in[6];
    const float* scale  = (const float*)d_in[7];
    const float* bn1_g  = (const float*)d_in[8];
    const float* bn1_b  = (const float*)d_in[9];
    const float* bn1_m  = (const float*)d_in[10];
    const float* bn1_v  = (const float*)d_in[11];
    const float* fc_w   = (const float*)d_in[12];
    const float* fc_b   = (const float*)d_in[13];
    float* out = (float*)d_out;   // [0:8192) encoding_feat, [8192:) output

    static bool attr_set = false;
    if (!attr_set) {
        cudaFuncSetAttribute(k1_mma, cudaFuncAttributeMaxDynamicSharedMemorySize, SMEM_K1M);
        attr_set = true;
    }

    kpw<<<(CC * CC + 255) / 256, 256>>>(conv_w);

    dim3 gpx(HWN / 32, CC / 32, BB);
    kpx<<<gpx, dim3(32, 8)>>>(x);

    k0_init<<<1024, 256>>>();

    dim3 g1(CC / 128, BB * HWN / 128);   // (4, 512)
    k1_mma<<<g1, 512, SMEM_K1M>>>(bn2_g, bn2_b, bn2_m, bn2_v);

    k2_assign<<<BB * HWN / 128, 256>>>(cw, scale);

    dim3 g3(CC / 128, NSPLIT, BB);
    k3_agg<<<g3, 256>>>();

    dim3 g4(CC / 128, BB);
    k4_ef<<<g4, 128>>>(cw, bn1_g, bn1_b, bn1_m, bn1_v, out);

    k5_gamma<<<BB, 512>>>(fc_w, fc_b, out);

    k6_out<<<(BB * CC * HWN / 4 + 255) / 256, 256>>>(x, out + BB * CC);
}

// round 8
// speedup vs baseline: 1.1032x; 1.1032x over previous
#include <cuda_runtime.h>
#include <cuda_bf16.h>
#include <cstdint>
#include <math.h>

#define BB 16
#define CC 512
#define KK 32
#define HWN 4096
#define EPSF 1e-5f
#define NSPLIT 8

// ---------------- scratch (static device globals: no allocation) ----------------
__device__ __nv_bfloat16 g_fb16[(size_t)BB * HWN * CC]; // feats bf16 (b,n,c) 67 MB
__device__ float g_assign[(size_t)BB * HWN * KK];  // (b, n, k)  8 MB
__device__ float g_x2[BB * HWN];                   // per-pixel ||feats||^2
__device__ float g_enc[BB * KK * CC];              // partial encoded
__device__ float g_asum[BB * KK];                  // sum_n assign
__device__ float g_gamma[BB * CC];
__device__ __nv_bfloat16 g_xhi[(size_t)BB * HWN * CC];  // x^T (b,n,c) bf16 hi
__device__ __nv_bfloat16 g_xlo[(size_t)BB * HWN * CC];  // x^T (b,n,c) bf16 lo
__device__ __nv_bfloat16 g_whi[CC * CC];
__device__ __nv_bfloat16 g_wlo[CC * CC];

// ---------------- helpers ----------------
__device__ __forceinline__ uint32_t smem_u32(const void* p) {
    uint32_t a;
    asm("{ .reg .u64 t; cvta.to.shared.u64 t, %1; cvt.u32.u64 %0, t; }" : "=r"(a) : "l"(p));
    return a;
}
__device__ __forceinline__ uint32_t swz64(uint32_t o) { return o ^ ((o >> 3) & 0x30); }

__device__ __forceinline__ void cpasync16(uint32_t dst, const void* src) {
    asm volatile("cp.async.cg.shared.global [%0], [%1], 16;"
                 :: "r"(dst), "l"(__cvta_generic_to_global(src)) : "memory");
}
#define CP_COMMIT() asm volatile("cp.async.commit_group;" ::: "memory")
#define CP_WAIT2()  asm volatile("cp.async.wait_group 2;" ::: "memory")

__device__ __forceinline__ void ldsm4(uint32_t addr, uint32_t* r) {
    asm volatile("ldmatrix.sync.aligned.m8n8.x4.shared.b16 {%0,%1,%2,%3}, [%4];"
                 : "=r"(r[0]), "=r"(r[1]), "=r"(r[2]), "=r"(r[3]) : "r"(addr));
}
__device__ __forceinline__ void mma_bf16(float* c, const uint32_t* a, uint32_t b0, uint32_t b1) {
    asm volatile(
        "mma.sync.aligned.m16n8k16.row.col.f32.bf16.bf16.f32 "
        "{%0,%1,%2,%3}, {%4,%5,%6,%7}, {%8,%9}, {%0,%1,%2,%3};"
        : "+f"(c[0]), "+f"(c[1]), "+f"(c[2]), "+f"(c[3])
        : "r"(a[0]), "r"(a[1]), "r"(a[2]), "r"(a[3]), "r"(b0), "r"(b1));
}

// ---------------- K_pre_w: conv_w -> bf16 hi/lo ----------------
__global__ void kpw(const float* __restrict__ w) {
    int i = blockIdx.x * blockDim.x + threadIdx.x;
    if (i < CC * CC) {
        float v = w[i];
        __nv_bfloat16 h = __float2bfloat16(v);
        g_whi[i] = h;
        g_wlo[i] = __float2bfloat16(v - __bfloat162float(h));
    }
}

// ---------------- K_pre_x: transpose x (b,c,n)->(b,n,c) + split bf16 hi/lo ----------------
__global__ void __launch_bounds__(256) kpx(const float* __restrict__ x) {
    __shared__ float t[32][33];
    int tx = threadIdx.x, ty = threadIdx.y;
    int b = blockIdx.z;
    int cb = blockIdx.y * 32;
    int nb = blockIdx.x * 32;
    const float* xb = x + (size_t)b * CC * HWN;
#pragma unroll
    for (int i = ty; i < 32; i += 8)
        t[i][tx] = xb[(size_t)(cb + i) * HWN + nb + tx];
    __syncthreads();
#pragma unroll
    for (int i = ty; i < 32; i += 8) {
        float v = t[tx][i];
        __nv_bfloat16 h = __float2bfloat16(v);
        size_t o = ((size_t)b * HWN + nb + i) * CC + cb + tx;
        g_xhi[o] = h;
        g_xlo[o] = __float2bfloat16(v - __bfloat162float(h));
    }
}

// ---------------- K0: zero scratch ----------------
__global__ void k0_init() {
    int i = blockIdx.x * blockDim.x + threadIdx.x;
    if (i < BB * KK * CC) g_enc[i] = 0.f;
    if (i < BB * HWN)     g_x2[i] = 0.f;
    if (i < BB * KK)      g_asum[i] = 0.f;
}

// ---------------- K1: HMMA split-bf16 GEMM + BN2 + relu -> fb16, x2 ----------------
// CTA: 128 px (M) x 128 ch (N), 8 warps 4(m) x 2(n), warp tile 32x64.
// K-chunk 32, 3-stage cp.async pipeline, SW64 swizzle, 2 CTAs/SM target.
// Stage (32 KB): Xhi[128x64B] Xlo Whi Wlo at +0,+8K,+16K,+24K.
#define K1_STAGE  32768
#define K1_BNS    1024
#define SMEM_K1M  (K1_BNS + 3 * K1_STAGE)

__global__ void __launch_bounds__(256, 2) k1_mma(
    const float* __restrict__ g2, const float* __restrict__ b2,
    const float* __restrict__ m2, const float* __restrict__ v2)
{
    extern __shared__ char sm[];
    uint32_t sb = smem_u32(sm);
    int tid = threadIdx.x;
    int lane = tid & 31;
    int wid = tid >> 5;
    int warp_m = wid >> 1;       // 0..3
    int warp_n = wid & 1;        // 0..1
    int n0 = blockIdx.x * 128;   // output-channel base
    int m0 = blockIdx.y * 128;   // pixel base (b*HWN + n)

    float* bns = (float*)sm;
    float* bnh = (float*)(sm + 512);
    if (tid < 128) {
        int o = n0 + tid;
        float s = rsqrtf(v2[o] + EPSF) * g2[o];
        bns[tid] = s;
        bnh[tid] = b2[o] - m2[o] * s;
    }

    const __nv_bfloat16* xh = g_xhi + (size_t)m0 * CC;
    const __nv_bfloat16* xl = g_xlo + (size_t)m0 * CC;
    const __nv_bfloat16* wh = g_whi + (size_t)n0 * CC;
    const __nv_bfloat16* wl = g_wlo + (size_t)n0 * CC;

    // 256 threads: each loads 2 rows per tile (rows 0..127 covered by it=0..1)
    auto issue_stage = [&](int s) {
        uint32_t base = sb + K1_BNS + (s % 3) * K1_STAGE;
#pragma unroll
        for (int it = 0; it < 2; it++) {
            int idx = tid + it * 256;
            int row = idx >> 2, seg = idx & 3;
            uint32_t d = swz64((uint32_t)(row * 64 + seg * 16));
            size_t go = (size_t)row * CC + s * 32 + seg * 8;
            cpasync16(base + d,         xh + go);
            cpasync16(base + 8192 + d,  xl + go);
            cpasync16(base + 16384 + d, wh + go);
            cpasync16(base + 24576 + d, wl + go);
        }
    };

    issue_stage(0); CP_COMMIT();
    issue_stage(1); CP_COMMIT();
    issue_stage(2); CP_COMMIT();

    float c[2][8][4];
#pragma unroll
    for (int i = 0; i < 2; i++)
#pragma unroll
        for (int j = 0; j < 8; j++)
#pragma unroll
            for (int l = 0; l < 4; l++) c[i][j][l] = 0.f;

    for (int s = 0; s < 16; s++) {
        CP_WAIT2();
        __syncthreads();
        uint32_t tb = sb + K1_BNS + (s % 3) * K1_STAGE;
#pragma unroll
        for (int kk = 0; kk < 2; kk++) {
            // B fragments first (held across mt)
            uint32_t bh[4][4], bl[4][4];
#pragma unroll
            for (int ng = 0; ng < 4; ng++) {
                uint32_t off = swz64((uint32_t)((warp_n * 64 + ng * 16 + (lane & 15)) * 64
                                               + kk * 32 + (lane >> 4) * 16));
                ldsm4(tb + 16384 + off, bh[ng]);
                ldsm4(tb + 24576 + off, bl[ng]);
            }
            // per-mt A fragments
#pragma unroll
            for (int mt = 0; mt < 2; mt++) {
                uint32_t ah[4], al[4];
                uint32_t off = swz64((uint32_t)((warp_m * 32 + mt * 16 + (lane & 15)) * 64
                                               + kk * 32 + (lane >> 4) * 16));
                ldsm4(tb + off, ah);
                ldsm4(tb + 8192 + off, al);
                // B ldsm.x4: [n0-7,k0-7],[n8-15,k0-7],[n0-7,k8-15],[n8-15,k8-15];
                // n8-slice h uses {regs h, h+2}
#pragma unroll
                for (int ng = 0; ng < 4; ng++)
#pragma unroll
                    for (int h = 0; h < 2; h++) {
                        float* cc = c[mt][ng * 2 + h];
                        mma_bf16(cc, ah, bh[ng][h], bh[ng][h + 2]);
                        mma_bf16(cc, ah, bl[ng][h], bl[ng][h + 2]);
                        mma_bf16(cc, al, bh[ng][h], bh[ng][h + 2]);
                    }
            }
        }
        __syncthreads();
        if (s + 3 < 16) issue_stage(s + 3);
        CP_COMMIT();
    }

    // epilogue: BN2 + relu -> bf16 feats; x2 from the ROUNDED values (consistent feats')
#pragma unroll
    for (int mt = 0; mt < 2; mt++) {
        int r0 = m0 + warp_m * 32 + mt * 16 + (lane >> 2);
        float q0 = 0.f, q1 = 0.f;
#pragma unroll
        for (int j = 0; j < 8; j++) {
            int cl = warp_n * 64 + j * 8 + (lane & 3) * 2;
            float s0 = bns[cl], h0 = bnh[cl];
            float s1 = bns[cl + 1], h1 = bnh[cl + 1];
            float v00 = fmaxf(fmaf(c[mt][j][0], s0, h0), 0.f);
            float v01 = fmaxf(fmaf(c[mt][j][1], s1, h1), 0.f);
            float v10 = fmaxf(fmaf(c[mt][j][2], s0, h0), 0.f);
            float v11 = fmaxf(fmaf(c[mt][j][3], s1, h1), 0.f);
            __nv_bfloat162 p0 = __floats2bfloat162_rn(v00, v01);
            __nv_bfloat162 p1 = __floats2bfloat162_rn(v10, v11);
            *(__nv_bfloat162*)&g_fb16[(size_t)r0 * CC + n0 + cl] = p0;
            *(__nv_bfloat162*)&g_fb16[(size_t)(r0 + 8) * CC + n0 + cl] = p1;
            float2 f0 = __bfloat1622float2(p0);
            float2 f1 = __bfloat1622float2(p1);
            q0 = fmaf(f0.x, f0.x, fmaf(f0.y, f0.y, q0));
            q1 = fmaf(f1.x, f1.x, fmaf(f1.y, f1.y, q1));
        }
        q0 += __shfl_xor_sync(0xffffffffu, q0, 1);
        q0 += __shfl_xor_sync(0xffffffffu, q0, 2);
        q1 += __shfl_xor_sync(0xffffffffu, q1, 1);
        q1 += __shfl_xor_sync(0xffffffffu, q1, 2);
        if ((lane & 3) == 0) {
            atomicAdd(&g_x2[r0], q0);
            atomicAdd(&g_x2[r0 + 8], q1);
        }
    }
}

// ---------------- K2: xc GEMM (128px x 32codes, bf16 feats) + softmax -> assign ----------------
__global__ void __launch_bounds__(256) k2_assign(
    const float* __restrict__ cw, const float* __restrict__ scale)
{
    __shared__ float Fs[128][33];
    __shared__ float Cs[32][33];
    __shared__ float c2s[32];
    __shared__ float x2s[128];
    __shared__ float scs[32];
    int tid = threadIdx.x;
    int m0 = blockIdx.x * 128;

    {
        int k = tid >> 3, seg = tid & 7;
        const float* p = cw + k * CC + seg * 64;
        float s = 0.f;
#pragma unroll 16
        for (int i = 0; i < 64; i++) { float v = p[i]; s = fmaf(v, v, s); }
#pragma unroll
        for (int off = 4; off >= 1; off >>= 1)
            s += __shfl_xor_sync(0xffffffffu, s, off);
        if (seg == 0) c2s[k] = s;
        if (tid < 32) scs[tid] = scale[tid];
        if (tid < 128) x2s[tid] = g_x2[m0 + tid];
    }

    int kg = tid & 7;
    int pg = tid >> 3;
    float acc[4][4];
#pragma unroll
    for (int i = 0; i < 4; i++)
#pragma unroll
        for (int j = 0; j < 4; j++) acc[i][j] = 0.f;

    for (int c0 = 0; c0 < CC; c0 += 32) {
        // feats tile 128x32 from bf16
#pragma unroll
        for (int i = 0; i < 2; i++) {
            int idx = tid + i * 256;
            int p = idx >> 2, seg = idx & 3;
            uint4 v = *(const uint4*)&g_fb16[((size_t)(m0 + p)) * CC + c0 + seg * 8];
            const __nv_bfloat162* bp = (const __nv_bfloat162*)&v;
#pragma unroll
            for (int t = 0; t < 4; t++) {
                float2 f = __bfloat1622float2(bp[t]);
                Fs[p][seg * 8 + t * 2]     = f.x;
                Fs[p][seg * 8 + t * 2 + 1] = f.y;
            }
        }
        {
            int k = tid >> 3, c4 = tid & 7;
            float4 v = *(const float4*)&cw[(size_t)k * CC + c0 + c4 * 4];
            Cs[k][c4 * 4 + 0] = v.x; Cs[k][c4 * 4 + 1] = v.y;
            Cs[k][c4 * 4 + 2] = v.z; Cs[k][c4 * 4 + 3] = v.w;
        }
        __syncthreads();
#pragma unroll 8
        for (int ccv = 0; ccv < 32; ccv++) {
            float rf[4], rc[4];
#pragma unroll
            for (int i = 0; i < 4; i++) rf[i] = Fs[pg * 4 + i][ccv];
#pragma unroll
            for (int j = 0; j < 4; j++) rc[j] = Cs[kg * 4 + j][ccv];
#pragma unroll
            for (int i = 0; i < 4; i++)
#pragma unroll
                for (int j = 0; j < 4; j++)
                    acc[i][j] = fmaf(rf[i], rc[j], acc[i][j]);
        }
        __syncthreads();
    }

#pragma unroll
    for (int i = 0; i < 4; i++) {
        int p = pg * 4 + i;
        float x2v = x2s[p];
        float d[4];
        float mx = -1e30f;
#pragma unroll
        for (int j = 0; j < 4; j++) {
            int k = kg * 4 + j;
            d[j] = scs[k] * (x2v - 2.f * acc[i][j] + c2s[k]);
            mx = fmaxf(mx, d[j]);
        }
#pragma unroll
        for (int off = 4; off >= 1; off >>= 1)
            mx = fmaxf(mx, __shfl_xor_sync(0xffffffffu, mx, off));
        float se = 0.f;
#pragma unroll
        for (int j = 0; j < 4; j++) { d[j] = __expf(d[j] - mx); se += d[j]; }
#pragma unroll
        for (int off = 4; off >= 1; off >>= 1)
            se += __shfl_xor_sync(0xffffffffu, se, off);
        float inv = 1.f / se;
        *(float4*)&g_assign[((size_t)(m0 + p)) * KK + kg * 4] =
            make_float4(d[0] * inv, d[1] * inv, d[2] * inv, d[3] * inv);
    }
}

// ---------------- K3: encoded_part = assign^T @ feats (bf16 feats, atomic acc) + asum ----------------
__global__ void __launch_bounds__(256) k3_agg()
{
    __shared__ float Ws[32][33];
    __shared__ float Fs[32][132];
    int tid = threadIdx.x;
    int b  = blockIdx.z;
    int c0 = blockIdx.x * 128;
    int n0 = blockIdx.y * (HWN / NSPLIT);
    int m0 = b * HWN + n0;
    int kg = tid >> 5;
    int cg = tid & 31;

    float acc[4][4];
#pragma unroll
    for (int j = 0; j < 4; j++)
#pragma unroll
        for (int l = 0; l < 4; l++) acc[j][l] = 0.f;
    float asumr[4] = {0.f, 0.f, 0.f, 0.f};

    for (int nt = 0; nt < HWN / NSPLIT; nt += 32) {
        {
            int nn = tid >> 3, kq = tid & 7;
            float4 v = *(const float4*)&g_assign[((size_t)(m0 + nt + nn)) * KK + kq * 4];
            Ws[nn][kq * 4 + 0] = v.x; Ws[nn][kq * 4 + 1] = v.y;
            Ws[nn][kq * 4 + 2] = v.z; Ws[nn][kq * 4 + 3] = v.w;
        }
        // feats tile 32x128 bf16
#pragma unroll
        for (int i = 0; i < 2; i++) {
            int idx = tid + i * 256;
            int nn = idx >> 4, seg = idx & 15;
            uint4 v = *(const uint4*)&g_fb16[((size_t)(m0 + nt + nn)) * CC + c0 + seg * 8];
            const __nv_bfloat162* bp = (const __nv_bfloat162*)&v;
#pragma unroll
            for (int t = 0; t < 4; t++) {
                float2 f = __bfloat1622float2(bp[t]);
                Fs[nn][seg * 8 + t * 2]     = f.x;
                Fs[nn][seg * 8 + t * 2 + 1] = f.y;
            }
        }
        __syncthreads();
#pragma unroll 4
        for (int nn = 0; nn < 32; nn++) {
            float w0 = Ws[nn][kg * 4 + 0];
            float w1 = Ws[nn][kg * 4 + 1];
            float w2 = Ws[nn][kg * 4 + 2];
            float w3 = Ws[nn][kg * 4 + 3];
            float4 f = *(const float4*)&Fs[nn][cg * 4];
            acc[0][0] = fmaf(w0, f.x, acc[0][0]); acc[0][1] = fmaf(w0, f.y, acc[0][1]);
            acc[0][2] = fmaf(w0, f.z, acc[0][2]); acc[0][3] = fmaf(w0, f.w, acc[0][3]);
            acc[1][0] = fmaf(w1, f.x, acc[1][0]); acc[1][1] = fmaf(w1, f.y, acc[1][1]);
            acc[1][2] = fmaf(w1, f.z, acc[1][2]); acc[1][3] = fmaf(w1, f.w, acc[1][3]);
            acc[2][0] = fmaf(w2, f.x, acc[2][0]); acc[2][1] = fmaf(w2, f.y, acc[2][1]);
            acc[2][2] = fmaf(w2, f.z, acc[2][2]); acc[2][3] = fmaf(w2, f.w, acc[2][3]);
            acc[3][0] = fmaf(w3, f.x, acc[3][0]); acc[3][1] = fmaf(w3, f.y, acc[3][1]);
            acc[3][2] = fmaf(w3, f.z, acc[3][2]); acc[3][3] = fmaf(w3, f.w, acc[3][3]);
            if (cg == 0) {
                asumr[0] += w0; asumr[1] += w1; asumr[2] += w2; asumr[3] += w3;
            }
        }
        __syncthreads();
    }

    int cbase = c0 + cg * 4;
#pragma unroll
    for (int j = 0; j < 4; j++) {
        int k = kg * 4 + j;
        float* dst = &g_enc[((size_t)b * KK + k) * CC + cbase];
        atomicAdd(dst + 0, acc[j][0]);
        atomicAdd(dst + 1, acc[j][1]);
        atomicAdd(dst + 2, acc[j][2]);
        atomicAdd(dst + 3, acc[j][3]);
    }
    if (cg == 0 && blockIdx.x == 0) {
#pragma unroll
        for (int j = 0; j < 4; j++)
            atomicAdd(&g_asum[b * KK + kg * 4 + j], asumr[j]);
    }
}

// ---------------- K4 ----------------
__global__ void k4_ef(
    const float* __restrict__ cw, const float* __restrict__ g1,
    const float* __restrict__ b1, const float* __restrict__ m1,
    const float* __restrict__ v1, float* __restrict__ ef_out)
{
    int b = blockIdx.y;
    int c = blockIdx.x * 128 + threadIdx.x;
    float s = 0.f;
#pragma unroll
    for (int k = 0; k < KK; k++) {
        float e = g_enc[((size_t)b * KK + k) * CC + c] - g_asum[b * KK + k] * cw[(size_t)k * CC + c];
        float sc = rsqrtf(v1[k] + EPSF) * g1[k];
        e = fmaf(e - m1[k], sc, b1[k]);
        e = fmaxf(e, 0.f);
        s += e;
    }
    ef_out[b * CC + c] = s * (1.f / KK);
}

// ---------------- K5 ----------------
__global__ void __launch_bounds__(512) k5_gamma(
    const float* __restrict__ fcw, const float* __restrict__ fcb,
    const float* __restrict__ ef)
{
    __shared__ float efs[CC];
    int b = blockIdx.x;
    int o = threadIdx.x;
    efs[o] = ef[b * CC + o];
    __syncthreads();
    const float* wr = fcw + (size_t)o * CC;
    float s = fcb[o];
#pragma unroll 8
    for (int c = 0; c < CC; c += 4) {
        float4 w4 = *(const float4*)&wr[c];
        s = fmaf(w4.x, efs[c + 0], s);
        s = fmaf(w4.y, efs[c + 1], s);
        s = fmaf(w4.z, efs[c + 2], s);
        s = fmaf(w4.w, efs[c + 3], s);
    }
    g_gamma[b * CC + o] = 1.f / (1.f + __expf(-s));
}

// ---------------- K6 ----------------
__global__ void __launch_bounds__(256) k6_out(
    const float* __restrict__ x, float* __restrict__ out)
{
    size_t i4 = (size_t)blockIdx.x * blockDim.x + threadIdx.x;
    size_t total4 = (size_t)BB * CC * HWN / 4;
    if (i4 >= total4) return;
    size_t i = i4 * 4;
    int bc = (int)(i >> 12);
    float g = 1.f + g_gamma[bc];
    float4 v = *(const float4*)&x[i];
    v.x = fmaxf(v.x * g, 0.f);
    v.y = fmaxf(v.y * g, 0.f);
    v.z = fmaxf(v.z * g, 0.f);
    v.w = fmaxf(v.w * g, 0.f);
    *(float4*)&out[i] = v;
}

// ---------------- launch ----------------
extern "C" void kernel_launch(void* const* d_in, const int* in_sizes, int n_in,
                              void* d_out, int out_size)
{
    const float* x      = (const float*)d_in[0];
    const float* conv_w = (const float*)d_in[1];
    const float* bn2_g  = (const float*)d_in[2];
    const float* bn2_b  = (const float*)d_in[3];
    const float* bn2_m  = (const float*)d_in[4];
    const float* bn2_v  = (const float*)d_in[5];
    const float* cw     = (const float*)d_in[6];
    const float* scale  = (const float*)d_in[7];
    const float* bn1_g  = (const float*)d_in[8];
    const float* bn1_b  = (const float*)d_in[9];
    const float* bn1_m  = (const float*)d_in[10];
    const float* bn1_v  = (const float*)d_in[11];
    const float* fc_w   = (const float*)d_in[12];
    const float* fc_b   = (const float*)d_in[13];
    float* out = (float*)d_out;   // [0:8192) encoding_feat, [8192:) output

    static bool attr_set = false;
    if (!attr_set) {
        cudaFuncSetAttribute(k1_mma, cudaFuncAttributeMaxDynamicSharedMemorySize, SMEM_K1M);
        attr_set = true;
    }

    kpw<<<(CC * CC + 255) / 256, 256>>>(conv_w);

    dim3 gpx(HWN / 32, CC / 32, BB);
    kpx<<<gpx, dim3(32, 8)>>>(x);

    k0_init<<<1024, 256>>>();

    dim3 g1(CC / 128, BB * HWN / 128);   // (4, 512)
    k1_mma<<<g1, 256, SMEM_K1M>>>(bn2_g, bn2_b, bn2_m, bn2_v);

    k2_assign<<<BB * HWN / 128, 256>>>(cw, scale);

    dim3 g3(CC / 128, NSPLIT, BB);
    k3_agg<<<g3, 256>>>();

    dim3 g4(CC / 128, BB);
    k4_ef<<<g4, 128>>>(cw, bn1_g, bn1_b, bn1_m, bn1_v, out);

    k5_gamma<<<BB, 512>>>(fc_w, fc_b, out);

    k6_out<<<(BB * CC * HWN / 4 + 255) / 256, 256>>>(x, out + BB * CC);
}

// round 9
// speedup vs baseline: 1.5652x; 1.4188x over previous
#include <cuda_runtime.h>
#include <cuda_bf16.h>
#include <cuda_fp16.h>
#include <cstdint>
#include <math.h>

#define BB 16
#define CC 512
#define KK 32
#define HWN 4096
#define EPSF 1e-5f
#define NSPLIT 8

// ---------------- scratch (static device globals: no allocation) ----------------
__device__ __nv_bfloat16 g_fb16[(size_t)BB * HWN * CC]; // feats bf16 (b,n,c) 67 MB
__device__ float g_assign[(size_t)BB * HWN * KK];  // (b, n, k)  8 MB
__device__ float g_x2[BB * HWN];                   // per-pixel ||feats||^2
__device__ float g_enc[BB * KK * CC];              // partial encoded
__device__ float g_asum[BB * KK];                  // sum_n assign
__device__ float g_gamma[BB * CC];
__device__ __half g_xh[(size_t)BB * HWN * CC];     // x^T (b,n,c) fp16  67 MB
__device__ __half g_wh[CC * CC];                   // conv_w fp16

// ---------------- helpers ----------------
__device__ __forceinline__ uint32_t smem_u32(const void* p) {
    uint32_t a;
    asm("{ .reg .u64 t; cvta.to.shared.u64 t, %1; cvt.u32.u64 %0, t; }" : "=r"(a) : "l"(p));
    return a;
}
__device__ __forceinline__ uint32_t swz64(uint32_t o) { return o ^ ((o >> 3) & 0x30); }

__device__ __forceinline__ void cpasync16(uint32_t dst, const void* src) {
    asm volatile("cp.async.cg.shared.global [%0], [%1], 16;"
                 :: "r"(dst), "l"(__cvta_generic_to_global(src)) : "memory");
}
#define CP_COMMIT() asm volatile("cp.async.commit_group;" ::: "memory")
#define CP_WAIT2()  asm volatile("cp.async.wait_group 2;" ::: "memory")

__device__ __forceinline__ void ldsm4(uint32_t addr, uint32_t* r) {
    asm volatile("ldmatrix.sync.aligned.m8n8.x4.shared.b16 {%0,%1,%2,%3}, [%4];"
                 : "=r"(r[0]), "=r"(r[1]), "=r"(r[2]), "=r"(r[3]) : "r"(addr));
}
__device__ __forceinline__ void mma_fp16(float* c, const uint32_t* a, uint32_t b0, uint32_t b1) {
    asm volatile(
        "mma.sync.aligned.m16n8k16.row.col.f32.f16.f16.f32 "
        "{%0,%1,%2,%3}, {%4,%5,%6,%7}, {%8,%9}, {%0,%1,%2,%3};"
        : "+f"(c[0]), "+f"(c[1]), "+f"(c[2]), "+f"(c[3])
        : "r"(a[0]), "r"(a[1]), "r"(a[2]), "r"(a[3]), "r"(b0), "r"(b1));
}

// ---------------- K_pre_w: conv_w -> fp16 ----------------
__global__ void kpw(const float* __restrict__ w) {
    int i = blockIdx.x * blockDim.x + threadIdx.x;
    if (i < CC * CC) g_wh[i] = __float2half(w[i]);
}

// ---------------- K_pre_x: transpose x (b,c,n)->(b,n,c) + fp16 ----------------
__global__ void __launch_bounds__(256) kpx(const float* __restrict__ x) {
    __shared__ float t[32][33];
    int tx = threadIdx.x, ty = threadIdx.y;
    int b = blockIdx.z;
    int cb = blockIdx.y * 32;
    int nb = blockIdx.x * 32;
    const float* xb = x + (size_t)b * CC * HWN;
#pragma unroll
    for (int i = ty; i < 32; i += 8)
        t[i][tx] = xb[(size_t)(cb + i) * HWN + nb + tx];
    __syncthreads();
#pragma unroll
    for (int i = ty; i < 32; i += 8)
        g_xh[((size_t)b * HWN + nb + i) * CC + cb + tx] = __float2half(t[tx][i]);
}

// ---------------- K0: zero scratch ----------------
__global__ void k0_init() {
    int i = blockIdx.x * blockDim.x + threadIdx.x;
    if (i < BB * KK * CC) g_enc[i] = 0.f;
    if (i < BB * HWN)     g_x2[i] = 0.f;
    if (i < BB * KK)      g_asum[i] = 0.f;
}

// ---------------- K1: HMMA fp16 single-term GEMM + BN2 + relu -> fb16, x2 ----------------
// CTA: 128 px (M) x 128 ch (N), 8 warps 4(m) x 2(n), warp tile 32x64.
// K-chunk 32, 3-stage cp.async pipeline, SW64 swizzle.
// Stage (16 KB): Xh[128x64B] at +0, Wh at +8K.
#define K1_STAGE  16384
#define K1_BNS    1024
#define SMEM_K1M  (K1_BNS + 3 * K1_STAGE)

__global__ void __launch_bounds__(256, 2) k1_mma(
    const float* __restrict__ g2, const float* __restrict__ b2,
    const float* __restrict__ m2, const float* __restrict__ v2)
{
    extern __shared__ char sm[];
    uint32_t sb = smem_u32(sm);
    int tid = threadIdx.x;
    int lane = tid & 31;
    int wid = tid >> 5;
    int warp_m = wid >> 1;       // 0..3
    int warp_n = wid & 1;        // 0..1
    int n0 = blockIdx.x * 128;   // output-channel base
    int m0 = blockIdx.y * 128;   // pixel base (b*HWN + n)

    float* bns = (float*)sm;
    float* bnh = (float*)(sm + 512);
    if (tid < 128) {
        int o = n0 + tid;
        float s = rsqrtf(v2[o] + EPSF) * g2[o];
        bns[tid] = s;
        bnh[tid] = b2[o] - m2[o] * s;
    }

    const __half* xh = g_xh + (size_t)m0 * CC;
    const __half* wh = g_wh + (size_t)n0 * CC;

    // 256 threads: 2 (row,seg) slots each covers 128 rows x 4 segs
    auto issue_stage = [&](int s) {
        uint32_t base = sb + K1_BNS + (s % 3) * K1_STAGE;
#pragma unroll
        for (int it = 0; it < 2; it++) {
            int idx = tid + it * 256;
            int row = idx >> 2, seg = idx & 3;
            uint32_t d = swz64((uint32_t)(row * 64 + seg * 16));
            size_t go = (size_t)row * CC + s * 32 + seg * 8;
            cpasync16(base + d,        xh + go);
            cpasync16(base + 8192 + d, wh + go);
        }
    };

    issue_stage(0); CP_COMMIT();
    issue_stage(1); CP_COMMIT();
    issue_stage(2); CP_COMMIT();

    float c[2][8][4];
#pragma unroll
    for (int i = 0; i < 2; i++)
#pragma unroll
        for (int j = 0; j < 8; j++)
#pragma unroll
            for (int l = 0; l < 4; l++) c[i][j][l] = 0.f;

    for (int s = 0; s < 16; s++) {
        CP_WAIT2();
        __syncthreads();
        uint32_t tb = sb + K1_BNS + (s % 3) * K1_STAGE;
#pragma unroll
        for (int kk = 0; kk < 2; kk++) {
            uint32_t bfr[4][4];
#pragma unroll
            for (int ng = 0; ng < 4; ng++) {
                uint32_t off = swz64((uint32_t)((warp_n * 64 + ng * 16 + (lane & 15)) * 64
                                               + kk * 32 + (lane >> 4) * 16));
                ldsm4(tb + 8192 + off, bfr[ng]);
            }
#pragma unroll
            for (int mt = 0; mt < 2; mt++) {
                uint32_t a[4];
                uint32_t off = swz64((uint32_t)((warp_m * 32 + mt * 16 + (lane & 15)) * 64
                                               + kk * 32 + (lane >> 4) * 16));
                ldsm4(tb + off, a);
                // B ldsm.x4: [n0-7,k0-7],[n8-15,k0-7],[n0-7,k8-15],[n8-15,k8-15];
                // n8-slice h uses {regs h, h+2}
#pragma unroll
                for (int ng = 0; ng < 4; ng++)
#pragma unroll
                    for (int h = 0; h < 2; h++)
                        mma_fp16(c[mt][ng * 2 + h], a, bfr[ng][h], bfr[ng][h + 2]);
            }
        }
        __syncthreads();
        if (s + 3 < 16) issue_stage(s + 3);
        CP_COMMIT();
    }

    // epilogue: BN2 + relu -> bf16 feats; x2 from the ROUNDED values
#pragma unroll
    for (int mt = 0; mt < 2; mt++) {
        int r0 = m0 + warp_m * 32 + mt * 16 + (lane >> 2);
        float q0 = 0.f, q1 = 0.f;
#pragma unroll
        for (int j = 0; j < 8; j++) {
            int cl = warp_n * 64 + j * 8 + (lane & 3) * 2;
            float s0 = bns[cl], h0 = bnh[cl];
            float s1 = bns[cl + 1], h1 = bnh[cl + 1];
            float v00 = fmaxf(fmaf(c[mt][j][0], s0, h0), 0.f);
            float v01 = fmaxf(fmaf(c[mt][j][1], s1, h1), 0.f);
            float v10 = fmaxf(fmaf(c[mt][j][2], s0, h0), 0.f);
            float v11 = fmaxf(fmaf(c[mt][j][3], s1, h1), 0.f);
            __nv_bfloat162 p0 = __floats2bfloat162_rn(v00, v01);
            __nv_bfloat162 p1 = __floats2bfloat162_rn(v10, v11);
            *(__nv_bfloat162*)&g_fb16[(size_t)r0 * CC + n0 + cl] = p0;
            *(__nv_bfloat162*)&g_fb16[(size_t)(r0 + 8) * CC + n0 + cl] = p1;
            float2 f0 = __bfloat1622float2(p0);
            float2 f1 = __bfloat1622float2(p1);
            q0 = fmaf(f0.x, f0.x, fmaf(f0.y, f0.y, q0));
            q1 = fmaf(f1.x, f1.x, fmaf(f1.y, f1.y, q1));
        }
        q0 += __shfl_xor_sync(0xffffffffu, q0, 1);
        q0 += __shfl_xor_sync(0xffffffffu, q0, 2);
        q1 += __shfl_xor_sync(0xffffffffu, q1, 1);
        q1 += __shfl_xor_sync(0xffffffffu, q1, 2);
        if ((lane & 3) == 0) {
            atomicAdd(&g_x2[r0], q0);
            atomicAdd(&g_x2[r0 + 8], q1);
        }
    }
}

// ---------------- K2: xc GEMM (128px x 32codes, bf16 feats) + softmax -> assign ----------------
__global__ void __launch_bounds__(256) k2_assign(
    const float* __restrict__ cw, const float* __restrict__ scale)
{
    __shared__ float Fs[128][33];
    __shared__ float Cs[32][33];
    __shared__ float c2s[32];
    __shared__ float x2s[128];
    __shared__ float scs[32];
    int tid = threadIdx.x;
    int m0 = blockIdx.x * 128;

    {
        int k = tid >> 3, seg = tid & 7;
        const float* p = cw + k * CC + seg * 64;
        float s = 0.f;
#pragma unroll 16
        for (int i = 0; i < 64; i++) { float v = p[i]; s = fmaf(v, v, s); }
#pragma unroll
        for (int off = 4; off >= 1; off >>= 1)
            s += __shfl_xor_sync(0xffffffffu, s, off);
        if (seg == 0) c2s[k] = s;
        if (tid < 32) scs[tid] = scale[tid];
        if (tid < 128) x2s[tid] = g_x2[m0 + tid];
    }

    int kg = tid & 7;
    int pg = tid >> 3;
    float acc[4][4];
#pragma unroll
    for (int i = 0; i < 4; i++)
#pragma unroll
        for (int j = 0; j < 4; j++) acc[i][j] = 0.f;

    for (int c0 = 0; c0 < CC; c0 += 32) {
#pragma unroll
        for (int i = 0; i < 2; i++) {
            int idx = tid + i * 256;
            int p = idx >> 2, seg = idx & 3;
            uint4 v = *(const uint4*)&g_fb16[((size_t)(m0 + p)) * CC + c0 + seg * 8];
            const __nv_bfloat162* bp = (const __nv_bfloat162*)&v;
#pragma unroll
            for (int t = 0; t < 4; t++) {
                float2 f = __bfloat1622float2(bp[t]);
                Fs[p][seg * 8 + t * 2]     = f.x;
                Fs[p][seg * 8 + t * 2 + 1] = f.y;
            }
        }
        {
            int k = tid >> 3, c4 = tid & 7;
            float4 v = *(const float4*)&cw[(size_t)k * CC + c0 + c4 * 4];
            Cs[k][c4 * 4 + 0] = v.x; Cs[k][c4 * 4 + 1] = v.y;
            Cs[k][c4 * 4 + 2] = v.z; Cs[k][c4 * 4 + 3] = v.w;
        }
        __syncthreads();
#pragma unroll 8
        for (int ccv = 0; ccv < 32; ccv++) {
            float rf[4], rc[4];
#pragma unroll
            for (int i = 0; i < 4; i++) rf[i] = Fs[pg * 4 + i][ccv];
#pragma unroll
            for (int j = 0; j < 4; j++) rc[j] = Cs[kg * 4 + j][ccv];
#pragma unroll
            for (int i = 0; i < 4; i++)
#pragma unroll
                for (int j = 0; j < 4; j++)
                    acc[i][j] = fmaf(rf[i], rc[j], acc[i][j]);
        }
        __syncthreads();
    }

#pragma unroll
    for (int i = 0; i < 4; i++) {
        int p = pg * 4 + i;
        float x2v = x2s[p];
        float d[4];
        float mx = -1e30f;
#pragma unroll
        for (int j = 0; j < 4; j++) {
            int k = kg * 4 + j;
            d[j] = scs[k] * (x2v - 2.f * acc[i][j] + c2s[k]);
            mx = fmaxf(mx, d[j]);
        }
#pragma unroll
        for (int off = 4; off >= 1; off >>= 1)
            mx = fmaxf(mx, __shfl_xor_sync(0xffffffffu, mx, off));
        float se = 0.f;
#pragma unroll
        for (int j = 0; j < 4; j++) { d[j] = __expf(d[j] - mx); se += d[j]; }
#pragma unroll
        for (int off = 4; off >= 1; off >>= 1)
            se += __shfl_xor_sync(0xffffffffu, se, off);
        float inv = 1.f / se;
        *(float4*)&g_assign[((size_t)(m0 + p)) * KK + kg * 4] =
            make_float4(d[0] * inv, d[1] * inv, d[2] * inv, d[3] * inv);
    }
}

// ---------------- K3: encoded_part = assign^T @ feats (bf16 feats, atomic acc) + asum ----------------
__global__ void __launch_bounds__(256) k3_agg()
{
    __shared__ float Ws[32][33];
    __shared__ float Fs[32][132];
    int tid = threadIdx.x;
    int b  = blockIdx.z;
    int c0 = blockIdx.x * 128;
    int n0 = blockIdx.y * (HWN / NSPLIT);
    int m0 = b * HWN + n0;
    int kg = tid >> 5;
    int cg = tid & 31;

    float acc[4][4];
#pragma unroll
    for (int j = 0; j < 4; j++)
#pragma unroll
        for (int l = 0; l < 4; l++) acc[j][l] = 0.f;
    float asumr[4] = {0.f, 0.f, 0.f, 0.f};

    for (int nt = 0; nt < HWN / NSPLIT; nt += 32) {
        {
            int nn = tid >> 3, kq = tid & 7;
            float4 v = *(const float4*)&g_assign[((size_t)(m0 + nt + nn)) * KK + kq * 4];
            Ws[nn][kq * 4 + 0] = v.x; Ws[nn][kq * 4 + 1] = v.y;
            Ws[nn][kq * 4 + 2] = v.z; Ws[nn][kq * 4 + 3] = v.w;
        }
#pragma unroll
        for (int i = 0; i < 2; i++) {
            int idx = tid + i * 256;
            int nn = idx >> 4, seg = idx & 15;
            uint4 v = *(const uint4*)&g_fb16[((size_t)(m0 + nt + nn)) * CC + c0 + seg * 8];
            const __nv_bfloat162* bp = (const __nv_bfloat162*)&v;
#pragma unroll
            for (int t = 0; t < 4; t++) {
                float2 f = __bfloat1622float2(bp[t]);
                Fs[nn][seg * 8 + t * 2]     = f.x;
                Fs[nn][seg * 8 + t * 2 + 1] = f.y;
            }
        }
        __syncthreads();
#pragma unroll 4
        for (int nn = 0; nn < 32; nn++) {
            float w0 = Ws[nn][kg * 4 + 0];
            float w1 = Ws[nn][kg * 4 + 1];
            float w2 = Ws[nn][kg * 4 + 2];
            float w3 = Ws[nn][kg * 4 + 3];
            float4 f = *(const float4*)&Fs[nn][cg * 4];
            acc[0][0] = fmaf(w0, f.x, acc[0][0]); acc[0][1] = fmaf(w0, f.y, acc[0][1]);
            acc[0][2] = fmaf(w0, f.z, acc[0][2]); acc[0][3] = fmaf(w0, f.w, acc[0][3]);
            acc[1][0] = fmaf(w1, f.x, acc[1][0]); acc[1][1] = fmaf(w1, f.y, acc[1][1]);
            acc[1][2] = fmaf(w1, f.z, acc[1][2]); acc[1][3] = fmaf(w1, f.w, acc[1][3]);
            acc[2][0] = fmaf(w2, f.x, acc[2][0]); acc[2][1] = fmaf(w2, f.y, acc[2][1]);
            acc[2][2] = fmaf(w2, f.z, acc[2][2]); acc[2][3] = fmaf(w2, f.w, acc[2][3]);
            acc[3][0] = fmaf(w3, f.x, acc[3][0]); acc[3][1] = fmaf(w3, f.y, acc[3][1]);
            acc[3][2] = fmaf(w3, f.z, acc[3][2]); acc[3][3] = fmaf(w3, f.w, acc[3][3]);
            if (cg == 0) {
                asumr[0] += w0; asumr[1] += w1; asumr[2] += w2; asumr[3] += w3;
            }
        }
        __syncthreads();
    }

    int cbase = c0 + cg * 4;
#pragma unroll
    for (int j = 0; j < 4; j++) {
        int k = kg * 4 + j;
        float* dst = &g_enc[((size_t)b * KK + k) * CC + cbase];
        atomicAdd(dst + 0, acc[j][0]);
        atomicAdd(dst + 1, acc[j][1]);
        atomicAdd(dst + 2, acc[j][2]);
        atomicAdd(dst + 3, acc[j][3]);
    }
    if (cg == 0 && blockIdx.x == 0) {
#pragma unroll
        for (int j = 0; j < 4; j++)
            atomicAdd(&g_asum[b * KK + kg * 4 + j], asumr[j]);
    }
}

// ---------------- K4 ----------------
__global__ void k4_ef(
    const float* __restrict__ cw, const float* __restrict__ g1,
    const float* __restrict__ b1, const float* __restrict__ m1,
    const float* __restrict__ v1, float* __restrict__ ef_out)
{
    int b = blockIdx.y;
    int c = blockIdx.x * 128 + threadIdx.x;
    float s = 0.f;
#pragma unroll
    for (int k = 0; k < KK; k++) {
        float e = g_enc[((size_t)b * KK + k) * CC + c] - g_asum[b * KK + k] * cw[(size_t)k * CC + c];
        float sc = rsqrtf(v1[k] + EPSF) * g1[k];
        e = fmaf(e - m1[k], sc, b1[k]);
        e = fmaxf(e, 0.f);
        s += e;
    }
    ef_out[b * CC + c] = s * (1.f / KK);
}

// ---------------- K5 ----------------
__global__ void __launch_bounds__(512) k5_gamma(
    const float* __restrict__ fcw, const float* __restrict__ fcb,
    const float* __restrict__ ef)
{
    __shared__ float efs[CC];
    int b = blockIdx.x;
    int o = threadIdx.x;
    efs[o] = ef[b * CC + o];
    __syncthreads();
    const float* wr = fcw + (size_t)o * CC;
    float s = fcb[o];
#pragma unroll 8
    for (int c = 0; c < CC; c += 4) {
        float4 w4 = *(const float4*)&wr[c];
        s = fmaf(w4.x, efs[c + 0], s);
        s = fmaf(w4.y, efs[c + 1], s);
        s = fmaf(w4.z, efs[c + 2], s);
        s = fmaf(w4.w, efs[c + 3], s);
    }
    g_gamma[b * CC + o] = 1.f / (1.f + __expf(-s));
}

// ---------------- K6 ----------------
__global__ void __launch_bounds__(256) k6_out(
    const float* __restrict__ x, float* __restrict__ out)
{
    size_t i4 = (size_t)blockIdx.x * blockDim.x + threadIdx.x;
    size_t total4 = (size_t)BB * CC * HWN / 4;
    if (i4 >= total4) return;
    size_t i = i4 * 4;
    int bc = (int)(i >> 12);
    float g = 1.f + g_gamma[bc];
    float4 v = *(const float4*)&x[i];
    v.x = fmaxf(v.x * g, 0.f);
    v.y = fmaxf(v.y * g, 0.f);
    v.z = fmaxf(v.z * g, 0.f);
    v.w = fmaxf(v.w * g, 0.f);
    *(float4*)&out[i] = v;
}

// ---------------- launch ----------------
extern "C" void kernel_launch(void* const* d_in, const int* in_sizes, int n_in,
                              void* d_out, int out_size)
{
    const float* x      = (const float*)d_in[0];
    const float* conv_w = (const float*)d_in[1];
    const float* bn2_g  = (const float*)d_in[2];
    const float* bn2_b  = (const float*)d_in[3];
    const float* bn2_m  = (const float*)d_in[4];
    const float* bn2_v  = (const float*)d_in[5];
    const float* cw     = (const float*)d_in[6];
    const float* scale  = (const float*)d_in[7];
    const float* bn1_g  = (const float*)d_in[8];
    const float* bn1_b  = (const float*)d_in[9];
    const float* bn1_m  = (const float*)d_in[10];
    const float* bn1_v  = (const float*)d_in[11];
    const float* fc_w   = (const float*)d_in[12];
    const float* fc_b   = (const float*)d_in[13];
    float* out = (float*)d_out;   // [0:8192) encoding_feat, [8192:) output

    static bool attr_set = false;
    if (!attr_set) {
        cudaFuncSetAttribute(k1_mma, cudaFuncAttributeMaxDynamicSharedMemorySize, SMEM_K1M);
        attr_set = true;
    }

    kpw<<<(CC * CC + 255) / 256, 256>>>(conv_w);

    dim3 gpx(HWN / 32, CC / 32, BB);
    kpx<<<gpx, dim3(32, 8)>>>(x);

    k0_init<<<1024, 256>>>();

    dim3 g1(CC / 128, BB * HWN / 128);   // (4, 512)
    k1_mma<<<g1, 256, SMEM_K1M>>>(bn2_g, bn2_b, bn2_m, bn2_v);

    k2_assign<<<BB * HWN / 128, 256>>>(cw, scale);

    dim3 g3(CC / 128, NSPLIT, BB);
    k3_agg<<<g3, 256>>>();

    dim3 g4(CC / 128, BB);
    k4_ef<<<g4, 128>>>(cw, bn1_g, bn1_b, bn1_m, bn1_v, out);

    k5_gamma<<<BB, 512>>>(fc_w, fc_b, out);

    k6_out<<<(BB * CC * HWN / 4 + 255) / 256, 256>>>(x, out + BB * CC);
}

// round 10
// speedup vs baseline: 2.1820x; 1.3941x over previous
#include <cuda_runtime.h>
#include <cuda_bf16.h>
#include <cuda_fp16.h>
#include <cstdint>
#include <math.h>

#define BB 16
#define CC 512
#define KK 32
#define HWN 4096
#define EPSF 1e-5f
#define NSPLIT 8

// ---------------- scratch (static device globals: no allocation) ----------------
__device__ __half g_fh[(size_t)BB * HWN * CC];     // feats fp16 (b,n,c) 67 MB
__device__ __half g_asnT[(size_t)BB * KK * HWN];   // assign^T fp16 (b,k,n) 4 MB
__device__ float g_x2[BB * HWN];                   // per-pixel ||feats||^2
__device__ float g_enc[BB * KK * CC];              // partial encoded
__device__ float g_asum[BB * KK];                  // sum_n assign
__device__ float g_gamma[BB * CC];
__device__ __half g_xh[(size_t)BB * HWN * CC];     // x^T (b,n,c) fp16  67 MB
__device__ __half g_wh[CC * CC];                   // conv_w fp16
__device__ __half g_cwh[KK * CC];                  // codewords fp16

// ---------------- helpers ----------------
__device__ __forceinline__ uint32_t smem_u32(const void* p) {
    uint32_t a;
    asm("{ .reg .u64 t; cvta.to.shared.u64 t, %1; cvt.u32.u64 %0, t; }" : "=r"(a) : "l"(p));
    return a;
}
__device__ __forceinline__ uint32_t swz64(uint32_t o)  { return o ^ ((o >> 3) & 0x30); }
__device__ __forceinline__ uint32_t swz256(uint32_t o) { return o ^ ((o >> 4) & 0x70); }

__device__ __forceinline__ void cpasync16(uint32_t dst, const void* src) {
    asm volatile("cp.async.cg.shared.global [%0], [%1], 16;"
                 :: "r"(dst), "l"(__cvta_generic_to_global(src)) : "memory");
}
#define CP_COMMIT() asm volatile("cp.async.commit_group;" ::: "memory")
#define CP_WAIT2()  asm volatile("cp.async.wait_group 2;" ::: "memory")

__device__ __forceinline__ void ldsm4(uint32_t addr, uint32_t* r) {
    asm volatile("ldmatrix.sync.aligned.m8n8.x4.shared.b16 {%0,%1,%2,%3}, [%4];"
                 : "=r"(r[0]), "=r"(r[1]), "=r"(r[2]), "=r"(r[3]) : "r"(addr));
}
__device__ __forceinline__ void ldsm4t(uint32_t addr, uint32_t* r) {
    asm volatile("ldmatrix.sync.aligned.m8n8.x4.trans.shared.b16 {%0,%1,%2,%3}, [%4];"
                 : "=r"(r[0]), "=r"(r[1]), "=r"(r[2]), "=r"(r[3]) : "r"(addr));
}
__device__ __forceinline__ void mma_fp16(float* c, const uint32_t* a, uint32_t b0, uint32_t b1) {
    asm volatile(
        "mma.sync.aligned.m16n8k16.row.col.f32.f16.f16.f32 "
        "{%0,%1,%2,%3}, {%4,%5,%6,%7}, {%8,%9}, {%0,%1,%2,%3};"
        : "+f"(c[0]), "+f"(c[1]), "+f"(c[2]), "+f"(c[3])
        : "r"(a[0]), "r"(a[1]), "r"(a[2]), "r"(a[3]), "r"(b0), "r"(b1));
}

// ---------------- K_pre_w: conv_w + codewords -> fp16 ----------------
__global__ void kpw(const float* __restrict__ w, const float* __restrict__ cw) {
    int i = blockIdx.x * blockDim.x + threadIdx.x;
    if (i < CC * CC) g_wh[i] = __float2half(w[i]);
    if (i < KK * CC) g_cwh[i] = __float2half(cw[i]);
}

// ---------------- K_pre_x: transpose x (b,c,n)->(b,n,c) + fp16 ----------------
__global__ void __launch_bounds__(256) kpx(const float* __restrict__ x) {
    __shared__ float t[32][33];
    int tx = threadIdx.x, ty = threadIdx.y;
    int b = blockIdx.z;
    int cb = blockIdx.y * 32;
    int nb = blockIdx.x * 32;
    const float* xb = x + (size_t)b * CC * HWN;
#pragma unroll
    for (int i = ty; i < 32; i += 8)
        t[i][tx] = xb[(size_t)(cb + i) * HWN + nb + tx];
    __syncthreads();
#pragma unroll
    for (int i = ty; i < 32; i += 8)
        g_xh[((size_t)b * HWN + nb + i) * CC + cb + tx] = __float2half(t[tx][i]);
}

// ---------------- K0: zero scratch ----------------
__global__ void k0_init() {
    int i = blockIdx.x * blockDim.x + threadIdx.x;
    if (i < BB * KK * CC) g_enc[i] = 0.f;
    if (i < BB * HWN)     g_x2[i] = 0.f;
    if (i < BB * KK)      g_asum[i] = 0.f;
}

// ---------------- K1: HMMA fp16 GEMM + BN2 + relu -> fp16 feats, x2 ----------------
#define K1_STAGE  16384
#define K1_BNS    1024
#define SMEM_K1M  (K1_BNS + 3 * K1_STAGE)

__global__ void __launch_bounds__(256, 2) k1_mma(
    const float* __restrict__ g2, const float* __restrict__ b2,
    const float* __restrict__ m2, const float* __restrict__ v2)
{
    extern __shared__ char sm[];
    uint32_t sb = smem_u32(sm);
    int tid = threadIdx.x;
    int lane = tid & 31;
    int wid = tid >> 5;
    int warp_m = wid >> 1;       // 0..3
    int warp_n = wid & 1;        // 0..1
    int n0 = blockIdx.x * 128;   // output-channel base
    int m0 = blockIdx.y * 128;   // pixel base (b*HWN + n)

    float* bns = (float*)sm;
    float* bnh = (float*)(sm + 512);
    if (tid < 128) {
        int o = n0 + tid;
        float s = rsqrtf(v2[o] + EPSF) * g2[o];
        bns[tid] = s;
        bnh[tid] = b2[o] - m2[o] * s;
    }

    const __half* xh = g_xh + (size_t)m0 * CC;
    const __half* wh = g_wh + (size_t)n0 * CC;

    auto issue_stage = [&](int s) {
        uint32_t base = sb + K1_BNS + (s % 3) * K1_STAGE;
#pragma unroll
        for (int it = 0; it < 2; it++) {
            int idx = tid + it * 256;
            int row = idx >> 2, seg = idx & 3;
            uint32_t d = swz64((uint32_t)(row * 64 + seg * 16));
            size_t go = (size_t)row * CC + s * 32 + seg * 8;
            cpasync16(base + d,        xh + go);
            cpasync16(base + 8192 + d, wh + go);
        }
    };

    issue_stage(0); CP_COMMIT();
    issue_stage(1); CP_COMMIT();
    issue_stage(2); CP_COMMIT();

    float c[2][8][4];
#pragma unroll
    for (int i = 0; i < 2; i++)
#pragma unroll
        for (int j = 0; j < 8; j++)
#pragma unroll
            for (int l = 0; l < 4; l++) c[i][j][l] = 0.f;

    for (int s = 0; s < 16; s++) {
        CP_WAIT2();
        __syncthreads();
        uint32_t tb = sb + K1_BNS + (s % 3) * K1_STAGE;
#pragma unroll
        for (int kk = 0; kk < 2; kk++) {
            uint32_t bfr[4][4];
#pragma unroll
            for (int ng = 0; ng < 4; ng++) {
                uint32_t off = swz64((uint32_t)((warp_n * 64 + ng * 16 + (lane & 15)) * 64
                                               + kk * 32 + (lane >> 4) * 16));
                ldsm4(tb + 8192 + off, bfr[ng]);
            }
#pragma unroll
            for (int mt = 0; mt < 2; mt++) {
                uint32_t a[4];
                uint32_t off = swz64((uint32_t)((warp_m * 32 + mt * 16 + (lane & 15)) * 64
                                               + kk * 32 + (lane >> 4) * 16));
                ldsm4(tb + off, a);
#pragma unroll
                for (int ng = 0; ng < 4; ng++)
#pragma unroll
                    for (int h = 0; h < 2; h++)
                        mma_fp16(c[mt][ng * 2 + h], a, bfr[ng][h], bfr[ng][h + 2]);
            }
        }
        __syncthreads();
        if (s + 3 < 16) issue_stage(s + 3);
        CP_COMMIT();
    }

    // epilogue: BN2 + relu -> fp16 feats; x2 from the ROUNDED values
#pragma unroll
    for (int mt = 0; mt < 2; mt++) {
        int r0 = m0 + warp_m * 32 + mt * 16 + (lane >> 2);
        float q0 = 0.f, q1 = 0.f;
#pragma unroll
        for (int j = 0; j < 8; j++) {
            int cl = warp_n * 64 + j * 8 + (lane & 3) * 2;
            float s0 = bns[cl], h0 = bnh[cl];
            float s1 = bns[cl + 1], h1 = bnh[cl + 1];
            float v00 = fmaxf(fmaf(c[mt][j][0], s0, h0), 0.f);
            float v01 = fmaxf(fmaf(c[mt][j][1], s1, h1), 0.f);
            float v10 = fmaxf(fmaf(c[mt][j][2], s0, h0), 0.f);
            float v11 = fmaxf(fmaf(c[mt][j][3], s1, h1), 0.f);
            __half2 p0 = __floats2half2_rn(v00, v01);
            __half2 p1 = __floats2half2_rn(v10, v11);
            *(__half2*)&g_fh[(size_t)r0 * CC + n0 + cl] = p0;
            *(__half2*)&g_fh[(size_t)(r0 + 8) * CC + n0 + cl] = p1;
            float2 f0 = __half22float2(p0);
            float2 f1 = __half22float2(p1);
            q0 = fmaf(f0.x, f0.x, fmaf(f0.y, f0.y, q0));
            q1 = fmaf(f1.x, f1.x, fmaf(f1.y, f1.y, q1));
        }
        q0 += __shfl_xor_sync(0xffffffffu, q0, 1);
        q0 += __shfl_xor_sync(0xffffffffu, q0, 2);
        q1 += __shfl_xor_sync(0xffffffffu, q1, 1);
        q1 += __shfl_xor_sync(0xffffffffu, q1, 2);
        if ((lane & 3) == 0) {
            atomicAdd(&g_x2[r0], q0);
            atomicAdd(&g_x2[r0 + 8], q1);
        }
    }
}

// ---------------- K2: HMMA xc + fused softmax -> assign^T fp16, asum ----------------
// CTA 128 px, 32 codes, contraction c=512. 8 warps, each 16 px rows.
#define K2_STG 10240
__global__ void __launch_bounds__(256) k2_assign(
    const float* __restrict__ cw, const float* __restrict__ scale)
{
    __shared__ __align__(16) char st[3 * K2_STG];
    __shared__ __half asn[32][136];
    __shared__ float c2s[32], x2s[128], scs[32];
    uint32_t sb = smem_u32(st);
    int tid = threadIdx.x;
    int lane = tid & 31, w = tid >> 5;
    int m0 = blockIdx.x * 128;
    int b = m0 >> 12;
    int n0 = m0 & (HWN - 1);

    auto issue = [&](int ch) {
        uint32_t base = sb + (ch % 3) * K2_STG;
#pragma unroll
        for (int it = 0; it < 2; it++) {
            int idx = tid + it * 256;
            int row = idx >> 2, seg = idx & 3;
            cpasync16(base + swz64((uint32_t)(row * 64 + seg * 16)),
                      g_fh + (size_t)(m0 + row) * CC + ch * 32 + seg * 8);
        }
        if (tid < 128) {
            int row = tid >> 2, seg = tid & 3;
            cpasync16(base + 8192 + swz64((uint32_t)(row * 64 + seg * 16)),
                      g_cwh + (size_t)row * CC + ch * 32 + seg * 8);
        }
    };
    issue(0); CP_COMMIT(); issue(1); CP_COMMIT(); issue(2); CP_COMMIT();

    // c2 (exact fp32 cw), scale, x2
    {
        int k = tid >> 3, seg = tid & 7;
        const float* p = cw + k * CC + seg * 64;
        float s = 0.f;
#pragma unroll 16
        for (int i = 0; i < 64; i++) { float v = p[i]; s = fmaf(v, v, s); }
#pragma unroll
        for (int off = 4; off >= 1; off >>= 1)
            s += __shfl_xor_sync(0xffffffffu, s, off);
        if (seg == 0) c2s[k] = s;
        if (tid < 32) scs[tid] = scale[tid];
        if (tid < 128) x2s[tid] = g_x2[m0 + tid];
    }

    float c[4][4];
#pragma unroll
    for (int i = 0; i < 4; i++)
#pragma unroll
        for (int j = 0; j < 4; j++) c[i][j] = 0.f;

    for (int ch = 0; ch < 16; ch++) {
        CP_WAIT2(); __syncthreads();
        uint32_t tb = sb + (ch % 3) * K2_STG;
#pragma unroll
        for (int kk = 0; kk < 2; kk++) {
            uint32_t a[4], b0[4], b1[4];
            ldsm4(tb + swz64((uint32_t)((w * 16 + (lane & 15)) * 64 + kk * 32 + (lane >> 4) * 16)), a);
            ldsm4(tb + 8192 + swz64((uint32_t)((lane & 15) * 64 + kk * 32 + (lane >> 4) * 16)), b0);
            ldsm4(tb + 8192 + swz64((uint32_t)((16 + (lane & 15)) * 64 + kk * 32 + (lane >> 4) * 16)), b1);
#pragma unroll
            for (int h = 0; h < 2; h++) {
                mma_fp16(c[h],     a, b0[h], b0[h + 2]);
                mma_fp16(c[2 + h], a, b1[h], b1[h + 2]);
            }
        }
        __syncthreads();
        if (ch + 3 < 16) issue(ch + 3);
        CP_COMMIT();
    }

    // dist + softmax over k (quad shuffles), write asn[k][px] fp16
    int q = lane & 3, r = lane >> 2;
#pragma unroll
    for (int half = 0; half < 2; half++) {
        int px = w * 16 + r + half * 8;
        float x2v = x2s[px];
        float d[8];
        float mx = -1e30f;
#pragma unroll
        for (int g = 0; g < 4; g++)
#pragma unroll
            for (int e = 0; e < 2; e++) {
                int k = g * 8 + q * 2 + e;
                float dd = scs[k] * (x2v - 2.f * c[g][half * 2 + e] + c2s[k]);
                d[g * 2 + e] = dd;
                mx = fmaxf(mx, dd);
            }
        mx = fmaxf(mx, __shfl_xor_sync(0xffffffffu, mx, 1));
        mx = fmaxf(mx, __shfl_xor_sync(0xffffffffu, mx, 2));
        float se = 0.f;
#pragma unroll
        for (int i = 0; i < 8; i++) { d[i] = __expf(d[i] - mx); se += d[i]; }
        se += __shfl_xor_sync(0xffffffffu, se, 1);
        se += __shfl_xor_sync(0xffffffffu, se, 2);
        float inv = 1.f / se;
#pragma unroll
        for (int g = 0; g < 4; g++)
#pragma unroll
            for (int e = 0; e < 2; e++)
                asn[g * 8 + q * 2 + e][px] = __float2half(d[g * 2 + e] * inv);
    }
    __syncthreads();

    // asum: k = tid>>3, 8 lanes each sum 16 px
    {
        int k = tid >> 3, seg = tid & 7;
        float s = 0.f;
#pragma unroll
        for (int j = 0; j < 16; j++)
            s += __half2float(asn[k][seg * 16 + j]);
        s += __shfl_xor_sync(0xffffffffu, s, 1);
        s += __shfl_xor_sync(0xffffffffu, s, 2);
        s += __shfl_xor_sync(0xffffffffu, s, 4);
        if (seg == 0) atomicAdd(&g_asum[b * KK + k], s);
    }
    // write assign^T (b,k,n) fp16, coalesced 16B
#pragma unroll
    for (int it = 0; it < 2; it++) {
        int idx = tid + it * 256;
        int row = idx >> 4, cs = idx & 15;
        uint4 v = *(const uint4*)&asn[row][cs * 8];
        *(uint4*)&g_asnT[((size_t)b * KK + row) * HWN + n0 + cs * 8] = v;
    }
}

// ---------------- K3: HMMA encoded^T[c][k] = feats^T @ assign^T, atomic acc ----------------
// grid (c/128, NSPLIT, B). A = feats via ldmatrix.trans; B = assign^T direct.
#define K3_STG 10240
__global__ void __launch_bounds__(256) k3_agg()
{
    __shared__ __align__(16) char st[3 * K3_STG];
    uint32_t sb = smem_u32(st);
    int tid = threadIdx.x, lane = tid & 31, w = tid >> 5;
    int b = blockIdx.z;
    int c0 = blockIdx.x * 128;
    int n0 = blockIdx.y * (HWN / NSPLIT);
    size_t m0 = (size_t)b * HWN + n0;

    auto issue = [&](int ch) {
        uint32_t base = sb + (ch % 3) * K3_STG;
#pragma unroll
        for (int it = 0; it < 2; it++) {
            int idx = tid + it * 256;
            int row = idx >> 4, seg = idx & 15;
            cpasync16(base + swz256((uint32_t)(row * 256 + seg * 16)),
                      g_fh + (m0 + ch * 32 + row) * CC + c0 + seg * 8);
        }
        if (tid < 128) {
            int row = tid >> 2, seg = tid & 3;
            cpasync16(base + 8192 + swz64((uint32_t)(row * 64 + seg * 16)),
                      g_asnT + ((size_t)b * KK + row) * HWN + n0 + ch * 32 + seg * 8);
        }
    };
    issue(0); CP_COMMIT(); issue(1); CP_COMMIT(); issue(2); CP_COMMIT();

    float c[4][4];
#pragma unroll
    for (int i = 0; i < 4; i++)
#pragma unroll
        for (int j = 0; j < 4; j++) c[i][j] = 0.f;

    for (int ch = 0; ch < 16; ch++) {
        CP_WAIT2(); __syncthreads();
        uint32_t tb = sb + (ch % 3) * K3_STG;
#pragma unroll
        for (int kk = 0; kk < 2; kk++) {
            uint32_t a[4], b0[4], b1[4];
            // A = feats^T fragment via trans: tile order [c-lo,n-lo],[c-hi,n-lo],[c-lo,n-hi],[c-hi,n-hi]
            int arow = kk * 16 + ((lane >> 4) << 3) + (lane & 7); // n row in tile
            int acol = w * 16 + (((lane >> 3) & 1) << 3);         // c col
            ldsm4t(tb + swz256((uint32_t)(arow * 256 + acol * 2)), a);
            ldsm4(tb + 8192 + swz64((uint32_t)((lane & 15) * 64 + kk * 32 + (lane >> 4) * 16)), b0);
            ldsm4(tb + 8192 + swz64((uint32_t)((16 + (lane & 15)) * 64 + kk * 32 + (lane >> 4) * 16)), b1);
#pragma unroll
            for (int h = 0; h < 2; h++) {
                mma_fp16(c[h],     a, b0[h], b0[h + 2]);
                mma_fp16(c[2 + h], a, b1[h], b1[h + 2]);
            }
        }
        __syncthreads();
        if (ch + 3 < 16) issue(ch + 3);
        CP_COMMIT();
    }

    // epilogue: atomicAdd into g_enc[b][k][c]
    int q = lane & 3, r = lane >> 2;
#pragma unroll
    for (int half = 0; half < 2; half++) {
        int cr = c0 + w * 16 + r + half * 8;
#pragma unroll
        for (int g = 0; g < 4; g++)
#pragma unroll
            for (int e = 0; e < 2; e++) {
                int k = g * 8 + q * 2 + e;
                atomicAdd(&g_enc[((size_t)b * KK + k) * CC + cr], c[g][half * 2 + e]);
            }
    }
}

// ---------------- K4 ----------------
__global__ void k4_ef(
    const float* __restrict__ cw, const float* __restrict__ g1,
    const float* __restrict__ b1, const float* __restrict__ m1,
    const float* __restrict__ v1, float* __restrict__ ef_out)
{
    int b = blockIdx.y;
    int c = blockIdx.x * 128 + threadIdx.x;
    float s = 0.f;
#pragma unroll
    for (int k = 0; k < KK; k++) {
        float e = g_enc[((size_t)b * KK + k) * CC + c] - g_asum[b * KK + k] * cw[(size_t)k * CC + c];
        float sc = rsqrtf(v1[k] + EPSF) * g1[k];
        e = fmaf(e - m1[k], sc, b1[k]);
        e = fmaxf(e, 0.f);
        s += e;
    }
    ef_out[b * CC + c] = s * (1.f / KK);
}

// ---------------- K5 ----------------
__global__ void __launch_bounds__(512) k5_gamma(
    const float* __restrict__ fcw, const float* __restrict__ fcb,
    const float* __restrict__ ef)
{
    __shared__ float efs[CC];
    int b = blockIdx.x;
    int o = threadIdx.x;
    efs[o] = ef[b * CC + o];
    __syncthreads();
    const float* wr = fcw + (size_t)o * CC;
    float s = fcb[o];
#pragma unroll 8
    for (int c = 0; c < CC; c += 4) {
        float4 w4 = *(const float4*)&wr[c];
        s = fmaf(w4.x, efs[c + 0], s);
        s = fmaf(w4.y, efs[c + 1], s);
        s = fmaf(w4.z, efs[c + 2], s);
        s = fmaf(w4.w, efs[c + 3], s);
    }
    g_gamma[b * CC + o] = 1.f / (1.f + __expf(-s));
}

// ---------------- K6 ----------------
__global__ void __launch_bounds__(256) k6_out(
    const float* __restrict__ x, float* __restrict__ out)
{
    size_t i4 = (size_t)blockIdx.x * blockDim.x + threadIdx.x;
    size_t total4 = (size_t)BB * CC * HWN / 4;
    if (i4 >= total4) return;
    size_t i = i4 * 4;
    int bc = (int)(i >> 12);
    float g = 1.f + g_gamma[bc];
    float4 v = *(const float4*)&x[i];
    v.x = fmaxf(v.x * g, 0.f);
    v.y = fmaxf(v.y * g, 0.f);
    v.z = fmaxf(v.z * g, 0.f);
    v.w = fmaxf(v.w * g, 0.f);
    *(float4*)&out[i] = v;
}

// ---------------- launch ----------------
extern "C" void kernel_launch(void* const* d_in, const int* in_sizes, int n_in,
                              void* d_out, int out_size)
{
    const float* x      = (const float*)d_in[0];
    const float* conv_w = (const float*)d_in[1];
    const float* bn2_g  = (const float*)d_in[2];
    const float* bn2_b  = (const float*)d_in[3];
    const float* bn2_m  = (const float*)d_in[4];
    const float* bn2_v  = (const float*)d_in[5];
    const float* cw     = (const float*)d_in[6];
    const float* scale  = (const float*)d_in[7];
    const float* bn1_g  = (const float*)d_in[8];
    const float* bn1_b  = (const float*)d_in[9];
    const float* bn1_m  = (const float*)d_in[10];
    const float* bn1_v  = (const float*)d_in[11];
    const float* fc_w   = (const float*)d_in[12];
    const float* fc_b   = (const float*)d_in[13];
    float* out = (float*)d_out;   // [0:8192) encoding_feat, [8192:) output

    static bool attr_set = false;
    if (!attr_set) {
        cudaFuncSetAttribute(k1_mma, cudaFuncAttributeMaxDynamicSharedMemorySize, SMEM_K1M);
        attr_set = true;
    }

    kpw<<<(CC * CC + 255) / 256, 256>>>(conv_w, cw);

    dim3 gpx(HWN / 32, CC / 32, BB);
    kpx<<<gpx, dim3(32, 8)>>>(x);

    k0_init<<<1024, 256>>>();

    dim3 g1(CC / 128, BB * HWN / 128);   // (4, 512)
    k1_mma<<<g1, 256, SMEM_K1M>>>(bn2_g, bn2_b, bn2_m, bn2_v);

    k2_assign<<<BB * HWN / 128, 256>>>(cw, scale);

    dim3 g3(CC / 128, NSPLIT, BB);
    k3_agg<<<g3, 256>>>();

    dim3 g4(CC / 128, BB);
    k4_ef<<<g4, 128>>>(cw, bn1_g, bn1_b, bn1_m, bn1_v, out);

    k5_gamma<<<BB, 512>>>(fc_w, fc_b, out);

    k6_out<<<(BB * CC * HWN / 4 + 255) / 256, 256>>>(x, out + BB * CC);
}

// round 11
// speedup vs baseline: 2.3430x; 1.0738x over previous
#include <cuda_runtime.h>
#include <cuda_bf16.h>
#include <cuda_fp16.h>
#include <cstdint>
#include <math.h>

#define BB 16
#define CC 512
#define KK 32
#define HWN 4096
#define EPSF 1e-5f
#define NSPLIT 8

// ---------------- scratch (static device globals: no allocation) ----------------
__device__ __half g_fh[(size_t)BB * HWN * CC];     // feats fp16 (b,n,c) 67 MB
__device__ __half g_asnT[(size_t)BB * KK * HWN];   // assign^T fp16 (b,k,n) 4 MB
__device__ float g_x2[BB * HWN];                   // per-pixel ||feats||^2
__device__ float g_enc[BB * KK * CC];              // partial encoded
__device__ float g_asum[BB * KK];                  // sum_n assign
__device__ float g_gamma[BB * CC];
__device__ __half g_xh[(size_t)BB * HWN * CC];     // x^T (b,n,c) fp16  67 MB
__device__ __half g_wh[CC * CC];                   // conv_w fp16
__device__ __half g_cwh[KK * CC];                  // codewords fp16

// ---------------- helpers ----------------
__device__ __forceinline__ uint32_t smem_u32(const void* p) {
    uint32_t a;
    asm("{ .reg .u64 t; cvta.to.shared.u64 t, %1; cvt.u32.u64 %0, t; }" : "=r"(a) : "l"(p));
    return a;
}
__device__ __forceinline__ uint32_t swz64(uint32_t o)  { return o ^ ((o >> 3) & 0x30); }
__device__ __forceinline__ uint32_t swz256(uint32_t o) { return o ^ ((o >> 4) & 0x70); }

__device__ __forceinline__ void cpasync16(uint32_t dst, const void* src) {
    asm volatile("cp.async.cg.shared.global [%0], [%1], 16;"
                 :: "r"(dst), "l"(__cvta_generic_to_global(src)) : "memory");
}
#define CP_COMMIT() asm volatile("cp.async.commit_group;" ::: "memory")
#define CP_WAIT2()  asm volatile("cp.async.wait_group 2;" ::: "memory")

__device__ __forceinline__ void ldsm4(uint32_t addr, uint32_t* r) {
    asm volatile("ldmatrix.sync.aligned.m8n8.x4.shared.b16 {%0,%1,%2,%3}, [%4];"
                 : "=r"(r[0]), "=r"(r[1]), "=r"(r[2]), "=r"(r[3]) : "r"(addr));
}
__device__ __forceinline__ void ldsm4t(uint32_t addr, uint32_t* r) {
    asm volatile("ldmatrix.sync.aligned.m8n8.x4.trans.shared.b16 {%0,%1,%2,%3}, [%4];"
                 : "=r"(r[0]), "=r"(r[1]), "=r"(r[2]), "=r"(r[3]) : "r"(addr));
}
__device__ __forceinline__ void mma_fp16(float* c, const uint32_t* a, uint32_t b0, uint32_t b1) {
    asm volatile(
        "mma.sync.aligned.m16n8k16.row.col.f32.f16.f16.f32 "
        "{%0,%1,%2,%3}, {%4,%5,%6,%7}, {%8,%9}, {%0,%1,%2,%3};"
        : "+f"(c[0]), "+f"(c[1]), "+f"(c[2]), "+f"(c[3])
        : "r"(a[0]), "r"(a[1]), "r"(a[2]), "r"(a[3]), "r"(b0), "r"(b1));
}

// ---------------- K_pre_w: conv_w + codewords -> fp16 ----------------
__global__ void kpw(const float* __restrict__ w, const float* __restrict__ cw) {
    int i = blockIdx.x * blockDim.x + threadIdx.x;
    if (i < CC * CC) g_wh[i] = __float2half(w[i]);
    if (i < KK * CC) g_cwh[i] = __float2half(cw[i]);
}

// ---------------- K_pre_x: transpose x (b,c,n)->(b,n,c) + fp16, half2 writes ----------------
__global__ void __launch_bounds__(256) kpx(const float* __restrict__ x) {
    __shared__ float t[64][33];
    int tid = threadIdx.x;
    int lane = tid & 31, w = tid >> 5;
    int b = blockIdx.z;
    int cb = blockIdx.y * 64;
    int nb = blockIdx.x * 32;
    const float* xb = x + (size_t)b * CC * HWN;
#pragma unroll
    for (int it = 0; it < 8; it++) {
        int r = w + it * 8;
        t[r][lane] = xb[(size_t)(cb + r) * HWN + nb + lane];
    }
    __syncthreads();
#pragma unroll
    for (int it = 0; it < 4; it++) {
        int idx = tid + it * 256;
        int n = idx >> 5;        // 0..31
        int cp = idx & 31;       // 0..31 (c pair)
        __half2 h = __floats2half2_rn(t[2 * cp][n], t[2 * cp + 1][n]);
        *(__half2*)&g_xh[((size_t)b * HWN + nb + n) * CC + cb + 2 * cp] = h;
    }
}

// ---------------- K0: zero scratch ----------------
__global__ void k0_init() {
    int i = blockIdx.x * blockDim.x + threadIdx.x;
    if (i < BB * KK * CC) g_enc[i] = 0.f;
    if (i < BB * HWN)     g_x2[i] = 0.f;
    if (i < BB * KK)      g_asum[i] = 0.f;
}

// ---------------- K1: HMMA fp16 GEMM + BN2 + relu -> fp16 feats, x2 ----------------
// 4-stage cp.async pipeline, single syncthreads per chunk, issue-before-compute.
#define K1_STAGE  16384
#define K1_BNS    1024
#define SMEM_K1M  (K1_BNS + 4 * K1_STAGE)

__global__ void __launch_bounds__(256, 2) k1_mma(
    const float* __restrict__ g2, const float* __restrict__ b2,
    const float* __restrict__ m2, const float* __restrict__ v2)
{
    extern __shared__ char sm[];
    uint32_t sb = smem_u32(sm);
    int tid = threadIdx.x;
    int lane = tid & 31;
    int wid = tid >> 5;
    int warp_m = wid >> 1;       // 0..3
    int warp_n = wid & 1;        // 0..1
    int n0 = blockIdx.x * 128;   // output-channel base
    int m0 = blockIdx.y * 128;   // pixel base (b*HWN + n)

    float* bns = (float*)sm;
    float* bnh = (float*)(sm + 512);
    if (tid < 128) {
        int o = n0 + tid;
        float s = rsqrtf(v2[o] + EPSF) * g2[o];
        bns[tid] = s;
        bnh[tid] = b2[o] - m2[o] * s;
    }

    const __half* xh = g_xh + (size_t)m0 * CC;
    const __half* wh = g_wh + (size_t)n0 * CC;

    auto issue_stage = [&](int s) {
        uint32_t base = sb + K1_BNS + (s & 3) * K1_STAGE;
#pragma unroll
        for (int it = 0; it < 2; it++) {
            int idx = tid + it * 256;
            int row = idx >> 2, seg = idx & 3;
            uint32_t d = swz64((uint32_t)(row * 64 + seg * 16));
            size_t go = (size_t)row * CC + s * 32 + seg * 8;
            cpasync16(base + d,        xh + go);
            cpasync16(base + 8192 + d, wh + go);
        }
    };

    issue_stage(0); CP_COMMIT();
    issue_stage(1); CP_COMMIT();
    issue_stage(2); CP_COMMIT();

    float c[2][8][4];
#pragma unroll
    for (int i = 0; i < 2; i++)
#pragma unroll
        for (int j = 0; j < 8; j++)
#pragma unroll
            for (int l = 0; l < 4; l++) c[i][j][l] = 0.f;

    for (int s = 0; s < 16; s++) {
        CP_WAIT2();
        __syncthreads();                 // single barrier per chunk (4 buffers)
        if (s + 3 < 16) issue_stage(s + 3);
        CP_COMMIT();
        uint32_t tb = sb + K1_BNS + (s & 3) * K1_STAGE;
#pragma unroll
        for (int kk = 0; kk < 2; kk++) {
            uint32_t bfr[4][4];
#pragma unroll
            for (int ng = 0; ng < 4; ng++) {
                uint32_t off = swz64((uint32_t)((warp_n * 64 + ng * 16 + (lane & 15)) * 64
                                               + kk * 32 + (lane >> 4) * 16));
                ldsm4(tb + 8192 + off, bfr[ng]);
            }
#pragma unroll
            for (int mt = 0; mt < 2; mt++) {
                uint32_t a[4];
                uint32_t off = swz64((uint32_t)((warp_m * 32 + mt * 16 + (lane & 15)) * 64
                                               + kk * 32 + (lane >> 4) * 16));
                ldsm4(tb + off, a);
#pragma unroll
                for (int ng = 0; ng < 4; ng++)
#pragma unroll
                    for (int h = 0; h < 2; h++)
                        mma_fp16(c[mt][ng * 2 + h], a, bfr[ng][h], bfr[ng][h + 2]);
            }
        }
    }

    // epilogue: BN2 + relu -> fp16 feats; x2 from the ROUNDED values
#pragma unroll
    for (int mt = 0; mt < 2; mt++) {
        int r0 = m0 + warp_m * 32 + mt * 16 + (lane >> 2);
        float q0 = 0.f, q1 = 0.f;
#pragma unroll
        for (int j = 0; j < 8; j++) {
            int cl = warp_n * 64 + j * 8 + (lane & 3) * 2;
            float s0 = bns[cl], h0 = bnh[cl];
            float s1 = bns[cl + 1], h1 = bnh[cl + 1];
            float v00 = fmaxf(fmaf(c[mt][j][0], s0, h0), 0.f);
            float v01 = fmaxf(fmaf(c[mt][j][1], s1, h1), 0.f);
            float v10 = fmaxf(fmaf(c[mt][j][2], s0, h0), 0.f);
            float v11 = fmaxf(fmaf(c[mt][j][3], s1, h1), 0.f);
            __half2 p0 = __floats2half2_rn(v00, v01);
            __half2 p1 = __floats2half2_rn(v10, v11);
            *(__half2*)&g_fh[(size_t)r0 * CC + n0 + cl] = p0;
            *(__half2*)&g_fh[(size_t)(r0 + 8) * CC + n0 + cl] = p1;
            float2 f0 = __half22float2(p0);
            float2 f1 = __half22float2(p1);
            q0 = fmaf(f0.x, f0.x, fmaf(f0.y, f0.y, q0));
            q1 = fmaf(f1.x, f1.x, fmaf(f1.y, f1.y, q1));
        }
        q0 += __shfl_xor_sync(0xffffffffu, q0, 1);
        q0 += __shfl_xor_sync(0xffffffffu, q0, 2);
        q1 += __shfl_xor_sync(0xffffffffu, q1, 1);
        q1 += __shfl_xor_sync(0xffffffffu, q1, 2);
        if ((lane & 3) == 0) {
            atomicAdd(&g_x2[r0], q0);
            atomicAdd(&g_x2[r0 + 8], q1);
        }
    }
}

// ---------------- K2: HMMA xc + fused softmax -> assign^T fp16, asum ----------------
#define K2_STG 10240
__global__ void __launch_bounds__(256) k2_assign(
    const float* __restrict__ cw, const float* __restrict__ scale)
{
    __shared__ __align__(16) char st[4 * K2_STG];
    __shared__ __half asn[32][136];
    __shared__ float c2s[32], x2s[128], scs[32];
    uint32_t sb = smem_u32(st);
    int tid = threadIdx.x;
    int lane = tid & 31, w = tid >> 5;
    int m0 = blockIdx.x * 128;
    int b = m0 >> 12;
    int n0 = m0 & (HWN - 1);

    auto issue = [&](int ch) {
        uint32_t base = sb + (ch & 3) * K2_STG;
#pragma unroll
        for (int it = 0; it < 2; it++) {
            int idx = tid + it * 256;
            int row = idx >> 2, seg = idx & 3;
            cpasync16(base + swz64((uint32_t)(row * 64 + seg * 16)),
                      g_fh + (size_t)(m0 + row) * CC + ch * 32 + seg * 8);
        }
        if (tid < 128) {
            int row = tid >> 2, seg = tid & 3;
            cpasync16(base + 8192 + swz64((uint32_t)(row * 64 + seg * 16)),
                      g_cwh + (size_t)row * CC + ch * 32 + seg * 8);
        }
    };
    issue(0); CP_COMMIT(); issue(1); CP_COMMIT(); issue(2); CP_COMMIT();

    {
        int k = tid >> 3, seg = tid & 7;
        const float* p = cw + k * CC + seg * 64;
        float s = 0.f;
#pragma unroll 16
        for (int i = 0; i < 64; i++) { float v = p[i]; s = fmaf(v, v, s); }
#pragma unroll
        for (int off = 4; off >= 1; off >>= 1)
            s += __shfl_xor_sync(0xffffffffu, s, off);
        if (seg == 0) c2s[k] = s;
        if (tid < 32) scs[tid] = scale[tid];
        if (tid < 128) x2s[tid] = g_x2[m0 + tid];
    }

    float c[4][4];
#pragma unroll
    for (int i = 0; i < 4; i++)
#pragma unroll
        for (int j = 0; j < 4; j++) c[i][j] = 0.f;

    for (int ch = 0; ch < 16; ch++) {
        CP_WAIT2();
        __syncthreads();
        if (ch + 3 < 16) issue(ch + 3);
        CP_COMMIT();
        uint32_t tb = sb + (ch & 3) * K2_STG;
#pragma unroll
        for (int kk = 0; kk < 2; kk++) {
            uint32_t a[4], b0[4], b1[4];
            ldsm4(tb + swz64((uint32_t)((w * 16 + (lane & 15)) * 64 + kk * 32 + (lane >> 4) * 16)), a);
            ldsm4(tb + 8192 + swz64((uint32_t)((lane & 15) * 64 + kk * 32 + (lane >> 4) * 16)), b0);
            ldsm4(tb + 8192 + swz64((uint32_t)((16 + (lane & 15)) * 64 + kk * 32 + (lane >> 4) * 16)), b1);
#pragma unroll
            for (int h = 0; h < 2; h++) {
                mma_fp16(c[h],     a, b0[h], b0[h + 2]);
                mma_fp16(c[2 + h], a, b1[h], b1[h + 2]);
            }
        }
    }
    __syncthreads();

    int q = lane & 3, r = lane >> 2;
#pragma unroll
    for (int half = 0; half < 2; half++) {
        int px = w * 16 + r + half * 8;
        float x2v = x2s[px];
        float d[8];
        float mx = -1e30f;
#pragma unroll
        for (int g = 0; g < 4; g++)
#pragma unroll
            for (int e = 0; e < 2; e++) {
                int k = g * 8 + q * 2 + e;
                float dd = scs[k] * (x2v - 2.f * c[g][half * 2 + e] + c2s[k]);
                d[g * 2 + e] = dd;
                mx = fmaxf(mx, dd);
            }
        mx = fmaxf(mx, __shfl_xor_sync(0xffffffffu, mx, 1));
        mx = fmaxf(mx, __shfl_xor_sync(0xffffffffu, mx, 2));
        float se = 0.f;
#pragma unroll
        for (int i = 0; i < 8; i++) { d[i] = __expf(d[i] - mx); se += d[i]; }
        se += __shfl_xor_sync(0xffffffffu, se, 1);
        se += __shfl_xor_sync(0xffffffffu, se, 2);
        float inv = 1.f / se;
#pragma unroll
        for (int g = 0; g < 4; g++)
#pragma unroll
            for (int e = 0; e < 2; e++)
                asn[g * 8 + q * 2 + e][px] = __float2half(d[g * 2 + e] * inv);
    }
    __syncthreads();

    {
        int k = tid >> 3, seg = tid & 7;
        float s = 0.f;
#pragma unroll
        for (int j = 0; j < 16; j++)
            s += __half2float(asn[k][seg * 16 + j]);
        s += __shfl_xor_sync(0xffffffffu, s, 1);
        s += __shfl_xor_sync(0xffffffffu, s, 2);
        s += __shfl_xor_sync(0xffffffffu, s, 4);
        if (seg == 0) atomicAdd(&g_asum[b * KK + k], s);
    }
#pragma unroll
    for (int it = 0; it < 2; it++) {
        int idx = tid + it * 256;
        int row = idx >> 4, cs = idx & 15;
        uint4 v = *(const uint4*)&asn[row][cs * 8];
        *(uint4*)&g_asnT[((size_t)b * KK + row) * HWN + n0 + cs * 8] = v;
    }
}

// ---------------- K3: HMMA encoded^T[c][k] = feats^T @ assign^T, atomic acc ----------------
#define K3_STG 10240
__global__ void __launch_bounds__(256) k3_agg()
{
    __shared__ __align__(16) char st[4 * K3_STG];
    uint32_t sb = smem_u32(st);
    int tid = threadIdx.x, lane = tid & 31, w = tid >> 5;
    int b = blockIdx.z;
    int c0 = blockIdx.x * 128;
    int n0 = blockIdx.y * (HWN / NSPLIT);
    size_t m0 = (size_t)b * HWN + n0;

    auto issue = [&](int ch) {
        uint32_t base = sb + (ch & 3) * K3_STG;
#pragma unroll
        for (int it = 0; it < 2; it++) {
            int idx = tid + it * 256;
            int row = idx >> 4, seg = idx & 15;
            cpasync16(base + swz256((uint32_t)(row * 256 + seg * 16)),
                      g_fh + (m0 + ch * 32 + row) * CC + c0 + seg * 8);
        }
        if (tid < 128) {
            int row = tid >> 2, seg = tid & 3;
            cpasync16(base + 8192 + swz64((uint32_t)(row * 64 + seg * 16)),
                      g_asnT + ((size_t)b * KK + row) * HWN + n0 + ch * 32 + seg * 8);
        }
    };
    issue(0); CP_COMMIT(); issue(1); CP_COMMIT(); issue(2); CP_COMMIT();

    float c[4][4];
#pragma unroll
    for (int i = 0; i < 4; i++)
#pragma unroll
        for (int j = 0; j < 4; j++) c[i][j] = 0.f;

    for (int ch = 0; ch < 16; ch++) {
        CP_WAIT2();
        __syncthreads();
        if (ch + 3 < 16) issue(ch + 3);
        CP_COMMIT();
        uint32_t tb = sb + (ch & 3) * K3_STG;
#pragma unroll
        for (int kk = 0; kk < 2; kk++) {
            uint32_t a[4], b0[4], b1[4];
            int arow = kk * 16 + ((lane >> 4) << 3) + (lane & 7);
            int acol = w * 16 + (((lane >> 3) & 1) << 3);
            ldsm4t(tb + swz256((uint32_t)(arow * 256 + acol * 2)), a);
            ldsm4(tb + 8192 + swz64((uint32_t)((lane & 15) * 64 + kk * 32 + (lane >> 4) * 16)), b0);
            ldsm4(tb + 8192 + swz64((uint32_t)((16 + (lane & 15)) * 64 + kk * 32 + (lane >> 4) * 16)), b1);
#pragma unroll
            for (int h = 0; h < 2; h++) {
                mma_fp16(c[h],     a, b0[h], b0[h + 2]);
                mma_fp16(c[2 + h], a, b1[h], b1[h + 2]);
            }
        }
    }

    int q = lane & 3, r = lane >> 2;
#pragma unroll
    for (int half = 0; half < 2; half++) {
        int cr = c0 + w * 16 + r + half * 8;
#pragma unroll
        for (int g = 0; g < 4; g++)
#pragma unroll
            for (int e = 0; e < 2; e++) {
                int k = g * 8 + q * 2 + e;
                atomicAdd(&g_enc[((size_t)b * KK + k) * CC + cr], c[g][half * 2 + e]);
            }
    }
}

// ---------------- K4 ----------------
__global__ void k4_ef(
    const float* __restrict__ cw, const float* __restrict__ g1,
    const float* __restrict__ b1, const float* __restrict__ m1,
    const float* __restrict__ v1, float* __restrict__ ef_out)
{
    int b = blockIdx.y;
    int c = blockIdx.x * 128 + threadIdx.x;
    float s = 0.f;
#pragma unroll
    for (int k = 0; k < KK; k++) {
        float e = g_enc[((size_t)b * KK + k) * CC + c] - g_asum[b * KK + k] * cw[(size_t)k * CC + c];
        float sc = rsqrtf(v1[k] + EPSF) * g1[k];
        e = fmaf(e - m1[k], sc, b1[k]);
        e = fmaxf(e, 0.f);
        s += e;
    }
    ef_out[b * CC + c] = s * (1.f / KK);
}

// ---------------- K5 ----------------
__global__ void __launch_bounds__(512) k5_gamma(
    const float* __restrict__ fcw, const float* __restrict__ fcb,
    const float* __restrict__ ef)
{
    __shared__ float efs[CC];
    int b = blockIdx.x;
    int o = threadIdx.x;
    efs[o] = ef[b * CC + o];
    __syncthreads();
    const float* wr = fcw + (size_t)o * CC;
    float s = fcb[o];
#pragma unroll 8
    for (int c = 0; c < CC; c += 4) {
        float4 w4 = *(const float4*)&wr[c];
        s = fmaf(w4.x, efs[c + 0], s);
        s = fmaf(w4.y, efs[c + 1], s);
        s = fmaf(w4.z, efs[c + 2], s);
        s = fmaf(w4.w, efs[c + 3], s);
    }
    g_gamma[b * CC + o] = 1.f / (1.f + __expf(-s));
}

// ---------------- K6 ----------------
__global__ void __launch_bounds__(256) k6_out(
    const float* __restrict__ x, float* __restrict__ out)
{
    size_t i4 = (size_t)blockIdx.x * blockDim.x + threadIdx.x;
    size_t total4 = (size_t)BB * CC * HWN / 4;
    if (i4 >= total4) return;
    size_t i = i4 * 4;
    int bc = (int)(i >> 12);
    float g = 1.f + g_gamma[bc];
    float4 v = *(const float4*)&x[i];
    v.x = fmaxf(v.x * g, 0.f);
    v.y = fmaxf(v.y * g, 0.f);
    v.z = fmaxf(v.z * g, 0.f);
    v.w = fmaxf(v.w * g, 0.f);
    *(float4*)&out[i] = v;
}

// ---------------- launch ----------------
extern "C" void kernel_launch(void* const* d_in, const int* in_sizes, int n_in,
                              void* d_out, int out_size)
{
    const float* x      = (const float*)d_in[0];
    const float* conv_w = (const float*)d_in[1];
    const float* bn2_g  = (const float*)d_in[2];
    const float* bn2_b  = (const float*)d_in[3];
    const float* bn2_m  = (const float*)d_in[4];
    const float* bn2_v  = (const float*)d_in[5];
    const float* cw     = (const float*)d_in[6];
    const float* scale  = (const float*)d_in[7];
    const float* bn1_g  = (const float*)d_in[8];
    const float* bn1_b  = (const float*)d_in[9];
    const float* bn1_m  = (const float*)d_in[10];
    const float* bn1_v  = (const float*)d_in[11];
    const float* fc_w   = (const float*)d_in[12];
    const float* fc_b   = (const float*)d_in[13];
    float* out = (float*)d_out;   // [0:8192) encoding_feat, [8192:) output

    static bool attr_set = false;
    if (!attr_set) {
        cudaFuncSetAttribute(k1_mma, cudaFuncAttributeMaxDynamicSharedMemorySize, SMEM_K1M);
        attr_set = true;
    }

    kpw<<<(CC * CC + 255) / 256, 256>>>(conv_w, cw);

    dim3 gpx(HWN / 32, CC / 64, BB);
    kpx<<<gpx, 256>>>(x);

    k0_init<<<1024, 256>>>();

    dim3 g1(CC / 128, BB * HWN / 128);   // (4, 512)
    k1_mma<<<g1, 256, SMEM_K1M>>>(bn2_g, bn2_b, bn2_m, bn2_v);

    k2_assign<<<BB * HWN / 128, 256>>>(cw, scale);

    dim3 g3(CC / 128, NSPLIT, BB);
    k3_agg<<<g3, 256>>>();

    dim3 g4(CC / 128, BB);
    k4_ef<<<g4, 128>>>(cw, bn1_g, bn1_b, bn1_m, bn1_v, out);

    k5_gamma<<<BB, 512>>>(fc_w, fc_b, out);

    k6_out<<<(BB * CC * HWN / 4 + 255) / 256, 256>>>(x, out + BB * CC);
}

// round 12
// speedup vs baseline: 2.4087x; 1.0281x over previous
#include <cuda_runtime.h>
#include <cuda_bf16.h>
#include <cuda_fp16.h>
#include <cstdint>
#include <math.h>

#define BB 16
#define CC 512
#define KK 32
#define HWN 4096
#define EPSF 1e-5f
#define NSPLIT 8

// ---------------- scratch (static device globals: no allocation) ----------------
__device__ __half g_fh[(size_t)BB * HWN * CC];     // feats fp16 (b,n,c) 67 MB
__device__ __half g_asnT[(size_t)BB * KK * HWN];   // assign^T fp16 (b,k,n) 4 MB
__device__ float g_x2[BB * HWN];                   // per-pixel ||feats||^2
__device__ float g_enc[BB * KK * CC];              // partial encoded
__device__ float g_asum[BB * KK];                  // sum_n assign
__device__ float g_gamma[BB * CC];
__device__ __half g_xh[(size_t)BB * HWN * CC];     // x^T (b,n,c) fp16  67 MB
__device__ __half g_wh[CC * CC];                   // conv_w fp16
__device__ __half g_cwh[KK * CC];                  // codewords fp16

// ---------------- helpers ----------------
__device__ __forceinline__ uint32_t smem_u32(const void* p) {
    uint32_t a;
    asm("{ .reg .u64 t; cvta.to.shared.u64 t, %1; cvt.u32.u64 %0, t; }" : "=r"(a) : "l"(p));
    return a;
}
__device__ __forceinline__ uint32_t swz64(uint32_t o)  { return o ^ ((o >> 3) & 0x30); }
__device__ __forceinline__ uint32_t swz256(uint32_t o) { return o ^ ((o >> 4) & 0x70); }

__device__ __forceinline__ void cpasync16(uint32_t dst, const void* src) {
    asm volatile("cp.async.cg.shared.global [%0], [%1], 16;"
                 :: "r"(dst), "l"(__cvta_generic_to_global(src)) : "memory");
}
#define CP_COMMIT() asm volatile("cp.async.commit_group;" ::: "memory")
#define CP_WAIT2()  asm volatile("cp.async.wait_group 2;" ::: "memory")

__device__ __forceinline__ void ldsm4(uint32_t addr, uint32_t* r) {
    asm volatile("ldmatrix.sync.aligned.m8n8.x4.shared.b16 {%0,%1,%2,%3}, [%4];"
                 : "=r"(r[0]), "=r"(r[1]), "=r"(r[2]), "=r"(r[3]) : "r"(addr));
}
__device__ __forceinline__ void ldsm4t(uint32_t addr, uint32_t* r) {
    asm volatile("ldmatrix.sync.aligned.m8n8.x4.trans.shared.b16 {%0,%1,%2,%3}, [%4];"
                 : "=r"(r[0]), "=r"(r[1]), "=r"(r[2]), "=r"(r[3]) : "r"(addr));
}
__device__ __forceinline__ void mma_fp16(float* c, const uint32_t* a, uint32_t b0, uint32_t b1) {
    asm volatile(
        "mma.sync.aligned.m16n8k16.row.col.f32.f16.f16.f32 "
        "{%0,%1,%2,%3}, {%4,%5,%6,%7}, {%8,%9}, {%0,%1,%2,%3};"
        : "+f"(c[0]), "+f"(c[1]), "+f"(c[2]), "+f"(c[3])
        : "r"(a[0]), "r"(a[1]), "r"(a[2]), "r"(a[3]), "r"(b0), "r"(b1));
}

// ---------------- K_pre_w: conv_w + codewords -> fp16 ----------------
__global__ void kpw(const float* __restrict__ w, const float* __restrict__ cw) {
    int i = blockIdx.x * blockDim.x + threadIdx.x;
    if (i < CC * CC) g_wh[i] = __float2half(w[i]);
    if (i < KK * CC) g_cwh[i] = __float2half(cw[i]);
}

// ---------------- K_pre_x: transpose x (b,c,n)->(b,n,c) + fp16, half2 writes ----------------
__global__ void __launch_bounds__(256) kpx(const float* __restrict__ x) {
    __shared__ float t[64][33];
    int tid = threadIdx.x;
    int lane = tid & 31, w = tid >> 5;
    int b = blockIdx.z;
    int cb = blockIdx.y * 64;
    int nb = blockIdx.x * 32;
    const float* xb = x + (size_t)b * CC * HWN;
#pragma unroll
    for (int it = 0; it < 8; it++) {
        int r = w + it * 8;
        t[r][lane] = xb[(size_t)(cb + r) * HWN + nb + lane];
    }
    __syncthreads();
#pragma unroll
    for (int it = 0; it < 4; it++) {
        int idx = tid + it * 256;
        int n = idx >> 5;        // 0..31
        int cp = idx & 31;       // 0..31 (c pair)
        __half2 h = __floats2half2_rn(t[2 * cp][n], t[2 * cp + 1][n]);
        *(__half2*)&g_xh[((size_t)b * HWN + nb + n) * CC + cb + 2 * cp] = h;
    }
}

// ---------------- K0: zero scratch ----------------
__global__ void k0_init() {
    int i = blockIdx.x * blockDim.x + threadIdx.x;
    if (i < BB * KK * CC) g_enc[i] = 0.f;
    if (i < BB * HWN)     g_x2[i] = 0.f;
    if (i < BB * KK)      g_asum[i] = 0.f;
}

// ---------------- K1: HMMA fp16 GEMM + BN2 + relu -> fp16 feats, x2 ----------------
// R10-proven mainloop: 3-stage cp.async, barrier / compute / barrier / issue.
#define K1_STAGE  16384
#define K1_BNS    1024
#define SMEM_K1M  (K1_BNS + 3 * K1_STAGE)

__global__ void __launch_bounds__(256, 2) k1_mma(
    const float* __restrict__ g2, const float* __restrict__ b2,
    const float* __restrict__ m2, const float* __restrict__ v2)
{
    extern __shared__ char sm[];
    uint32_t sb = smem_u32(sm);
    int tid = threadIdx.x;
    int lane = tid & 31;
    int wid = tid >> 5;
    int warp_m = wid >> 1;       // 0..3
    int warp_n = wid & 1;        // 0..1
    int n0 = blockIdx.x * 128;   // output-channel base
    int m0 = blockIdx.y * 128;   // pixel base (b*HWN + n)

    float* bns = (float*)sm;
    float* bnh = (float*)(sm + 512);
    if (tid < 128) {
        int o = n0 + tid;
        float s = rsqrtf(v2[o] + EPSF) * g2[o];
        bns[tid] = s;
        bnh[tid] = b2[o] - m2[o] * s;
    }

    const __half* xh = g_xh + (size_t)m0 * CC;
    const __half* wh = g_wh + (size_t)n0 * CC;

    auto issue_stage = [&](int s) {
        uint32_t base = sb + K1_BNS + (s % 3) * K1_STAGE;
#pragma unroll
        for (int it = 0; it < 2; it++) {
            int idx = tid + it * 256;
            int row = idx >> 2, seg = idx & 3;
            uint32_t d = swz64((uint32_t)(row * 64 + seg * 16));
            size_t go = (size_t)row * CC + s * 32 + seg * 8;
            cpasync16(base + d,        xh + go);
            cpasync16(base + 8192 + d, wh + go);
        }
    };

    issue_stage(0); CP_COMMIT();
    issue_stage(1); CP_COMMIT();
    issue_stage(2); CP_COMMIT();

    float c[2][8][4];
#pragma unroll
    for (int i = 0; i < 2; i++)
#pragma unroll
        for (int j = 0; j < 8; j++)
#pragma unroll
            for (int l = 0; l < 4; l++) c[i][j][l] = 0.f;

    for (int s = 0; s < 16; s++) {
        CP_WAIT2();
        __syncthreads();
        uint32_t tb = sb + K1_BNS + (s % 3) * K1_STAGE;
#pragma unroll
        for (int kk = 0; kk < 2; kk++) {
            uint32_t bfr[4][4];
#pragma unroll
            for (int ng = 0; ng < 4; ng++) {
                uint32_t off = swz64((uint32_t)((warp_n * 64 + ng * 16 + (lane & 15)) * 64
                                               + kk * 32 + (lane >> 4) * 16));
                ldsm4(tb + 8192 + off, bfr[ng]);
            }
#pragma unroll
            for (int mt = 0; mt < 2; mt++) {
                uint32_t a[4];
                uint32_t off = swz64((uint32_t)((warp_m * 32 + mt * 16 + (lane & 15)) * 64
                                               + kk * 32 + (lane >> 4) * 16));
                ldsm4(tb + off, a);
#pragma unroll
                for (int ng = 0; ng < 4; ng++)
#pragma unroll
                    for (int h = 0; h < 2; h++)
                        mma_fp16(c[mt][ng * 2 + h], a, bfr[ng][h], bfr[ng][h + 2]);
            }
        }
        __syncthreads();
        if (s + 3 < 16) issue_stage(s + 3);
        CP_COMMIT();
    }

    // epilogue: BN2 + relu -> fp16 feats; x2 from the ROUNDED values
#pragma unroll
    for (int mt = 0; mt < 2; mt++) {
        int r0 = m0 + warp_m * 32 + mt * 16 + (lane >> 2);
        float q0 = 0.f, q1 = 0.f;
#pragma unroll
        for (int j = 0; j < 8; j++) {
            int cl = warp_n * 64 + j * 8 + (lane & 3) * 2;
            float s0 = bns[cl], h0 = bnh[cl];
            float s1 = bns[cl + 1], h1 = bnh[cl + 1];
            float v00 = fmaxf(fmaf(c[mt][j][0], s0, h0), 0.f);
            float v01 = fmaxf(fmaf(c[mt][j][1], s1, h1), 0.f);
            float v10 = fmaxf(fmaf(c[mt][j][2], s0, h0), 0.f);
            float v11 = fmaxf(fmaf(c[mt][j][3], s1, h1), 0.f);
            __half2 p0 = __floats2half2_rn(v00, v01);
            __half2 p1 = __floats2half2_rn(v10, v11);
            *(__half2*)&g_fh[(size_t)r0 * CC + n0 + cl] = p0;
            *(__half2*)&g_fh[(size_t)(r0 + 8) * CC + n0 + cl] = p1;
            float2 f0 = __half22float2(p0);
            float2 f1 = __half22float2(p1);
            q0 = fmaf(f0.x, f0.x, fmaf(f0.y, f0.y, q0));
            q1 = fmaf(f1.x, f1.x, fmaf(f1.y, f1.y, q1));
        }
        q0 += __shfl_xor_sync(0xffffffffu, q0, 1);
        q0 += __shfl_xor_sync(0xffffffffu, q0, 2);
        q1 += __shfl_xor_sync(0xffffffffu, q1, 1);
        q1 += __shfl_xor_sync(0xffffffffu, q1, 2);
        if ((lane & 3) == 0) {
            atomicAdd(&g_x2[r0], q0);
            atomicAdd(&g_x2[r0 + 8], q1);
        }
    }
}

// ---------------- K2: HMMA xc + fused softmax -> assign^T fp16, asum ----------------
#define K2_STG 10240
__global__ void __launch_bounds__(256) k2_assign(
    const float* __restrict__ cw, const float* __restrict__ scale)
{
    __shared__ __align__(16) char st[4 * K2_STG];
    __shared__ __half asn[32][136];
    __shared__ float c2s[32], x2s[128], scs[32];
    uint32_t sb = smem_u32(st);
    int tid = threadIdx.x;
    int lane = tid & 31, w = tid >> 5;
    int m0 = blockIdx.x * 128;
    int b = m0 >> 12;
    int n0 = m0 & (HWN - 1);

    auto issue = [&](int ch) {
        uint32_t base = sb + (ch & 3) * K2_STG;
#pragma unroll
        for (int it = 0; it < 2; it++) {
            int idx = tid + it * 256;
            int row = idx >> 2, seg = idx & 3;
            cpasync16(base + swz64((uint32_t)(row * 64 + seg * 16)),
                      g_fh + (size_t)(m0 + row) * CC + ch * 32 + seg * 8);
        }
        if (tid < 128) {
            int row = tid >> 2, seg = tid & 3;
            cpasync16(base + 8192 + swz64((uint32_t)(row * 64 + seg * 16)),
                      g_cwh + (size_t)row * CC + ch * 32 + seg * 8);
        }
    };
    issue(0); CP_COMMIT(); issue(1); CP_COMMIT(); issue(2); CP_COMMIT();

    {
        int k = tid >> 3, seg = tid & 7;
        const float* p = cw + k * CC + seg * 64;
        float s = 0.f;
#pragma unroll 16
        for (int i = 0; i < 64; i++) { float v = p[i]; s = fmaf(v, v, s); }
#pragma unroll
        for (int off = 4; off >= 1; off >>= 1)
            s += __shfl_xor_sync(0xffffffffu, s, off);
        if (seg == 0) c2s[k] = s;
        if (tid < 32) scs[tid] = scale[tid];
        if (tid < 128) x2s[tid] = g_x2[m0 + tid];
    }

    float c[4][4];
#pragma unroll
    for (int i = 0; i < 4; i++)
#pragma unroll
        for (int j = 0; j < 4; j++) c[i][j] = 0.f;

    for (int ch = 0; ch < 16; ch++) {
        CP_WAIT2();
        __syncthreads();
        if (ch + 3 < 16) issue(ch + 3);
        CP_COMMIT();
        uint32_t tb = sb + (ch & 3) * K2_STG;
#pragma unroll
        for (int kk = 0; kk < 2; kk++) {
            uint32_t a[4], b0[4], b1[4];
            ldsm4(tb + swz64((uint32_t)((w * 16 + (lane & 15)) * 64 + kk * 32 + (lane >> 4) * 16)), a);
            ldsm4(tb + 8192 + swz64((uint32_t)((lane & 15) * 64 + kk * 32 + (lane >> 4) * 16)), b0);
            ldsm4(tb + 8192 + swz64((uint32_t)((16 + (lane & 15)) * 64 + kk * 32 + (lane >> 4) * 16)), b1);
#pragma unroll
            for (int h = 0; h < 2; h++) {
                mma_fp16(c[h],     a, b0[h], b0[h + 2]);
                mma_fp16(c[2 + h], a, b1[h], b1[h + 2]);
            }
        }
    }
    __syncthreads();

    int q = lane & 3, r = lane >> 2;
#pragma unroll
    for (int half = 0; half < 2; half++) {
        int px = w * 16 + r + half * 8;
        float x2v = x2s[px];
        float d[8];
        float mx = -1e30f;
#pragma unroll
        for (int g = 0; g < 4; g++)
#pragma unroll
            for (int e = 0; e < 2; e++) {
                int k = g * 8 + q * 2 + e;
                float dd = scs[k] * (x2v - 2.f * c[g][half * 2 + e] + c2s[k]);
                d[g * 2 + e] = dd;
                mx = fmaxf(mx, dd);
            }
        mx = fmaxf(mx, __shfl_xor_sync(0xffffffffu, mx, 1));
        mx = fmaxf(mx, __shfl_xor_sync(0xffffffffu, mx, 2));
        float se = 0.f;
#pragma unroll
        for (int i = 0; i < 8; i++) { d[i] = __expf(d[i] - mx); se += d[i]; }
        se += __shfl_xor_sync(0xffffffffu, se, 1);
        se += __shfl_xor_sync(0xffffffffu, se, 2);
        float inv = 1.f / se;
#pragma unroll
        for (int g = 0; g < 4; g++)
#pragma unroll
            for (int e = 0; e < 2; e++)
                asn[g * 8 + q * 2 + e][px] = __float2half(d[g * 2 + e] * inv);
    }
    __syncthreads();

    {
        int k = tid >> 3, seg = tid & 7;
        float s = 0.f;
#pragma unroll
        for (int j = 0; j < 16; j++)
            s += __half2float(asn[k][seg * 16 + j]);
        s += __shfl_xor_sync(0xffffffffu, s, 1);
        s += __shfl_xor_sync(0xffffffffu, s, 2);
        s += __shfl_xor_sync(0xffffffffu, s, 4);
        if (seg == 0) atomicAdd(&g_asum[b * KK + k], s);
    }
#pragma unroll
    for (int it = 0; it < 2; it++) {
        int idx = tid + it * 256;
        int row = idx >> 4, cs = idx & 15;
        uint4 v = *(const uint4*)&asn[row][cs * 8];
        *(uint4*)&g_asnT[((size_t)b * KK + row) * HWN + n0 + cs * 8] = v;
    }
}

// ---------------- K3: HMMA encoded^T[c][k] = feats^T @ assign^T, atomic acc ----------------
#define K3_STG 10240
__global__ void __launch_bounds__(256) k3_agg()
{
    __shared__ __align__(16) char st[4 * K3_STG];
    uint32_t sb = smem_u32(st);
    int tid = threadIdx.x, lane = tid & 31, w = tid >> 5;
    int b = blockIdx.z;
    int c0 = blockIdx.x * 128;
    int n0 = blockIdx.y * (HWN / NSPLIT);
    size_t m0 = (size_t)b * HWN + n0;

    auto issue = [&](int ch) {
        uint32_t base = sb + (ch & 3) * K3_STG;
#pragma unroll
        for (int it = 0; it < 2; it++) {
            int idx = tid + it * 256;
            int row = idx >> 4, seg = idx & 15;
            cpasync16(base + swz256((uint32_t)(row * 256 + seg * 16)),
                      g_fh + (m0 + ch * 32 + row) * CC + c0 + seg * 8);
        }
        if (tid < 128) {
            int row = tid >> 2, seg = tid & 3;
            cpasync16(base + 8192 + swz64((uint32_t)(row * 64 + seg * 16)),
                      g_asnT + ((size_t)b * KK + row) * HWN + n0 + ch * 32 + seg * 8);
        }
    };
    issue(0); CP_COMMIT(); issue(1); CP_COMMIT(); issue(2); CP_COMMIT();

    float c[4][4];
#pragma unroll
    for (int i = 0; i < 4; i++)
#pragma unroll
        for (int j = 0; j < 4; j++) c[i][j] = 0.f;

    for (int ch = 0; ch < 16; ch++) {
        CP_WAIT2();
        __syncthreads();
        if (ch + 3 < 16) issue(ch + 3);
        CP_COMMIT();
        uint32_t tb = sb + (ch & 3) * K3_STG;
#pragma unroll
        for (int kk = 0; kk < 2; kk++) {
            uint32_t a[4], b0[4], b1[4];
            int arow = kk * 16 + ((lane >> 4) << 3) + (lane & 7);
            int acol = w * 16 + (((lane >> 3) & 1) << 3);
            ldsm4t(tb + swz256((uint32_t)(arow * 256 + acol * 2)), a);
            ldsm4(tb + 8192 + swz64((uint32_t)((lane & 15) * 64 + kk * 32 + (lane >> 4) * 16)), b0);
            ldsm4(tb + 8192 + swz64((uint32_t)((16 + (lane & 15)) * 64 + kk * 32 + (lane >> 4) * 16)), b1);
#pragma unroll
            for (int h = 0; h < 2; h++) {
                mma_fp16(c[h],     a, b0[h], b0[h + 2]);
                mma_fp16(c[2 + h], a, b1[h], b1[h + 2]);
            }
        }
    }

    int q = lane & 3, r = lane >> 2;
#pragma unroll
    for (int half = 0; half < 2; half++) {
        int cr = c0 + w * 16 + r + half * 8;
#pragma unroll
        for (int g = 0; g < 4; g++)
#pragma unroll
            for (int e = 0; e < 2; e++) {
                int k = g * 8 + q * 2 + e;
                atomicAdd(&g_enc[((size_t)b * KK + k) * CC + cr], c[g][half * 2 + e]);
            }
    }
}

// ---------------- K4 ----------------
__global__ void k4_ef(
    const float* __restrict__ cw, const float* __restrict__ g1,
    const float* __restrict__ b1, const float* __restrict__ m1,
    const float* __restrict__ v1, float* __restrict__ ef_out)
{
    int b = blockIdx.y;
    int c = blockIdx.x * 128 + threadIdx.x;
    float s = 0.f;
#pragma unroll
    for (int k = 0; k < KK; k++) {
        float e = g_enc[((size_t)b * KK + k) * CC + c] - g_asum[b * KK + k] * cw[(size_t)k * CC + c];
        float sc = rsqrtf(v1[k] + EPSF) * g1[k];
        e = fmaf(e - m1[k], sc, b1[k]);
        e = fmaxf(e, 0.f);
        s += e;
    }
    ef_out[b * CC + c] = s * (1.f / KK);
}

// ---------------- K5 ----------------
__global__ void __launch_bounds__(512) k5_gamma(
    const float* __restrict__ fcw, const float* __restrict__ fcb,
    const float* __restrict__ ef)
{
    __shared__ float efs[CC];
    int b = blockIdx.x;
    int o = threadIdx.x;
    efs[o] = ef[b * CC + o];
    __syncthreads();
    const float* wr = fcw + (size_t)o * CC;
    float s = fcb[o];
#pragma unroll 8
    for (int c = 0; c < CC; c += 4) {
        float4 w4 = *(const float4*)&wr[c];
        s = fmaf(w4.x, efs[c + 0], s);
        s = fmaf(w4.y, efs[c + 1], s);
        s = fmaf(w4.z, efs[c + 2], s);
        s = fmaf(w4.w, efs[c + 3], s);
    }
    g_gamma[b * CC + o] = 1.f / (1.f + __expf(-s));
}

// ---------------- K6 ----------------
__global__ void __launch_bounds__(256) k6_out(
    const float* __restrict__ x, float* __restrict__ out)
{
    size_t i4 = (size_t)blockIdx.x * blockDim.x + threadIdx.x;
    size_t total4 = (size_t)BB * CC * HWN / 4;
    if (i4 >= total4) return;
    size_t i = i4 * 4;
    int bc = (int)(i >> 12);
    float g = 1.f + g_gamma[bc];
    float4 v = *(const float4*)&x[i];
    v.x = fmaxf(v.x * g, 0.f);
    v.y = fmaxf(v.y * g, 0.f);
    v.z = fmaxf(v.z * g, 0.f);
    v.w = fmaxf(v.w * g, 0.f);
    *(float4*)&out[i] = v;
}

// ---------------- launch ----------------
extern "C" void kernel_launch(void* const* d_in, const int* in_sizes, int n_in,
                              void* d_out, int out_size)
{
    const float* x      = (const float*)d_in[0];
    const float* conv_w = (const float*)d_in[1];
    const float* bn2_g  = (const float*)d_in[2];
    const float* bn2_b  = (const float*)d_in[3];
    const float* bn2_m  = (const float*)d_in[4];
    const float* bn2_v  = (const float*)d_in[5];
    const float* cw     = (const float*)d_in[6];
    const float* scale  = (const float*)d_in[7];
    const float* bn1_g  = (const float*)d_in[8];
    const float* bn1_b  = (const float*)d_in[9];
    const float* bn1_m  = (const float*)d_in[10];
    const float* bn1_v  = (const float*)d_in[11];
    const float* fc_w   = (const float*)d_in[12];
    const float* fc_b   = (const float*)d_in[13];
    float* out = (float*)d_out;   // [0:8192) encoding_feat, [8192:) output

    static bool attr_set = false;
    if (!attr_set) {
        cudaFuncSetAttribute(k1_mma, cudaFuncAttributeMaxDynamicSharedMemorySize, SMEM_K1M);
        attr_set = true;
    }

    kpw<<<(CC * CC + 255) / 256, 256>>>(conv_w, cw);

    dim3 gpx(HWN / 32, CC / 64, BB);
    kpx<<<gpx, 256>>>(x);

    k0_init<<<1024, 256>>>();

    dim3 g1(CC / 128, BB * HWN / 128);   // (4, 512)
    k1_mma<<<g1, 256, SMEM_K1M>>>(bn2_g, bn2_b, bn2_m, bn2_v);

    k2_assign<<<BB * HWN / 128, 256>>>(cw, scale);

    dim3 g3(CC / 128, NSPLIT, BB);
    k3_agg<<<g3, 256>>>();

    dim3 g4(CC / 128, BB);
    k4_ef<<<g4, 128>>>(cw, bn1_g, bn1_b, bn1_m, bn1_v, out);

    k5_gamma<<<BB, 512>>>(fc_w, fc_b, out);

    k6_out<<<(BB * CC * HWN / 4 + 255) / 256, 256>>>(x, out + BB * CC);
}

// round 13
// speedup vs baseline: 2.4870x; 1.0325x over previous
#include <cuda_runtime.h>
#include <cuda_bf16.h>
#include <cuda_fp16.h>
#include <cstdint>
#include <math.h>

#define BB 16
#define CC 512
#define KK 32
#define HWN 4096
#define EPSF 1e-5f
#define NSPLIT 8

// ---------------- scratch (static device globals: no allocation) ----------------
__device__ __half g_fh[(size_t)BB * HWN * CC];     // feats fp16 (b,n,c) 67 MB
__device__ __half g_asnT[(size_t)BB * KK * HWN];   // assign^T fp16 (b,k,n) 4 MB
__device__ float g_x2[BB * HWN];                   // per-pixel ||feats||^2
__device__ float g_enc[BB * KK * CC];              // partial encoded
__device__ float g_asum[BB * KK];                  // sum_n assign
__device__ float g_gamma[BB * CC];
__device__ __half g_xh[(size_t)BB * HWN * CC];     // x^T (b,n,c) fp16  67 MB
__device__ __half g_wh[CC * CC];                   // conv_w fp16
__device__ __half g_cwh[KK * CC];                  // codewords fp16

// ---------------- helpers ----------------
__device__ __forceinline__ uint32_t smem_u32(const void* p) {
    uint32_t a;
    asm("{ .reg .u64 t; cvta.to.shared.u64 t, %1; cvt.u32.u64 %0, t; }" : "=r"(a) : "l"(p));
    return a;
}
__device__ __forceinline__ uint32_t swz64(uint32_t o)  { return o ^ ((o >> 3) & 0x30); }
__device__ __forceinline__ uint32_t swz256(uint32_t o) { return o ^ ((o >> 4) & 0x70); }

__device__ __forceinline__ void cpasync16(uint32_t dst, const void* src) {
    asm volatile("cp.async.cg.shared.global [%0], [%1], 16;"
                 :: "r"(dst), "l"(__cvta_generic_to_global(src)) : "memory");
}
#define CP_COMMIT() asm volatile("cp.async.commit_group;" ::: "memory")
#define CP_WAIT2()  asm volatile("cp.async.wait_group 2;" ::: "memory")

__device__ __forceinline__ void ldsm4(uint32_t addr, uint32_t* r) {
    asm volatile("ldmatrix.sync.aligned.m8n8.x4.shared.b16 {%0,%1,%2,%3}, [%4];"
                 : "=r"(r[0]), "=r"(r[1]), "=r"(r[2]), "=r"(r[3]) : "r"(addr));
}
__device__ __forceinline__ void ldsm4t(uint32_t addr, uint32_t* r) {
    asm volatile("ldmatrix.sync.aligned.m8n8.x4.trans.shared.b16 {%0,%1,%2,%3}, [%4];"
                 : "=r"(r[0]), "=r"(r[1]), "=r"(r[2]), "=r"(r[3]) : "r"(addr));
}
__device__ __forceinline__ void mma_fp16(float* c, const uint32_t* a, uint32_t b0, uint32_t b1) {
    asm volatile(
        "mma.sync.aligned.m16n8k16.row.col.f32.f16.f16.f32 "
        "{%0,%1,%2,%3}, {%4,%5,%6,%7}, {%8,%9}, {%0,%1,%2,%3};"
        : "+f"(c[0]), "+f"(c[1]), "+f"(c[2]), "+f"(c[3])
        : "r"(a[0]), "r"(a[1]), "r"(a[2]), "r"(a[3]), "r"(b0), "r"(b1));
}

// ---------------- K_pre_w: conv_w + codewords -> fp16; also zero scratch ----------------
__global__ void kpw(const float* __restrict__ w, const float* __restrict__ cw) {
    int i = blockIdx.x * blockDim.x + threadIdx.x;
    if (i < CC * CC) g_wh[i] = __float2half(w[i]);
    if (i < KK * CC) g_cwh[i] = __float2half(cw[i]);
    if (i < BB * KK * CC) g_enc[i] = 0.f;      // BB*KK*CC == CC*CC == grid coverage
    if (i < BB * HWN)     g_x2[i] = 0.f;
    if (i < BB * KK)      g_asum[i] = 0.f;
}

// ---------------- K_pre_x: transpose x (b,c,n)->(b,n,c) + fp16, half2 writes ----------------
__global__ void __launch_bounds__(256) kpx(const float* __restrict__ x) {
    __shared__ float t[64][33];
    int tid = threadIdx.x;
    int lane = tid & 31, w = tid >> 5;
    int b = blockIdx.z;
    int cb = blockIdx.y * 64;
    int nb = blockIdx.x * 32;
    const float* xb = x + (size_t)b * CC * HWN;
#pragma unroll
    for (int it = 0; it < 8; it++) {
        int r = w + it * 8;
        t[r][lane] = xb[(size_t)(cb + r) * HWN + nb + lane];
    }
    __syncthreads();
#pragma unroll
    for (int it = 0; it < 4; it++) {
        int idx = tid + it * 256;
        int n = idx >> 5;        // 0..31
        int cp = idx & 31;       // 0..31 (c pair)
        __half2 h = __floats2half2_rn(t[2 * cp][n], t[2 * cp + 1][n]);
        *(__half2*)&g_xh[((size_t)b * HWN + nb + n) * CC + cb + 2 * cp] = h;
    }
}

// ---------------- K1: HMMA fp16 GEMM + BN2 + relu -> fp16 feats, x2 ----------------
// 3-stage cp.async, barrier / compute / barrier / issue; frag loads hoisted per kk.
#define K1_STAGE  16384
#define K1_BNS    1024
#define SMEM_K1M  (K1_BNS + 3 * K1_STAGE)

__global__ void __launch_bounds__(256, 2) k1_mma(
    const float* __restrict__ g2, const float* __restrict__ b2,
    const float* __restrict__ m2, const float* __restrict__ v2)
{
    extern __shared__ char sm[];
    uint32_t sb = smem_u32(sm);
    int tid = threadIdx.x;
    int lane = tid & 31;
    int wid = tid >> 5;
    int warp_m = wid >> 1;       // 0..3
    int warp_n = wid & 1;        // 0..1
    int n0 = blockIdx.x * 128;   // output-channel base
    int m0 = blockIdx.y * 128;   // pixel base (b*HWN + n)

    float* bns = (float*)sm;
    float* bnh = (float*)(sm + 512);
    if (tid < 128) {
        int o = n0 + tid;
        float s = rsqrtf(v2[o] + EPSF) * g2[o];
        bns[tid] = s;
        bnh[tid] = b2[o] - m2[o] * s;
    }

    const __half* xh = g_xh + (size_t)m0 * CC;
    const __half* wh = g_wh + (size_t)n0 * CC;

    auto issue_stage = [&](int s) {
        uint32_t base = sb + K1_BNS + (s % 3) * K1_STAGE;
#pragma unroll
        for (int it = 0; it < 2; it++) {
            int idx = tid + it * 256;
            int row = idx >> 2, seg = idx & 3;
            uint32_t d = swz64((uint32_t)(row * 64 + seg * 16));
            size_t go = (size_t)row * CC + s * 32 + seg * 8;
            cpasync16(base + d,        xh + go);
            cpasync16(base + 8192 + d, wh + go);
        }
    };

    issue_stage(0); CP_COMMIT();
    issue_stage(1); CP_COMMIT();
    issue_stage(2); CP_COMMIT();

    float c[2][8][4];
#pragma unroll
    for (int i = 0; i < 2; i++)
#pragma unroll
        for (int j = 0; j < 8; j++)
#pragma unroll
            for (int l = 0; l < 4; l++) c[i][j][l] = 0.f;

    for (int s = 0; s < 16; s++) {
        CP_WAIT2();
        __syncthreads();
        uint32_t tb = sb + K1_BNS + (s % 3) * K1_STAGE;
#pragma unroll
        for (int kk = 0; kk < 2; kk++) {
            // hoist ALL fragment loads for this kk before the mma block
            uint32_t bfr[4][4], a2[2][4];
#pragma unroll
            for (int ng = 0; ng < 4; ng++) {
                uint32_t off = swz64((uint32_t)((warp_n * 64 + ng * 16 + (lane & 15)) * 64
                                               + kk * 32 + (lane >> 4) * 16));
                ldsm4(tb + 8192 + off, bfr[ng]);
            }
#pragma unroll
            for (int mt = 0; mt < 2; mt++) {
                uint32_t off = swz64((uint32_t)((warp_m * 32 + mt * 16 + (lane & 15)) * 64
                                               + kk * 32 + (lane >> 4) * 16));
                ldsm4(tb + off, a2[mt]);
            }
#pragma unroll
            for (int mt = 0; mt < 2; mt++)
#pragma unroll
                for (int ng = 0; ng < 4; ng++)
#pragma unroll
                    for (int h = 0; h < 2; h++)
                        mma_fp16(c[mt][ng * 2 + h], a2[mt], bfr[ng][h], bfr[ng][h + 2]);
        }
        __syncthreads();
        if (s + 3 < 16) issue_stage(s + 3);
        CP_COMMIT();
    }

    // epilogue: BN2 + relu -> fp16 feats; x2 from the ROUNDED values
#pragma unroll
    for (int mt = 0; mt < 2; mt++) {
        int r0 = m0 + warp_m * 32 + mt * 16 + (lane >> 2);
        float q0 = 0.f, q1 = 0.f;
#pragma unroll
        for (int j = 0; j < 8; j++) {
            int cl = warp_n * 64 + j * 8 + (lane & 3) * 2;
            float s0 = bns[cl], h0 = bnh[cl];
            float s1 = bns[cl + 1], h1 = bnh[cl + 1];
            float v00 = fmaxf(fmaf(c[mt][j][0], s0, h0), 0.f);
            float v01 = fmaxf(fmaf(c[mt][j][1], s1, h1), 0.f);
            float v10 = fmaxf(fmaf(c[mt][j][2], s0, h0), 0.f);
            float v11 = fmaxf(fmaf(c[mt][j][3], s1, h1), 0.f);
            __half2 p0 = __floats2half2_rn(v00, v01);
            __half2 p1 = __floats2half2_rn(v10, v11);
            *(__half2*)&g_fh[(size_t)r0 * CC + n0 + cl] = p0;
            *(__half2*)&g_fh[(size_t)(r0 + 8) * CC + n0 + cl] = p1;
            float2 f0 = __half22float2(p0);
            float2 f1 = __half22float2(p1);
            q0 = fmaf(f0.x, f0.x, fmaf(f0.y, f0.y, q0));
            q1 = fmaf(f1.x, f1.x, fmaf(f1.y, f1.y, q1));
        }
        q0 += __shfl_xor_sync(0xffffffffu, q0, 1);
        q0 += __shfl_xor_sync(0xffffffffu, q0, 2);
        q1 += __shfl_xor_sync(0xffffffffu, q1, 1);
        q1 += __shfl_xor_sync(0xffffffffu, q1, 2);
        if ((lane & 3) == 0) {
            atomicAdd(&g_x2[r0], q0);
            atomicAdd(&g_x2[r0 + 8], q1);
        }
    }
}

// ---------------- K2: HMMA xc + fused softmax -> assign^T fp16, asum ----------------
#define K2_STG 10240
__global__ void __launch_bounds__(256) k2_assign(
    const float* __restrict__ cw, const float* __restrict__ scale)
{
    __shared__ __align__(16) char st[4 * K2_STG];
    __shared__ __half asn[32][136];
    __shared__ float c2s[32], x2s[128], scs[32];
    uint32_t sb = smem_u32(st);
    int tid = threadIdx.x;
    int lane = tid & 31, w = tid >> 5;
    int m0 = blockIdx.x * 128;
    int b = m0 >> 12;
    int n0 = m0 & (HWN - 1);

    auto issue = [&](int ch) {
        uint32_t base = sb + (ch & 3) * K2_STG;
#pragma unroll
        for (int it = 0; it < 2; it++) {
            int idx = tid + it * 256;
            int row = idx >> 2, seg = idx & 3;
            cpasync16(base + swz64((uint32_t)(row * 64 + seg * 16)),
                      g_fh + (size_t)(m0 + row) * CC + ch * 32 + seg * 8);
        }
        if (tid < 128) {
            int row = tid >> 2, seg = tid & 3;
            cpasync16(base + 8192 + swz64((uint32_t)(row * 64 + seg * 16)),
                      g_cwh + (size_t)row * CC + ch * 32 + seg * 8);
        }
    };
    issue(0); CP_COMMIT(); issue(1); CP_COMMIT(); issue(2); CP_COMMIT();

    {
        int k = tid >> 3, seg = tid & 7;
        const float* p = cw + k * CC + seg * 64;
        float s = 0.f;
#pragma unroll 16
        for (int i = 0; i < 64; i++) { float v = p[i]; s = fmaf(v, v, s); }
#pragma unroll
        for (int off = 4; off >= 1; off >>= 1)
            s += __shfl_xor_sync(0xffffffffu, s, off);
        if (seg == 0) c2s[k] = s;
        if (tid < 32) scs[tid] = scale[tid];
        if (tid < 128) x2s[tid] = g_x2[m0 + tid];
    }

    float c[4][4];
#pragma unroll
    for (int i = 0; i < 4; i++)
#pragma unroll
        for (int j = 0; j < 4; j++) c[i][j] = 0.f;

    for (int ch = 0; ch < 16; ch++) {
        CP_WAIT2();
        __syncthreads();
        if (ch + 3 < 16) issue(ch + 3);
        CP_COMMIT();
        uint32_t tb = sb + (ch & 3) * K2_STG;
#pragma unroll
        for (int kk = 0; kk < 2; kk++) {
            uint32_t a[4], b0[4], b1[4];
            ldsm4(tb + swz64((uint32_t)((w * 16 + (lane & 15)) * 64 + kk * 32 + (lane >> 4) * 16)), a);
            ldsm4(tb + 8192 + swz64((uint32_t)((lane & 15) * 64 + kk * 32 + (lane >> 4) * 16)), b0);
            ldsm4(tb + 8192 + swz64((uint32_t)((16 + (lane & 15)) * 64 + kk * 32 + (lane >> 4) * 16)), b1);
#pragma unroll
            for (int h = 0; h < 2; h++) {
                mma_fp16(c[h],     a, b0[h], b0[h + 2]);
                mma_fp16(c[2 + h], a, b1[h], b1[h + 2]);
            }
        }
    }
    __syncthreads();

    int q = lane & 3, r = lane >> 2;
#pragma unroll
    for (int half = 0; half < 2; half++) {
        int px = w * 16 + r + half * 8;
        float x2v = x2s[px];
        float d[8];
        float mx = -1e30f;
#pragma unroll
        for (int g = 0; g < 4; g++)
#pragma unroll
            for (int e = 0; e < 2; e++) {
                int k = g * 8 + q * 2 + e;
                float dd = scs[k] * (x2v - 2.f * c[g][half * 2 + e] + c2s[k]);
                d[g * 2 + e] = dd;
                mx = fmaxf(mx, dd);
            }
        mx = fmaxf(mx, __shfl_xor_sync(0xffffffffu, mx, 1));
        mx = fmaxf(mx, __shfl_xor_sync(0xffffffffu, mx, 2));
        float se = 0.f;
#pragma unroll
        for (int i = 0; i < 8; i++) { d[i] = __expf(d[i] - mx); se += d[i]; }
        se += __shfl_xor_sync(0xffffffffu, se, 1);
        se += __shfl_xor_sync(0xffffffffu, se, 2);
        float inv = 1.f / se;
#pragma unroll
        for (int g = 0; g < 4; g++)
#pragma unroll
            for (int e = 0; e < 2; e++)
                asn[g * 8 + q * 2 + e][px] = __float2half(d[g * 2 + e] * inv);
    }
    __syncthreads();

    {
        int k = tid >> 3, seg = tid & 7;
        float s = 0.f;
#pragma unroll
        for (int j = 0; j < 16; j++)
            s += __half2float(asn[k][seg * 16 + j]);
        s += __shfl_xor_sync(0xffffffffu, s, 1);
        s += __shfl_xor_sync(0xffffffffu, s, 2);
        s += __shfl_xor_sync(0xffffffffu, s, 4);
        if (seg == 0) atomicAdd(&g_asum[b * KK + k], s);
    }
#pragma unroll
    for (int it = 0; it < 2; it++) {
        int idx = tid + it * 256;
        int row = idx >> 4, cs = idx & 15;
        uint4 v = *(const uint4*)&asn[row][cs * 8];
        *(uint4*)&g_asnT[((size_t)b * KK + row) * HWN + n0 + cs * 8] = v;
    }
}

// ---------------- K3: HMMA encoded^T[c][k] = feats^T @ assign^T, atomic acc ----------------
#define K3_STG 10240
__global__ void __launch_bounds__(256) k3_agg()
{
    __shared__ __align__(16) char st[4 * K3_STG];
    uint32_t sb = smem_u32(st);
    int tid = threadIdx.x, lane = tid & 31, w = tid >> 5;
    int b = blockIdx.z;
    int c0 = blockIdx.x * 128;
    int n0 = blockIdx.y * (HWN / NSPLIT);
    size_t m0 = (size_t)b * HWN + n0;

    auto issue = [&](int ch) {
        uint32_t base = sb + (ch & 3) * K3_STG;
#pragma unroll
        for (int it = 0; it < 2; it++) {
            int idx = tid + it * 256;
            int row = idx >> 4, seg = idx & 15;
            cpasync16(base + swz256((uint32_t)(row * 256 + seg * 16)),
                      g_fh + (m0 + ch * 32 + row) * CC + c0 + seg * 8);
        }
        if (tid < 128) {
            int row = tid >> 2, seg = tid & 3;
            cpasync16(base + 8192 + swz64((uint32_t)(row * 64 + seg * 16)),
                      g_asnT + ((size_t)b * KK + row) * HWN + n0 + ch * 32 + seg * 8);
        }
    };
    issue(0); CP_COMMIT(); issue(1); CP_COMMIT(); issue(2); CP_COMMIT();

    float c[4][4];
#pragma unroll
    for (int i = 0; i < 4; i++)
#pragma unroll
        for (int j = 0; j < 4; j++) c[i][j] = 0.f;

    for (int ch = 0; ch < 16; ch++) {
        CP_WAIT2();
        __syncthreads();
        if (ch + 3 < 16) issue(ch + 3);
        CP_COMMIT();
        uint32_t tb = sb + (ch & 3) * K3_STG;
#pragma unroll
        for (int kk = 0; kk < 2; kk++) {
            uint32_t a[4], b0[4], b1[4];
            int arow = kk * 16 + ((lane >> 4) << 3) + (lane & 7);
            int acol = w * 16 + (((lane >> 3) & 1) << 3);
            ldsm4t(tb + swz256((uint32_t)(arow * 256 + acol * 2)), a);
            ldsm4(tb + 8192 + swz64((uint32_t)((lane & 15) * 64 + kk * 32 + (lane >> 4) * 16)), b0);
            ldsm4(tb + 8192 + swz64((uint32_t)((16 + (lane & 15)) * 64 + kk * 32 + (lane >> 4) * 16)), b1);
#pragma unroll
            for (int h = 0; h < 2; h++) {
                mma_fp16(c[h],     a, b0[h], b0[h + 2]);
                mma_fp16(c[2 + h], a, b1[h], b1[h + 2]);
            }
        }
    }

    int q = lane & 3, r = lane >> 2;
#pragma unroll
    for (int half = 0; half < 2; half++) {
        int cr = c0 + w * 16 + r + half * 8;
#pragma unroll
        for (int g = 0; g < 4; g++)
#pragma unroll
            for (int e = 0; e < 2; e++) {
                int k = g * 8 + q * 2 + e;
                atomicAdd(&g_enc[((size_t)b * KK + k) * CC + cr], c[g][half * 2 + e]);
            }
    }
}

// ---------------- K45: ef (BN1+relu+mean) then gamma = sigmoid(fc) ----------------
__global__ void __launch_bounds__(512) k45(
    const float* __restrict__ cw, const float* __restrict__ g1,
    const float* __restrict__ b1, const float* __restrict__ m1,
    const float* __restrict__ v1,
    const float* __restrict__ fcw, const float* __restrict__ fcb,
    float* __restrict__ ef_out)
{
    __shared__ float efs[CC];
    int b = blockIdx.x;
    int o = threadIdx.x;   // 0..511
    float s = 0.f;
#pragma unroll
    for (int k = 0; k < KK; k++) {
        float e = g_enc[((size_t)b * KK + k) * CC + o] - g_asum[b * KK + k] * cw[(size_t)k * CC + o];
        float sc = rsqrtf(v1[k] + EPSF) * g1[k];
        e = fmaf(e - m1[k], sc, b1[k]);
        e = fmaxf(e, 0.f);
        s += e;
    }
    float ef = s * (1.f / KK);
    efs[o] = ef;
    ef_out[b * CC + o] = ef;
    __syncthreads();

    const float* wr = fcw + (size_t)o * CC;
    float g = fcb[o];
#pragma unroll 8
    for (int c = 0; c < CC; c += 4) {
        float4 w4 = *(const float4*)&wr[c];
        g = fmaf(w4.x, efs[c + 0], g);
        g = fmaf(w4.y, efs[c + 1], g);
        g = fmaf(w4.z, efs[c + 2], g);
        g = fmaf(w4.w, efs[c + 3], g);
    }
    g_gamma[b * CC + o] = 1.f / (1.f + __expf(-g));
}

// ---------------- K6: output = relu(x*(1+gamma)) reading fp16 x^T (smem transpose) ----------------
// grid (HWN/64, CC/64, BB), block 256. smem tile 64n x 64c fp16, XOR-swizzled.
__global__ void __launch_bounds__(256) k6_out(float* __restrict__ out)
{
    __shared__ __align__(16) __half t[64 * 64];
    int tid = threadIdx.x;
    int b  = blockIdx.z;
    int cb = blockIdx.y * 64;
    int nb = blockIdx.x * 64;

    // store phase: row n = 8 uint4 segs, phys seg = seg ^ ((n>>2)&7)
#pragma unroll
    for (int it = 0; it < 2; it++) {
        int idx = tid + it * 256;
        int n = idx >> 3, seg = idx & 7;
        int phys = seg ^ ((n >> 2) & 7);
        uint4 v = *(const uint4*)&g_xh[((size_t)b * HWN + nb + n) * CC + cb + seg * 8];
        *(uint4*)&t[n * 64 + phys * 8] = v;
    }
    __syncthreads();

    // load phase: thread handles (c, 4 consecutive n)
#pragma unroll
    for (int it = 0; it < 4; it++) {
        int idx = tid + it * 256;
        int c = idx >> 4;              // 0..63
        int nb4 = (idx & 15) * 4;      // 0,4,..60
        float g = 1.f + g_gamma[b * CC + cb + c];
        int seg = c >> 3, coff = c & 7;
        float4 o;
        float* op = &o.x;
#pragma unroll
        for (int dn = 0; dn < 4; dn++) {
            int n = nb4 + dn;
            int phys = seg ^ ((n >> 2) & 7);
            float v = __half2float(t[n * 64 + phys * 8 + coff]);
            op[dn] = fmaxf(v * g, 0.f);
        }
        *(float4*)&out[((size_t)b * CC + cb + c) * HWN + nb + nb4] = o;
    }
}

// ---------------- launch ----------------
extern "C" void kernel_launch(void* const* d_in, const int* in_sizes, int n_in,
                              void* d_out, int out_size)
{
    const float* x      = (const float*)d_in[0];
    const float* conv_w = (const float*)d_in[1];
    const float* bn2_g  = (const float*)d_in[2];
    const float* bn2_b  = (const float*)d_in[3];
    const float* bn2_m  = (const float*)d_in[4];
    const float* bn2_v  = (const float*)d_in[5];
    const float* cw     = (const float*)d_in[6];
    const float* scale  = (const float*)d_in[7];
    const float* bn1_g  = (const float*)d_in[8];
    const float* bn1_b  = (const float*)d_in[9];
    const float* bn1_m  = (const float*)d_in[10];
    const float* bn1_v  = (const float*)d_in[11];
    const float* fc_w   = (const float*)d_in[12];
    const float* fc_b   = (const float*)d_in[13];
    float* out = (float*)d_out;   // [0:8192) encoding_feat, [8192:) output

    static bool attr_set = false;
    if (!attr_set) {
        cudaFuncSetAttribute(k1_mma, cudaFuncAttributeMaxDynamicSharedMemorySize, SMEM_K1M);
        attr_set = true;
    }

    kpw<<<(CC * CC + 255) / 256, 256>>>(conv_w, cw);

    dim3 gpx(HWN / 32, CC / 64, BB);
    kpx<<<gpx, 256>>>(x);

    dim3 g1(CC / 128, BB * HWN / 128);   // (4, 512)
    k1_mma<<<g1, 256, SMEM_K1M>>>(bn2_g, bn2_b, bn2_m, bn2_v);

    k2_assign<<<BB * HWN / 128, 256>>>(cw, scale);

    dim3 g3(CC / 128, NSPLIT, BB);
    k3_agg<<<g3, 256>>>();

    k45<<<BB, 512>>>(cw, bn1_g, bn1_b, bn1_m, bn1_v, fc_w, fc_b, out);

    dim3 g6(HWN / 64, CC / 64, BB);
    k6_out<<<g6, 256>>>(out + BB * CC);
}

// round 15
// speedup vs baseline: 2.5204x; 1.0134x over previous
#include <cuda_runtime.h>
#include <cuda_bf16.h>
#include <cuda_fp16.h>
#include <cstdint>
#include <math.h>

#define BB 16
#define CC 512
#define KK 32
#define HWN 4096
#define EPSF 1e-5f
#define NSPLIT 8

// ---------------- scratch (static device globals: no allocation) ----------------
__device__ __half g_fh[(size_t)BB * HWN * CC];     // feats fp16 (b,n,c) 67 MB
__device__ __half g_asnT[(size_t)BB * KK * HWN];   // assign^T fp16 (b,k,n) 4 MB
__device__ float g_x2[BB * HWN];                   // per-pixel ||feats||^2
__device__ float g_enc[BB * KK * CC];              // partial encoded
__device__ float g_asum[BB * KK];                  // sum_n assign
__device__ float g_gamma[BB * CC];
__device__ __half g_xh[(size_t)BB * HWN * CC];     // x^T (b,n,c) fp16  67 MB
__device__ __half g_wh[CC * CC];                   // conv_w fp16
__device__ __half g_cwh[KK * CC];                  // codewords fp16

// ---------------- helpers ----------------
__device__ __forceinline__ uint32_t smem_u32(const void* p) {
    uint32_t a;
    asm("{ .reg .u64 t; cvta.to.shared.u64 t, %1; cvt.u32.u64 %0, t; }" : "=r"(a) : "l"(p));
    return a;
}
__device__ __forceinline__ uint32_t swz64(uint32_t o)  { return o ^ ((o >> 3) & 0x30); }
__device__ __forceinline__ uint32_t swz128(uint32_t o) { return o ^ ((o >> 3) & 0x70); }
__device__ __forceinline__ uint32_t swz256(uint32_t o) { return o ^ ((o >> 4) & 0x70); }

__device__ __forceinline__ void cpasync16(uint32_t dst, const void* src) {
    asm volatile("cp.async.cg.shared.global [%0], [%1], 16;"
                 :: "r"(dst), "l"(__cvta_generic_to_global(src)) : "memory");
}
#define CP_COMMIT() asm volatile("cp.async.commit_group;" ::: "memory")
#define CP_WAIT2()  asm volatile("cp.async.wait_group 2;" ::: "memory")

__device__ __forceinline__ void ldsm4(uint32_t addr, uint32_t* r) {
    asm volatile("ldmatrix.sync.aligned.m8n8.x4.shared.b16 {%0,%1,%2,%3}, [%4];"
                 : "=r"(r[0]), "=r"(r[1]), "=r"(r[2]), "=r"(r[3]) : "r"(addr));
}
__device__ __forceinline__ void ldsm4t(uint32_t addr, uint32_t* r) {
    asm volatile("ldmatrix.sync.aligned.m8n8.x4.trans.shared.b16 {%0,%1,%2,%3}, [%4];"
                 : "=r"(r[0]), "=r"(r[1]), "=r"(r[2]), "=r"(r[3]) : "r"(addr));
}
__device__ __forceinline__ void mma_fp16(float* c, const uint32_t* a, uint32_t b0, uint32_t b1) {
    asm volatile(
        "mma.sync.aligned.m16n8k16.row.col.f32.f16.f16.f32 "
        "{%0,%1,%2,%3}, {%4,%5,%6,%7}, {%8,%9}, {%0,%1,%2,%3};"
        : "+f"(c[0]), "+f"(c[1]), "+f"(c[2]), "+f"(c[3])
        : "r"(a[0]), "r"(a[1]), "r"(a[2]), "r"(a[3]), "r"(b0), "r"(b1));
}

// ---------------- K_pre_w: conv_w + codewords -> fp16; also zero scratch ----------------
__global__ void kpw(const float* __restrict__ w, const float* __restrict__ cw) {
    int i = blockIdx.x * blockDim.x + threadIdx.x;
    if (i < CC * CC) g_wh[i] = __float2half(w[i]);
    if (i < KK * CC) g_cwh[i] = __float2half(cw[i]);
    if (i < BB * KK * CC) g_enc[i] = 0.f;
    if (i < BB * HWN)     g_x2[i] = 0.f;
    if (i < BB * KK)      g_asum[i] = 0.f;
}

// ---------------- K_pre_x: transpose x (b,c,n)->(b,n,c) + fp16, half2 writes ----------------
__global__ void __launch_bounds__(256) kpx(const float* __restrict__ x) {
    __shared__ float t[64][33];
    int tid = threadIdx.x;
    int lane = tid & 31, w = tid >> 5;
    int b = blockIdx.z;
    int cb = blockIdx.y * 64;
    int nb = blockIdx.x * 32;
    const float* xb = x + (size_t)b * CC * HWN;
#pragma unroll
    for (int it = 0; it < 8; it++) {
        int r = w + it * 8;
        t[r][lane] = xb[(size_t)(cb + r) * HWN + nb + lane];
    }
    __syncthreads();
#pragma unroll
    for (int it = 0; it < 4; it++) {
        int idx = tid + it * 256;
        int n = idx >> 5;
        int cp = idx & 31;
        __half2 h = __floats2half2_rn(t[2 * cp][n], t[2 * cp + 1][n]);
        *(__half2*)&g_xh[((size_t)b * HWN + nb + n) * CC + cb + 2 * cp] = h;
    }
}

// ---------------- K1: HMMA fp16 GEMM + BN2 + relu -> fp16 feats, x2 ----------------
#define K1_STAGE  16384
#define K1_BNS    1024
#define SMEM_K1M  (K1_BNS + 3 * K1_STAGE)

__global__ void __launch_bounds__(256, 2) k1_mma(
    const float* __restrict__ g2, const float* __restrict__ b2,
    const float* __restrict__ m2, const float* __restrict__ v2)
{
    extern __shared__ char sm[];
    uint32_t sb = smem_u32(sm);
    int tid = threadIdx.x;
    int lane = tid & 31;
    int wid = tid >> 5;
    int warp_m = wid >> 1;
    int warp_n = wid & 1;
    int n0 = blockIdx.x * 128;
    int m0 = blockIdx.y * 128;

    float* bns = (float*)sm;
    float* bnh = (float*)(sm + 512);
    if (tid < 128) {
        int o = n0 + tid;
        float s = rsqrtf(v2[o] + EPSF) * g2[o];
        bns[tid] = s;
        bnh[tid] = b2[o] - m2[o] * s;
    }

    const __half* xh = g_xh + (size_t)m0 * CC;
    const __half* wh = g_wh + (size_t)n0 * CC;

    auto issue_stage = [&](int s) {
        uint32_t base = sb + K1_BNS + (s % 3) * K1_STAGE;
#pragma unroll
        for (int it = 0; it < 2; it++) {
            int idx = tid + it * 256;
            int row = idx >> 2, seg = idx & 3;
            uint32_t d = swz64((uint32_t)(row * 64 + seg * 16));
            size_t go = (size_t)row * CC + s * 32 + seg * 8;
            cpasync16(base + d,        xh + go);
            cpasync16(base + 8192 + d, wh + go);
        }
    };

    issue_stage(0); CP_COMMIT();
    issue_stage(1); CP_COMMIT();
    issue_stage(2); CP_COMMIT();

    float c[2][8][4];
#pragma unroll
    for (int i = 0; i < 2; i++)
#pragma unroll
        for (int j = 0; j < 8; j++)
#pragma unroll
            for (int l = 0; l < 4; l++) c[i][j][l] = 0.f;

    for (int s = 0; s < 16; s++) {
        CP_WAIT2();
        __syncthreads();
        uint32_t tb = sb + K1_BNS + (s % 3) * K1_STAGE;
#pragma unroll
        for (int kk = 0; kk < 2; kk++) {
            uint32_t bfr[4][4], a2[2][4];
#pragma unroll
            for (int ng = 0; ng < 4; ng++) {
                uint32_t off = swz64((uint32_t)((warp_n * 64 + ng * 16 + (lane & 15)) * 64
                                               + kk * 32 + (lane >> 4) * 16));
                ldsm4(tb + 8192 + off, bfr[ng]);
            }
#pragma unroll
            for (int mt = 0; mt < 2; mt++) {
                uint32_t off = swz64((uint32_t)((warp_m * 32 + mt * 16 + (lane & 15)) * 64
                                               + kk * 32 + (lane >> 4) * 16));
                ldsm4(tb + off, a2[mt]);
            }
#pragma unroll
            for (int mt = 0; mt < 2; mt++)
#pragma unroll
                for (int ng = 0; ng < 4; ng++)
#pragma unroll
                    for (int h = 0; h < 2; h++)
                        mma_fp16(c[mt][ng * 2 + h], a2[mt], bfr[ng][h], bfr[ng][h + 2]);
        }
        __syncthreads();
        if (s + 3 < 16) issue_stage(s + 3);
        CP_COMMIT();
    }

#pragma unroll
    for (int mt = 0; mt < 2; mt++) {
        int r0 = m0 + warp_m * 32 + mt * 16 + (lane >> 2);
        float q0 = 0.f, q1 = 0.f;
#pragma unroll
        for (int j = 0; j < 8; j++) {
            int cl = warp_n * 64 + j * 8 + (lane & 3) * 2;
            float s0 = bns[cl], h0 = bnh[cl];
            float s1 = bns[cl + 1], h1 = bnh[cl + 1];
            float v00 = fmaxf(fmaf(c[mt][j][0], s0, h0), 0.f);
            float v01 = fmaxf(fmaf(c[mt][j][1], s1, h1), 0.f);
            float v10 = fmaxf(fmaf(c[mt][j][2], s0, h0), 0.f);
            float v11 = fmaxf(fmaf(c[mt][j][3], s1, h1), 0.f);
            __half2 p0 = __floats2half2_rn(v00, v01);
            __half2 p1 = __floats2half2_rn(v10, v11);
            *(__half2*)&g_fh[(size_t)r0 * CC + n0 + cl] = p0;
            *(__half2*)&g_fh[(size_t)(r0 + 8) * CC + n0 + cl] = p1;
            float2 f0 = __half22float2(p0);
            float2 f1 = __half22float2(p1);
            q0 = fmaf(f0.x, f0.x, fmaf(f0.y, f0.y, q0));
            q1 = fmaf(f1.x, f1.x, fmaf(f1.y, f1.y, q1));
        }
        q0 += __shfl_xor_sync(0xffffffffu, q0, 1);
        q0 += __shfl_xor_sync(0xffffffffu, q0, 2);
        q1 += __shfl_xor_sync(0xffffffffu, q1, 1);
        q1 += __shfl_xor_sync(0xffffffffu, q1, 2);
        if ((lane & 3) == 0) {
            atomicAdd(&g_x2[r0], q0);
            atomicAdd(&g_x2[r0 + 8], q1);
        }
    }
}

// ---------------- K2: HMMA xc + fused softmax -> assign^T fp16, asum ----------------
// 64-c chunks: stage = feats 128x128B (16KB) + cw 32x128B (4KB) = 20KB, 3 stages.
// Mainloop ordering: wait / barrier / COMPUTE / barrier / issue (no buffer aliasing).
#define K2_STG 20480
__global__ void __launch_bounds__(256) k2_assign(
    const float* __restrict__ cw, const float* __restrict__ scale)
{
    __shared__ __align__(16) char st[3 * K2_STG];
    __shared__ __half asn[32][136];
    __shared__ float c2s[32], x2s[128], scs[32];
    uint32_t sb = smem_u32(st);
    int tid = threadIdx.x;
    int lane = tid & 31, w = tid >> 5;
    int m0 = blockIdx.x * 128;
    int b = m0 >> 12;
    int n0 = m0 & (HWN - 1);

    auto issue = [&](int ch) {
        uint32_t base = sb + (ch % 3) * K2_STG;
#pragma unroll
        for (int it = 0; it < 4; it++) {
            int idx = tid + it * 256;
            int row = idx >> 3, seg = idx & 7;
            cpasync16(base + swz128((uint32_t)(row * 128 + seg * 16)),
                      g_fh + (size_t)(m0 + row) * CC + ch * 64 + seg * 8);
        }
        {
            int row = tid >> 3, seg = tid & 7;
            cpasync16(base + 16384 + swz128((uint32_t)(row * 128 + seg * 16)),
                      g_cwh + (size_t)row * CC + ch * 64 + seg * 8);
        }
    };
    issue(0); CP_COMMIT(); issue(1); CP_COMMIT(); issue(2); CP_COMMIT();

    {
        int k = tid >> 3, seg = tid & 7;
        const float* p = cw + k * CC + seg * 64;
        float s = 0.f;
#pragma unroll 16
        for (int i = 0; i < 64; i++) { float v = p[i]; s = fmaf(v, v, s); }
#pragma unroll
        for (int off = 4; off >= 1; off >>= 1)
            s += __shfl_xor_sync(0xffffffffu, s, off);
        if (seg == 0) c2s[k] = s;
        if (tid < 32) scs[tid] = scale[tid];
        if (tid < 128) x2s[tid] = g_x2[m0 + tid];
    }

    float c[4][4];
#pragma unroll
    for (int i = 0; i < 4; i++)
#pragma unroll
        for (int j = 0; j < 4; j++) c[i][j] = 0.f;

    for (int ch = 0; ch < 8; ch++) {
        CP_WAIT2();
        __syncthreads();
        uint32_t tb = sb + (ch % 3) * K2_STG;
#pragma unroll
        for (int kk = 0; kk < 4; kk++) {
            uint32_t a[4], b0[4], b1[4];
            ldsm4(tb + swz128((uint32_t)((w * 16 + (lane & 15)) * 128 + kk * 32 + (lane >> 4) * 16)), a);
            ldsm4(tb + 16384 + swz128((uint32_t)((lane & 15) * 128 + kk * 32 + (lane >> 4) * 16)), b0);
            ldsm4(tb + 16384 + swz128((uint32_t)((16 + (lane & 15)) * 128 + kk * 32 + (lane >> 4) * 16)), b1);
#pragma unroll
            for (int h = 0; h < 2; h++) {
                mma_fp16(c[h],     a, b0[h], b0[h + 2]);
                mma_fp16(c[2 + h], a, b1[h], b1[h + 2]);
            }
        }
        __syncthreads();
        if (ch + 3 < 8) issue(ch + 3);
        CP_COMMIT();
    }
    __syncthreads();

    int q = lane & 3, r = lane >> 2;
#pragma unroll
    for (int half = 0; half < 2; half++) {
        int px = w * 16 + r + half * 8;
        float x2v = x2s[px];
        float d[8];
        float mx = -1e30f;
#pragma unroll
        for (int g = 0; g < 4; g++)
#pragma unroll
            for (int e = 0; e < 2; e++) {
                int k = g * 8 + q * 2 + e;
                float dd = scs[k] * (x2v - 2.f * c[g][half * 2 + e] + c2s[k]);
                d[g * 2 + e] = dd;
                mx = fmaxf(mx, dd);
            }
        mx = fmaxf(mx, __shfl_xor_sync(0xffffffffu, mx, 1));
        mx = fmaxf(mx, __shfl_xor_sync(0xffffffffu, mx, 2));
        float se = 0.f;
#pragma unroll
        for (int i = 0; i < 8; i++) { d[i] = __expf(d[i] - mx); se += d[i]; }
        se += __shfl_xor_sync(0xffffffffu, se, 1);
        se += __shfl_xor_sync(0xffffffffu, se, 2);
        float inv = 1.f / se;
#pragma unroll
        for (int g = 0; g < 4; g++)
#pragma unroll
            for (int e = 0; e < 2; e++)
                asn[g * 8 + q * 2 + e][px] = __float2half(d[g * 2 + e] * inv);
    }
    __syncthreads();

    {
        int k = tid >> 3, seg = tid & 7;
        float s = 0.f;
#pragma unroll
        for (int j = 0; j < 16; j++)
            s += __half2float(asn[k][seg * 16 + j]);
        s += __shfl_xor_sync(0xffffffffu, s, 1);
        s += __shfl_xor_sync(0xffffffffu, s, 2);
        s += __shfl_xor_sync(0xffffffffu, s, 4);
        if (seg == 0) atomicAdd(&g_asum[b * KK + k], s);
    }
#pragma unroll
    for (int it = 0; it < 2; it++) {
        int idx = tid + it * 256;
        int row = idx >> 4, cs = idx & 15;
        uint4 v = *(const uint4*)&asn[row][cs * 8];
        *(uint4*)&g_asnT[((size_t)b * KK + row) * HWN + n0 + cs * 8] = v;
    }
}

// ---------------- K3: HMMA encoded^T[c][k] = feats^T @ assign^T, atomic acc ----------------
// 64-n chunks: stage = feats 64x256B (16KB) + asnT 32x128B (4KB) = 20KB, 3 stages.
#define K3_STG 20480
__global__ void __launch_bounds__(256) k3_agg()
{
    __shared__ __align__(16) char st[3 * K3_STG];
    uint32_t sb = smem_u32(st);
    int tid = threadIdx.x, lane = tid & 31, w = tid >> 5;
    int b = blockIdx.z;
    int c0 = blockIdx.x * 128;
    int n0 = blockIdx.y * (HWN / NSPLIT);
    size_t m0 = (size_t)b * HWN + n0;

    auto issue = [&](int ch) {
        uint32_t base = sb + (ch % 3) * K3_STG;
#pragma unroll
        for (int it = 0; it < 4; it++) {
            int idx = tid + it * 256;
            int row = idx >> 4, seg = idx & 15;
            cpasync16(base + swz256((uint32_t)(row * 256 + seg * 16)),
                      g_fh + (m0 + ch * 64 + row) * CC + c0 + seg * 8);
        }
        {
            int row = tid >> 3, seg = tid & 7;
            cpasync16(base + 16384 + swz128((uint32_t)(row * 128 + seg * 16)),
                      g_asnT + ((size_t)b * KK + row) * HWN + n0 + ch * 64 + seg * 8);
        }
    };
    issue(0); CP_COMMIT(); issue(1); CP_COMMIT(); issue(2); CP_COMMIT();

    float c[4][4];
#pragma unroll
    for (int i = 0; i < 4; i++)
#pragma unroll
        for (int j = 0; j < 4; j++) c[i][j] = 0.f;

    for (int ch = 0; ch < 8; ch++) {
        CP_WAIT2();
        __syncthreads();
        uint32_t tb = sb + (ch % 3) * K3_STG;
#pragma unroll
        for (int kk = 0; kk < 4; kk++) {
            uint32_t a[4], b0[4], b1[4];
            int arow = kk * 16 + ((lane >> 4) << 3) + (lane & 7);
            int acol = w * 16 + (((lane >> 3) & 1) << 3);
            ldsm4t(tb + swz256((uint32_t)(arow * 256 + acol * 2)), a);
            ldsm4(tb + 16384 + swz128((uint32_t)((lane & 15) * 128 + kk * 32 + (lane >> 4) * 16)), b0);
            ldsm4(tb + 16384 + swz128((uint32_t)((16 + (lane & 15)) * 128 + kk * 32 + (lane >> 4) * 16)), b1);
#pragma unroll
            for (int h = 0; h < 2; h++) {
                mma_fp16(c[h],     a, b0[h], b0[h + 2]);
                mma_fp16(c[2 + h], a, b1[h], b1[h + 2]);
            }
        }
        __syncthreads();
        if (ch + 3 < 8) issue(ch + 3);
        CP_COMMIT();
    }

    int q = lane & 3, r = lane >> 2;
#pragma unroll
    for (int half = 0; half < 2; half++) {
        int cr = c0 + w * 16 + r + half * 8;
#pragma unroll
        for (int g = 0; g < 4; g++)
#pragma unroll
            for (int e = 0; e < 2; e++) {
                int k = g * 8 + q * 2 + e;
                atomicAdd(&g_enc[((size_t)b * KK + k) * CC + cr], c[g][half * 2 + e]);
            }
    }
}

// ---------------- K45: ef (BN1+relu+mean) then gamma = sigmoid(fc) ----------------
__global__ void __launch_bounds__(512) k45(
    const float* __restrict__ cw, const float* __restrict__ g1,
    const float* __restrict__ b1, const float* __restrict__ m1,
    const float* __restrict__ v1,
    const float* __restrict__ fcw, const float* __restrict__ fcb,
    float* __restrict__ ef_out)
{
    __shared__ float efs[CC];
    int b = blockIdx.x;
    int o = threadIdx.x;
    float s = 0.f;
#pragma unroll
    for (int k = 0; k < KK; k++) {
        float e = g_enc[((size_t)b * KK + k) * CC + o] - g_asum[b * KK + k] * cw[(size_t)k * CC + o];
        float sc = rsqrtf(v1[k] + EPSF) * g1[k];
        e = fmaf(e - m1[k], sc, b1[k]);
        e = fmaxf(e, 0.f);
        s += e;
    }
    float ef = s * (1.f / KK);
    efs[o] = ef;
    ef_out[b * CC + o] = ef;
    __syncthreads();

    const float* wr = fcw + (size_t)o * CC;
    float g = fcb[o];
#pragma unroll 8
    for (int c = 0; c < CC; c += 4) {
        float4 w4 = *(const float4*)&wr[c];
        g = fmaf(w4.x, efs[c + 0], g);
        g = fmaf(w4.y, efs[c + 1], g);
        g = fmaf(w4.z, efs[c + 2], g);
        g = fmaf(w4.w, efs[c + 3], g);
    }
    g_gamma[b * CC + o] = 1.f / (1.f + __expf(-g));
}

// ---------------- K6: output = relu(x*(1+gamma)) reading fp16 x^T (smem transpose) ----------------
__global__ void __launch_bounds__(256) k6_out(float* __restrict__ out)
{
    __shared__ __align__(16) __half t[64 * 64];
    int tid = threadIdx.x;
    int b  = blockIdx.z;
    int cb = blockIdx.y * 64;
    int nb = blockIdx.x * 64;

#pragma unroll
    for (int it = 0; it < 2; it++) {
        int idx = tid + it * 256;
        int n = idx >> 3, seg = idx & 7;
        int phys = seg ^ ((n >> 2) & 7);
        uint4 v = *(const uint4*)&g_xh[((size_t)b * HWN + nb + n) * CC + cb + seg * 8];
        *(uint4*)&t[n * 64 + phys * 8] = v;
    }
    __syncthreads();

#pragma unroll
    for (int it = 0; it < 4; it++) {
        int idx = tid + it * 256;
        int c = idx >> 4;
        int nb4 = (idx & 15) * 4;
        float g = 1.f + g_gamma[b * CC + cb + c];
        int seg = c >> 3, coff = c & 7;
        float4 o;
        float* op = &o.x;
#pragma unroll
        for (int dn = 0; dn < 4; dn++) {
            int n = nb4 + dn;
            int phys = seg ^ ((n >> 2) & 7);
            float v = __half2float(t[n * 64 + phys * 8 + coff]);
            op[dn] = fmaxf(v * g, 0.f);
        }
        *(float4*)&out[((size_t)b * CC + cb + c) * HWN + nb + nb4] = o;
    }
}

// ---------------- launch ----------------
extern "C" void kernel_launch(void* const* d_in, const int* in_sizes, int n_in,
                              void* d_out, int out_size)
{
    const float* x      = (const float*)d_in[0];
    const float* conv_w = (const float*)d_in[1];
    const float* bn2_g  = (const float*)d_in[2];
    const float* bn2_b  = (const float*)d_in[3];
    const float* bn2_m  = (const float*)d_in[4];
    const float* bn2_v  = (const float*)d_in[5];
    const float* cw     = (const float*)d_in[6];
    const float* scale  = (const float*)d_in[7];
    const float* bn1_g  = (const float*)d_in[8];
    const float* bn1_b  = (const float*)d_in[9];
    const float* bn1_m  = (const float*)d_in[10];
    const float* bn1_v  = (const float*)d_in[11];
    const float* fc_w   = (const float*)d_in[12];
    const float* fc_b   = (const float*)d_in[13];
    float* out = (float*)d_out;   // [0:8192) encoding_feat, [8192:) output

    static bool attr_set = false;
    if (!attr_set) {
        cudaFuncSetAttribute(k1_mma, cudaFuncAttributeMaxDynamicSharedMemorySize, SMEM_K1M);
        attr_set = true;
    }

    kpw<<<(CC * CC + 255) / 256, 256>>>(conv_w, cw);

    dim3 gpx(HWN / 32, CC / 64, BB);
    kpx<<<gpx, 256>>>(x);

    dim3 g1(CC / 128, BB * HWN / 128);   // (4, 512)
    k1_mma<<<g1, 256, SMEM_K1M>>>(bn2_g, bn2_b, bn2_m, bn2_v);

    k2_assign<<<BB * HWN / 128, 256>>>(cw, scale);

    dim3 g3(CC / 128, NSPLIT, BB);
    k3_agg<<<g3, 256>>>();

    k45<<<BB, 512>>>(cw, bn1_g, bn1_b, bn1_m, bn1_v, fc_w, fc_b, out);

    dim3 g6(HWN / 64, CC / 64, BB);
    k6_out<<<g6, 256>>>(out + BB * CC);
}

// round 16
// speedup vs baseline: 2.6009x; 1.0320x over previous
#include <cuda_runtime.h>
#include <cuda_bf16.h>
#include <cuda_fp16.h>
#include <cstdint>
#include <math.h>

#define BB 16
#define CC 512
#define KK 32
#define HWN 4096
#define EPSF 1e-5f
#define NSPLIT 8

// ---------------- scratch (static device globals: no allocation) ----------------
__device__ __half g_fh[(size_t)BB * HWN * CC];     // feats fp16 (b,n,c) 67 MB
__device__ __half g_asnT[(size_t)BB * KK * HWN];   // assign^T fp16 (b,k,n) 4 MB
__device__ float g_xc[(size_t)BB * HWN * KK];      // xc partial sums (b,n,k) 8 MB
__device__ float g_x2[BB * HWN];                   // per-pixel ||feats||^2
__device__ float g_c2[KK];                         // ||codeword||^2
__device__ float g_enc[BB * KK * CC];              // partial encoded
__device__ float g_asum[BB * KK];                  // sum_n assign
__device__ float g_gamma[BB * CC];
__device__ __half g_xh[(size_t)BB * HWN * CC];     // x^T (b,n,c) fp16  67 MB
__device__ __half g_wh[CC * CC];                   // conv_w fp16
__device__ __half g_cwh[KK * CC];                  // codewords fp16

// ---------------- helpers ----------------
__device__ __forceinline__ uint32_t smem_u32(const void* p) {
    uint32_t a;
    asm("{ .reg .u64 t; cvta.to.shared.u64 t, %1; cvt.u32.u64 %0, t; }" : "=r"(a) : "l"(p));
    return a;
}
__device__ __forceinline__ uint32_t swz64(uint32_t o)  { return o ^ ((o >> 3) & 0x30); }
__device__ __forceinline__ uint32_t swz128(uint32_t o) { return o ^ ((o >> 3) & 0x70); }
__device__ __forceinline__ uint32_t swz256(uint32_t o) { return o ^ ((o >> 4) & 0x70); }

__device__ __forceinline__ void cpasync16(uint32_t dst, const void* src) {
    asm volatile("cp.async.cg.shared.global [%0], [%1], 16;"
                 :: "r"(dst), "l"(__cvta_generic_to_global(src)) : "memory");
}
#define CP_COMMIT() asm volatile("cp.async.commit_group;" ::: "memory")
#define CP_WAIT2()  asm volatile("cp.async.wait_group 2;" ::: "memory")
#define CP_WAIT0()  asm volatile("cp.async.wait_group 0;" ::: "memory")

__device__ __forceinline__ void ldsm4(uint32_t addr, uint32_t* r) {
    asm volatile("ldmatrix.sync.aligned.m8n8.x4.shared.b16 {%0,%1,%2,%3}, [%4];"
                 : "=r"(r[0]), "=r"(r[1]), "=r"(r[2]), "=r"(r[3]) : "r"(addr));
}
__device__ __forceinline__ void ldsm4t(uint32_t addr, uint32_t* r) {
    asm volatile("ldmatrix.sync.aligned.m8n8.x4.trans.shared.b16 {%0,%1,%2,%3}, [%4];"
                 : "=r"(r[0]), "=r"(r[1]), "=r"(r[2]), "=r"(r[3]) : "r"(addr));
}
__device__ __forceinline__ void mma_fp16(float* c, const uint32_t* a, uint32_t b0, uint32_t b1) {
    asm volatile(
        "mma.sync.aligned.m16n8k16.row.col.f32.f16.f16.f32 "
        "{%0,%1,%2,%3}, {%4,%5,%6,%7}, {%8,%9}, {%0,%1,%2,%3};"
        : "+f"(c[0]), "+f"(c[1]), "+f"(c[2]), "+f"(c[3])
        : "r"(a[0]), "r"(a[1]), "r"(a[2]), "r"(a[3]), "r"(b0), "r"(b1));
}

// ---------------- K_pre_w: params -> fp16; zero scratch; c2 ----------------
__global__ void kpw(const float* __restrict__ w, const float* __restrict__ cw) {
    int i = blockIdx.x * blockDim.x + threadIdx.x;
    if (i < CC * CC) g_wh[i] = __float2half(w[i]);
    if (i < KK * CC) g_cwh[i] = __float2half(cw[i]);
    if (i < BB * KK * CC) g_enc[i] = 0.f;
    if (i < BB * HWN)     g_x2[i] = 0.f;
    if (i < BB * KK)      g_asum[i] = 0.f;
    {   // zero g_xc: 2M floats over 262144 threads -> 8 each
        size_t base = (size_t)i * 8;
        float4 z = make_float4(0.f, 0.f, 0.f, 0.f);
        *(float4*)&g_xc[base]     = z;
        *(float4*)&g_xc[base + 4] = z;
    }
    if (i < KK) {
        const float* p = cw + (size_t)i * CC;
        float s = 0.f;
        for (int c = 0; c < CC; c++) { float v = p[c]; s = fmaf(v, v, s); }
        g_c2[i] = s;
    }
}

// ---------------- K_pre_x: transpose x (b,c,n)->(b,n,c) + fp16, half2 writes ----------------
__global__ void __launch_bounds__(256) kpx(const float* __restrict__ x) {
    __shared__ float t[64][33];
    int tid = threadIdx.x;
    int lane = tid & 31, w = tid >> 5;
    int b = blockIdx.z;
    int cb = blockIdx.y * 64;
    int nb = blockIdx.x * 32;
    const float* xb = x + (size_t)b * CC * HWN;
#pragma unroll
    for (int it = 0; it < 8; it++) {
        int r = w + it * 8;
        t[r][lane] = xb[(size_t)(cb + r) * HWN + nb + lane];
    }
    __syncthreads();
#pragma unroll
    for (int it = 0; it < 4; it++) {
        int idx = tid + it * 256;
        int n = idx >> 5;
        int cp = idx & 31;
        __half2 h = __floats2half2_rn(t[2 * cp][n], t[2 * cp + 1][n]);
        *(__half2*)&g_xh[((size_t)b * HWN + nb + n) * CC + cb + 2 * cp] = h;
    }
}

// ---------------- K1: HMMA GEMM + BN2 + relu -> fp16 feats, x2, PARTIAL XC ----------------
#define K1_STAGE  16384
#define K1_BNS    1024
#define OFF_FT    1024                  // feats tile staging (32 KB, reuses stages 0,1)
#define OFF_CW    (1024 + 32768)        // cw slice staging (8 KB, reuses stage 2)
#define SMEM_K1M  (K1_BNS + 3 * K1_STAGE)

__global__ void __launch_bounds__(256, 2) k1_mma(
    const float* __restrict__ g2, const float* __restrict__ b2,
    const float* __restrict__ m2, const float* __restrict__ v2)
{
    extern __shared__ char sm[];
    uint32_t sb = smem_u32(sm);
    int tid = threadIdx.x;
    int lane = tid & 31;
    int wid = tid >> 5;
    int warp_m = wid >> 1;
    int warp_n = wid & 1;
    int n0 = blockIdx.x * 128;
    int m0 = blockIdx.y * 128;

    float* bns = (float*)sm;
    float* bnh = (float*)(sm + 512);
    if (tid < 128) {
        int o = n0 + tid;
        float s = rsqrtf(v2[o] + EPSF) * g2[o];
        bns[tid] = s;
        bnh[tid] = b2[o] - m2[o] * s;
    }

    const __half* xh = g_xh + (size_t)m0 * CC;
    const __half* wh = g_wh + (size_t)n0 * CC;

    auto issue_stage = [&](int s) {
        uint32_t base = sb + K1_BNS + (s % 3) * K1_STAGE;
#pragma unroll
        for (int it = 0; it < 2; it++) {
            int idx = tid + it * 256;
            int row = idx >> 2, seg = idx & 3;
            uint32_t d = swz64((uint32_t)(row * 64 + seg * 16));
            size_t go = (size_t)row * CC + s * 32 + seg * 8;
            cpasync16(base + d,        xh + go);
            cpasync16(base + 8192 + d, wh + go);
        }
    };

    issue_stage(0); CP_COMMIT();
    issue_stage(1); CP_COMMIT();
    issue_stage(2); CP_COMMIT();

    float c[2][8][4];
#pragma unroll
    for (int i = 0; i < 2; i++)
#pragma unroll
        for (int j = 0; j < 8; j++)
#pragma unroll
            for (int l = 0; l < 4; l++) c[i][j][l] = 0.f;

    for (int s = 0; s < 16; s++) {
        CP_WAIT2();
        __syncthreads();
        uint32_t tb = sb + K1_BNS + (s % 3) * K1_STAGE;
#pragma unroll
        for (int kk = 0; kk < 2; kk++) {
            uint32_t bfr[4][4], a2[2][4];
#pragma unroll
            for (int ng = 0; ng < 4; ng++) {
                uint32_t off = swz64((uint32_t)((warp_n * 64 + ng * 16 + (lane & 15)) * 64
                                               + kk * 32 + (lane >> 4) * 16));
                ldsm4(tb + 8192 + off, bfr[ng]);
            }
#pragma unroll
            for (int mt = 0; mt < 2; mt++) {
                uint32_t off = swz64((uint32_t)((warp_m * 32 + mt * 16 + (lane & 15)) * 64
                                               + kk * 32 + (lane >> 4) * 16));
                ldsm4(tb + off, a2[mt]);
            }
#pragma unroll
            for (int mt = 0; mt < 2; mt++)
#pragma unroll
                for (int ng = 0; ng < 4; ng++)
#pragma unroll
                    for (int h = 0; h < 2; h++)
                        mma_fp16(c[mt][ng * 2 + h], a2[mt], bfr[ng][h], bfr[ng][h + 2]);
        }
        __syncthreads();
        if (s + 3 < 16) issue_stage(s + 3);
        CP_COMMIT();
    }

    // load cw slice [32k x 128c] for this CTA's channel range (stage 2 area, now free)
#pragma unroll
    for (int it = 0; it < 2; it++) {
        int idx = tid + it * 256;
        int row = idx >> 4, seg = idx & 15;
        cpasync16(sb + OFF_CW + swz256((uint32_t)(row * 256 + seg * 16)),
                  g_cwh + (size_t)row * CC + n0 + seg * 8);
    }
    CP_COMMIT();

    // epilogue: BN2 + relu -> fp16 feats (gmem + smem tile), x2 from ROUNDED values
#pragma unroll
    for (int mt = 0; mt < 2; mt++) {
        int rl0 = warp_m * 32 + mt * 16 + (lane >> 2);   // local row 0..127
        int r0 = m0 + rl0;
        float q0 = 0.f, q1 = 0.f;
#pragma unroll
        for (int j = 0; j < 8; j++) {
            int cl = warp_n * 64 + j * 8 + (lane & 3) * 2;
            float s0 = bns[cl], h0 = bnh[cl];
            float s1 = bns[cl + 1], h1 = bnh[cl + 1];
            float v00 = fmaxf(fmaf(c[mt][j][0], s0, h0), 0.f);
            float v01 = fmaxf(fmaf(c[mt][j][1], s1, h1), 0.f);
            float v10 = fmaxf(fmaf(c[mt][j][2], s0, h0), 0.f);
            float v11 = fmaxf(fmaf(c[mt][j][3], s1, h1), 0.f);
            __half2 p0 = __floats2half2_rn(v00, v01);
            __half2 p1 = __floats2half2_rn(v10, v11);
            *(__half2*)&g_fh[(size_t)r0 * CC + n0 + cl] = p0;
            *(__half2*)&g_fh[(size_t)(r0 + 8) * CC + n0 + cl] = p1;
            *(__half2*)(sm + OFF_FT + swz128((uint32_t)(rl0 * 128 + cl * 2))) = p0;
            *(__half2*)(sm + OFF_FT + swz128((uint32_t)((rl0 + 8) * 128 + cl * 2))) = p1;
            float2 f0 = __half22float2(p0);
            float2 f1 = __half22float2(p1);
            q0 = fmaf(f0.x, f0.x, fmaf(f0.y, f0.y, q0));
            q1 = fmaf(f1.x, f1.x, fmaf(f1.y, f1.y, q1));
        }
        q0 += __shfl_xor_sync(0xffffffffu, q0, 1);
        q0 += __shfl_xor_sync(0xffffffffu, q0, 2);
        q1 += __shfl_xor_sync(0xffffffffu, q1, 1);
        q1 += __shfl_xor_sync(0xffffffffu, q1, 2);
        if ((lane & 3) == 0) {
            atomicAdd(&g_x2[r0], q0);
            atomicAdd(&g_x2[r0 + 8], q1);
        }
    }

    CP_WAIT0();
    __syncthreads();

    // fused partial xc: [128px x 32k] += feats_tile[128px x 128c] @ cw_slice^T
    float cc2[4][4];
#pragma unroll
    for (int i = 0; i < 4; i++)
#pragma unroll
        for (int j = 0; j < 4; j++) cc2[i][j] = 0.f;

#pragma unroll
    for (int kk = 0; kk < 8; kk++) {
        uint32_t a[4], b0[4], b1[4];
        ldsm4(sb + OFF_FT + swz128((uint32_t)((wid * 16 + (lane & 15)) * 128
                                             + kk * 32 + (lane >> 4) * 16)), a);
        ldsm4(sb + OFF_CW + swz256((uint32_t)((lane & 15) * 256 + kk * 32 + (lane >> 4) * 16)), b0);
        ldsm4(sb + OFF_CW + swz256((uint32_t)((16 + (lane & 15)) * 256 + kk * 32 + (lane >> 4) * 16)), b1);
#pragma unroll
        for (int h = 0; h < 2; h++) {
            mma_fp16(cc2[h],     a, b0[h], b0[h + 2]);
            mma_fp16(cc2[2 + h], a, b1[h], b1[h + 2]);
        }
    }

    int q = lane & 3, r = lane >> 2;
#pragma unroll
    for (int half = 0; half < 2; half++) {
        int px = m0 + wid * 16 + r + half * 8;
        float* dst = &g_xc[(size_t)px * KK];
#pragma unroll
        for (int g = 0; g < 4; g++)
#pragma unroll
            for (int e = 0; e < 2; e++)
                atomicAdd(dst + g * 8 + q * 2 + e, cc2[g][half * 2 + e]);
    }
}

// ---------------- KSF: softmax over xc -> assign^T fp16, asum ----------------
__global__ void __launch_bounds__(128) ksf(const float* __restrict__ scale)
{
    __shared__ __half asn[32][136];
    __shared__ float scs[32], c2s[32];
    int tid = threadIdx.x;
    int m0 = blockIdx.x * 128;
    int b = m0 >> 12;
    int n0 = m0 & (HWN - 1);

    if (tid < 32) { scs[tid] = scale[tid]; c2s[tid] = g_c2[tid]; }
    __syncthreads();

    float xc[32];
#pragma unroll
    for (int i = 0; i < 8; i++)
        *(float4*)&xc[i * 4] = *(const float4*)&g_xc[((size_t)(m0 + tid)) * KK + i * 4];
    float x2v = g_x2[m0 + tid];

    float d[32], mx = -1e30f;
#pragma unroll
    for (int k = 0; k < 32; k++) {
        d[k] = scs[k] * (x2v - 2.f * xc[k] + c2s[k]);
        mx = fmaxf(mx, d[k]);
    }
    float se = 0.f;
#pragma unroll
    for (int k = 0; k < 32; k++) { d[k] = __expf(d[k] - mx); se += d[k]; }
    float inv = 1.f / se;
#pragma unroll
    for (int k = 0; k < 32; k++)
        asn[k][tid] = __float2half(d[k] * inv);
    __syncthreads();

    {   // asum: thread t -> k = t>>2, seg = t&3 sums 32 px
        int k = tid >> 2, seg = tid & 3;
        float s = 0.f;
#pragma unroll
        for (int j = 0; j < 32; j++)
            s += __half2float(asn[k][seg * 32 + j]);
        s += __shfl_xor_sync(0xffffffffu, s, 1);
        s += __shfl_xor_sync(0xffffffffu, s, 2);
        if (seg == 0) atomicAdd(&g_asum[b * KK + k], s);
    }
#pragma unroll
    for (int it = 0; it < 4; it++) {
        int idx = tid + it * 128;
        int row = idx >> 4, cs = idx & 15;
        uint4 v = *(const uint4*)&asn[row][cs * 8];
        *(uint4*)&g_asnT[((size_t)b * KK + row) * HWN + n0 + cs * 8] = v;
    }
}

// ---------------- K3: HMMA encoded^T[c][k] = feats^T @ assign^T, atomic acc ----------------
#define K3_STG 20480
__global__ void __launch_bounds__(256) k3_agg()
{
    __shared__ __align__(16) char st[3 * K3_STG];
    uint32_t sb = smem_u32(st);
    int tid = threadIdx.x, lane = tid & 31, w = tid >> 5;
    int b = blockIdx.z;
    int c0 = blockIdx.x * 128;
    int n0 = blockIdx.y * (HWN / NSPLIT);
    size_t m0 = (size_t)b * HWN + n0;

    auto issue = [&](int ch) {
        uint32_t base = sb + (ch % 3) * K3_STG;
#pragma unroll
        for (int it = 0; it < 4; it++) {
            int idx = tid + it * 256;
            int row = idx >> 4, seg = idx & 15;
            cpasync16(base + swz256((uint32_t)(row * 256 + seg * 16)),
                      g_fh + (m0 + ch * 64 + row) * CC + c0 + seg * 8);
        }
        {
            int row = tid >> 3, seg = tid & 7;
            cpasync16(base + 16384 + swz128((uint32_t)(row * 128 + seg * 16)),
                      g_asnT + ((size_t)b * KK + row) * HWN + n0 + ch * 64 + seg * 8);
        }
    };
    issue(0); CP_COMMIT(); issue(1); CP_COMMIT(); issue(2); CP_COMMIT();

    float c[4][4];
#pragma unroll
    for (int i = 0; i < 4; i++)
#pragma unroll
        for (int j = 0; j < 4; j++) c[i][j] = 0.f;

    for (int ch = 0; ch < 8; ch++) {
        CP_WAIT2();
        __syncthreads();
        uint32_t tb = sb + (ch % 3) * K3_STG;
#pragma unroll
        for (int kk = 0; kk < 4; kk++) {
            uint32_t a[4], b0[4], b1[4];
            int arow = kk * 16 + ((lane >> 4) << 3) + (lane & 7);
            int acol = w * 16 + (((lane >> 3) & 1) << 3);
            ldsm4t(tb + swz256((uint32_t)(arow * 256 + acol * 2)), a);
            ldsm4(tb + 16384 + swz128((uint32_t)((lane & 15) * 128 + kk * 32 + (lane >> 4) * 16)), b0);
            ldsm4(tb + 16384 + swz128((uint32_t)((16 + (lane & 15)) * 128 + kk * 32 + (lane >> 4) * 16)), b1);
#pragma unroll
            for (int h = 0; h < 2; h++) {
                mma_fp16(c[h],     a, b0[h], b0[h + 2]);
                mma_fp16(c[2 + h], a, b1[h], b1[h + 2]);
            }
        }
        __syncthreads();
        if (ch + 3 < 8) issue(ch + 3);
        CP_COMMIT();
    }

    int q = lane & 3, r = lane >> 2;
#pragma unroll
    for (int half = 0; half < 2; half++) {
        int cr = c0 + w * 16 + r + half * 8;
#pragma unroll
        for (int g = 0; g < 4; g++)
#pragma unroll
            for (int e = 0; e < 2; e++) {
                int k = g * 8 + q * 2 + e;
                atomicAdd(&g_enc[((size_t)b * KK + k) * CC + cr], c[g][half * 2 + e]);
            }
    }
}

// ---------------- K45: ef (BN1+relu+mean) then gamma = sigmoid(fc) ----------------
__global__ void __launch_bounds__(512) k45(
    const float* __restrict__ cw, const float* __restrict__ g1,
    const float* __restrict__ b1, const float* __restrict__ m1,
    const float* __restrict__ v1,
    const float* __restrict__ fcw, const float* __restrict__ fcb,
    float* __restrict__ ef_out)
{
    __shared__ float efs[CC];
    int b = blockIdx.x;
    int o = threadIdx.x;
    float s = 0.f;
#pragma unroll
    for (int k = 0; k < KK; k++) {
        float e = g_enc[((size_t)b * KK + k) * CC + o] - g_asum[b * KK + k] * cw[(size_t)k * CC + o];
        float sc = rsqrtf(v1[k] + EPSF) * g1[k];
        e = fmaf(e - m1[k], sc, b1[k]);
        e = fmaxf(e, 0.f);
        s += e;
    }
    float ef = s * (1.f / KK);
    efs[o] = ef;
    ef_out[b * CC + o] = ef;
    __syncthreads();

    const float* wr = fcw + (size_t)o * CC;
    float g = fcb[o];
#pragma unroll 8
    for (int c = 0; c < CC; c += 4) {
        float4 w4 = *(const float4*)&wr[c];
        g = fmaf(w4.x, efs[c + 0], g);
        g = fmaf(w4.y, efs[c + 1], g);
        g = fmaf(w4.z, efs[c + 2], g);
        g = fmaf(w4.w, efs[c + 3], g);
    }
    g_gamma[b * CC + o] = 1.f / (1.f + __expf(-g));
}

// ---------------- K6: output = relu(x*(1+gamma)) reading fp16 x^T (smem transpose) ----------------
__global__ void __launch_bounds__(256) k6_out(float* __restrict__ out)
{
    __shared__ __align__(16) __half t[64 * 64];
    int tid = threadIdx.x;
    int b  = blockIdx.z;
    int cb = blockIdx.y * 64;
    int nb = blockIdx.x * 64;

#pragma unroll
    for (int it = 0; it < 2; it++) {
        int idx = tid + it * 256;
        int n = idx >> 3, seg = idx & 7;
        int phys = seg ^ ((n >> 2) & 7);
        uint4 v = *(const uint4*)&g_xh[((size_t)b * HWN + nb + n) * CC + cb + seg * 8];
        *(uint4*)&t[n * 64 + phys * 8] = v;
    }
    __syncthreads();

#pragma unroll
    for (int it = 0; it < 4; it++) {
        int idx = tid + it * 256;
        int c = idx >> 4;
        int nb4 = (idx & 15) * 4;
        float g = 1.f + g_gamma[b * CC + cb + c];
        int seg = c >> 3, coff = c & 7;
        float4 o;
        float* op = &o.x;
#pragma unroll
        for (int dn = 0; dn < 4; dn++) {
            int n = nb4 + dn;
            int phys = seg ^ ((n >> 2) & 7);
            float v = __half2float(t[n * 64 + phys * 8 + coff]);
            op[dn] = fmaxf(v * g, 0.f);
        }
        *(float4*)&out[((size_t)b * CC + cb + c) * HWN + nb + nb4] = o;
    }
}

// ---------------- launch ----------------
extern "C" void kernel_launch(void* const* d_in, const int* in_sizes, int n_in,
                              void* d_out, int out_size)
{
    const float* x      = (const float*)d_in[0];
    const float* conv_w = (const float*)d_in[1];
    const float* bn2_g  = (const float*)d_in[2];
    const float* bn2_b  = (const float*)d_in[3];
    const float* bn2_m  = (const float*)d_in[4];
    const float* bn2_v  = (const float*)d_in[5];
    const float* cw     = (const float*)d_in[6];
    const float* scale  = (const float*)d_in[7];
    const float* bn1_g  = (const float*)d_in[8];
    const float* bn1_b  = (const float*)d_in[9];
    const float* bn1_m  = (const float*)d_in[10];
    const float* bn1_v  = (const float*)d_in[11];
    const float* fc_w   = (const float*)d_in[12];
    const float* fc_b   = (const float*)d_in[13];
    float* out = (float*)d_out;   // [0:8192) encoding_feat, [8192:) output

    static bool attr_set = false;
    if (!attr_set) {
        cudaFuncSetAttribute(k1_mma, cudaFuncAttributeMaxDynamicSharedMemorySize, SMEM_K1M);
        attr_set = true;
    }

    kpw<<<(CC * CC + 255) / 256, 256>>>(conv_w, cw);

    dim3 gpx(HWN / 32, CC / 64, BB);
    kpx<<<gpx, 256>>>(x);

    dim3 g1(CC / 128, BB * HWN / 128);   // (4, 512)
    k1_mma<<<g1, 256, SMEM_K1M>>>(bn2_g, bn2_b, bn2_m, bn2_v);

    ksf<<<BB * HWN / 128, 128>>>(scale);

    dim3 g3(CC / 128, NSPLIT, BB);
    k3_agg<<<g3, 256>>>();

    k45<<<BB, 512>>>(cw, bn1_g, bn1_b, bn1_m, bn1_v, fc_w, fc_b, out);

    dim3 g6(HWN / 64, CC / 64, BB);
    k6_out<<<g6, 256>>>(out + BB * CC);
}